// round 8
// baseline (speedup 1.0000x reference)
#include <cuda_runtime.h>
#include <cuda_fp16.h>
#include <math.h>
#include <cstdint>

#define BSZ 128
#define TLEN 256
#define DMODEL 512
#define NHEADS 8
#define HDIM 64
#define MROWS (BSZ * TLEN)          // 32768
#define GK 512                       // K dim of both GEMMs

// ---------------------------------------------------------------------------
// Scratch: __device__ globals (allocation-free rule).
// ---------------------------------------------------------------------------
__device__ float g_qkv[(size_t)MROWS * 3 * DMODEL];   // [32768,1536]
__device__ __half g_ah[(size_t)MROWS * GK];    // A hi (x, then attn out)
__device__ __half g_al[(size_t)MROWS * GK];    // A lo
__device__ __half g_bh[(size_t)(3 * DMODEL) * GK];  // W_qkv^T hi
__device__ __half g_bl[(size_t)(3 * DMODEL) * GK];
__device__ __half g_b2h[(size_t)DMODEL * GK];       // W_out^T hi
__device__ __half g_b2l[(size_t)DMODEL * GK];

// ---------------------------------------------------------------------------
// PTX helpers — plain-sm_103-legal only (mma.sync / ldmatrix / cp.async).
// ---------------------------------------------------------------------------
__device__ __forceinline__ uint32_t smem_to_u32(const void* smem_ptr) {
    uint32_t addr;
    asm("{ .reg .u64 tmp; cvta.to.shared.u64 tmp, %1; cvt.u32.u64 %0, tmp; }"
        : "=r"(addr) : "l"(smem_ptr));
    return addr;
}

__device__ __forceinline__ void ldsm_x4(uint32_t* r, uint32_t addr) {
    asm volatile("ldmatrix.sync.aligned.m8n8.x4.shared.b16 {%0,%1,%2,%3}, [%4];"
                 : "=r"(r[0]), "=r"(r[1]), "=r"(r[2]), "=r"(r[3]) : "r"(addr));
}

// fp16 operands, fp32 accumulate (half-rate on sm_103 mma.sync — main term)
__device__ __forceinline__ void mma16816(float* c, const uint32_t* a,
                                         const uint32_t* b) {
    asm volatile(
        "mma.sync.aligned.m16n8k16.row.col.f32.f16.f16.f32 "
        "{%0,%1,%2,%3}, {%4,%5,%6,%7}, {%8,%9}, {%0,%1,%2,%3};"
        : "+f"(c[0]), "+f"(c[1]), "+f"(c[2]), "+f"(c[3])
        : "r"(a[0]), "r"(a[1]), "r"(a[2]), "r"(a[3]), "r"(b[0]), "r"(b[1]));
}

// fp16 operands, fp16 accumulate (full-rate — small correction terms)
__device__ __forceinline__ void mma16816h(uint32_t& c0, uint32_t& c1,
                                          const uint32_t* a, const uint32_t* b) {
    asm volatile(
        "mma.sync.aligned.m16n8k16.row.col.f16.f16.f16.f16 "
        "{%0,%1}, {%2,%3,%4,%5}, {%6,%7}, {%0,%1};"
        : "+r"(c0), "+r"(c1)
        : "r"(a[0]), "r"(a[1]), "r"(a[2]), "r"(a[3]), "r"(b[0]), "r"(b[1]));
}

__device__ __forceinline__ void flush_corr(float* c, uint32_t c0, uint32_t c1) {
    float2 f0 = __half22float2(*reinterpret_cast<__half2*>(&c0));
    float2 f1 = __half22float2(*reinterpret_cast<__half2*>(&c1));
    c[0] += f0.x; c[1] += f0.y; c[2] += f1.x; c[3] += f1.y;
}

__device__ __forceinline__ void cp_async16(uint32_t saddr, const void* gaddr) {
    asm volatile("cp.async.cg.shared.global [%0], [%1], 16;"
                 :: "r"(saddr), "l"(gaddr));
}
#define CP_COMMIT() asm volatile("cp.async.commit_group;" ::: "memory")
#define CP_WAIT(n)  asm volatile("cp.async.wait_group %0;" :: "n"(n) : "memory")

__device__ __forceinline__ uint32_t pack_h2(float a, float b) {
    __half2 t = __floats2half2_rn(a, b);
    return *(uint32_t*)&t;
}

// ---------------------------------------------------------------------------
// Precision-split conversion kernels (fp16 hi/lo: ~22 mantissa bits combined)
// ---------------------------------------------------------------------------
__global__ void split_f16_kernel(const float* __restrict__ in,
                                 __half* __restrict__ hi,
                                 __half* __restrict__ lo, int n4) {
    int i = blockIdx.x * blockDim.x + threadIdx.x;
    if (i >= n4) return;
    float4 v = ((const float4*)in)[i];
    float vv[4] = {v.x, v.y, v.z, v.w};
    __half hb[4], lb[4];
#pragma unroll
    for (int j = 0; j < 4; j++) {
        hb[j] = __float2half_rn(vv[j]);
        lb[j] = __float2half_rn(vv[j] - __half2float(hb[j]));
    }
    __half2* h2 = (__half2*)(hi + (size_t)i * 4);
    __half2* l2 = (__half2*)(lo + (size_t)i * 4);
    h2[0] = __halves2half2(hb[0], hb[1]);
    h2[1] = __halves2half2(hb[2], hb[3]);
    l2[0] = __halves2half2(lb[0], lb[1]);
    l2[1] = __halves2half2(lb[2], lb[3]);
}

__global__ void splitT_f16_kernel(const float* __restrict__ W,
                                  __half* __restrict__ th,
                                  __half* __restrict__ tl,
                                  int K, int N) {
    int idx = blockIdx.x * blockDim.x + threadIdx.x;
    if (idx >= K * N) return;
    int k = idx / N, n = idx % N;
    float v = W[idx];
    __half h = __float2half_rn(v);
    th[(size_t)n * K + k] = h;
    tl[(size_t)n * K + k] = __float2half_rn(v - __half2float(h));
}

// ---------------------------------------------------------------------------
// fp16x2-split mma.sync GEMM. 128x128 tile, 8 warps (32x64), BK=32, dbuf.
// Main term f32-acc (half-rate), corrections f16-acc (full-rate), flushed
// into the f32 accumulator per k-step. Pipe cost 6 -> 4 rt-units.
// ---------------------------------------------------------------------------
#define ROWB 80
#define SM_TILE (128 * ROWB)
#define SM_T_AH 0
#define SM_T_AL (SM_TILE)
#define SM_T_BH (2 * SM_TILE)
#define SM_T_BL (3 * SM_TILE)
#define SM_STAGE (4 * SM_TILE)
#define GEMM_SMEM (2 * SM_STAGE)

__global__ __launch_bounds__(256, 2)
void gemm_mma_kernel(const __half* __restrict__ Ah,
                     const __half* __restrict__ Al,
                     const __half* __restrict__ Bh,
                     const __half* __restrict__ Bl,
                     const float* __restrict__ bias,
                     float* __restrict__ C, int N) {
    extern __shared__ char smem[];
    const uint32_t sbase = smem_to_u32(smem);
    const int tid = threadIdx.x;
    const int wid = tid >> 5, lane = tid & 31;
    const int warpM = wid & 3, warpN = wid >> 2;
    const int m0 = blockIdx.y * 128, n0 = blockIdx.x * 128;

    const char* gAh = (const char*)(Ah + (size_t)m0 * GK);
    const char* gAl = (const char*)(Al + (size_t)m0 * GK);
    const char* gBh = (const char*)(Bh + (size_t)n0 * GK);
    const char* gBl = (const char*)(Bl + (size_t)n0 * GK);

    float acc[2][8][4];
#pragma unroll
    for (int mt = 0; mt < 2; mt++)
#pragma unroll
        for (int nt = 0; nt < 8; nt++)
#pragma unroll
            for (int r = 0; r < 4; r++) acc[mt][nt][r] = 0.0f;

    const int lr2 = (tid >> 2);
    const int lc2 = (tid & 3);

    {
        uint32_t sb = sbase;
#pragma unroll
        for (int p = 0; p < 2; p++) {
            int r = lr2 + p * 64;
            uint32_t so = r * ROWB + lc2 * 16;
            size_t go = (size_t)r * (GK * 2) + lc2 * 16;
            cp_async16(sb + SM_T_AH + so, gAh + go);
            cp_async16(sb + SM_T_AL + so, gAl + go);
            cp_async16(sb + SM_T_BH + so, gBh + go);
            cp_async16(sb + SM_T_BL + so, gBl + go);
        }
        CP_COMMIT();
    }

    const int lrow = lane & 15;
    const int lcs = lane >> 4;

    constexpr int NSTAGES = GK / 32;
    for (int s = 0; s < NSTAGES; s++) {
        if (s + 1 < NSTAGES) {
            uint32_t sb = sbase + ((s + 1) & 1) * SM_STAGE;
            const int kbyte = (s + 1) * 64;
#pragma unroll
            for (int p = 0; p < 2; p++) {
                int r = lr2 + p * 64;
                uint32_t so = r * ROWB + lc2 * 16;
                size_t go = (size_t)r * (GK * 2) + kbyte + lc2 * 16;
                cp_async16(sb + SM_T_AH + so, gAh + go);
                cp_async16(sb + SM_T_AL + so, gAl + go);
                cp_async16(sb + SM_T_BH + so, gBh + go);
                cp_async16(sb + SM_T_BL + so, gBl + go);
            }
            CP_COMMIT();
            CP_WAIT(1);
        } else {
            CP_WAIT(0);
        }
        __syncthreads();

        const uint32_t sb = sbase + (s & 1) * SM_STAGE;
#pragma unroll
        for (int kk = 0; kk < 2; kk++) {
            const uint32_t coff = (kk * 2 + lcs) * 16;
            uint32_t aH[2][4], aL[2][4];
#pragma unroll
            for (int mt = 0; mt < 2; mt++) {
                uint32_t ro = (uint32_t)(warpM * 32 + mt * 16 + lrow) * ROWB + coff;
                ldsm_x4(aH[mt], sb + SM_T_AH + ro);
                ldsm_x4(aL[mt], sb + SM_T_AL + ro);
            }
            uint32_t bH[8][2], bL[8][2];
#pragma unroll
            for (int q = 0; q < 4; q++) {
                uint32_t ro = (uint32_t)(warpN * 64 + q * 16 + lrow) * ROWB + coff;
                uint32_t t[4];
                ldsm_x4(t, sb + SM_T_BH + ro);
                bH[2 * q][0] = t[0]; bH[2 * q][1] = t[2];
                bH[2 * q + 1][0] = t[1]; bH[2 * q + 1][1] = t[3];
                ldsm_x4(t, sb + SM_T_BL + ro);
                bL[2 * q][0] = t[0]; bL[2 * q][1] = t[2];
                bL[2 * q + 1][0] = t[1]; bL[2 * q + 1][1] = t[3];
            }
#pragma unroll
            for (int mt = 0; mt < 2; mt++)
#pragma unroll
                for (int nt = 0; nt < 8; nt++) {
                    mma16816(acc[mt][nt], aH[mt], bH[nt]);   // main, f32 acc
                    uint32_t c0 = 0, c1 = 0;                 // corrections, f16 acc
                    mma16816h(c0, c1, aH[mt], bL[nt]);
                    mma16816h(c0, c1, aL[mt], bH[nt]);
                    flush_corr(acc[mt][nt], c0, c1);
                }
        }
        __syncthreads();
    }

    const int g = lane >> 2, tc4 = lane & 3;
#pragma unroll
    for (int mt = 0; mt < 2; mt++) {
        const int row = m0 + warpM * 32 + mt * 16 + g;
#pragma unroll
        for (int nt = 0; nt < 8; nt++) {
            const int col = n0 + warpN * 64 + nt * 8 + tc4 * 2;
            const float bv0 = bias[col], bv1 = bias[col + 1];
            float2 v0, v1;
            v0.x = acc[mt][nt][0] + bv0; v0.y = acc[mt][nt][1] + bv1;
            v1.x = acc[mt][nt][2] + bv0; v1.y = acc[mt][nt][3] + bv1;
            *(float2*)(C + (size_t)row * N + col) = v0;
            *(float2*)(C + (size_t)(row + 8) * N + col) = v1;
        }
    }
}

// ---------------------------------------------------------------------------
// Flash attention, fp16x2-split mma.sync. One block per (b,h), 8 warps.
// ---------------------------------------------------------------------------
#define AT_QH 0
#define AT_QL 36864
#define AT_KH 73728
#define AT_KL 110592
#define AT_VTH 147456
#define AT_VTL 181248
#define ATTN_SMEM 215040
#define AT_VSTAGE 0          // fp32 V staging [256][272B], overlaps Q region

__global__ __launch_bounds__(256, 1)
void attn_mma_kernel(const float* __restrict__ qkv,
                     __half* __restrict__ yh,
                     __half* __restrict__ yl) {
    extern __shared__ char smem[];
    const uint32_t sbase = smem_to_u32(smem);
    const int b = blockIdx.x >> 3;
    const int h = blockIdx.x & 7;
    const int tid = threadIdx.x;
    const int wid = tid >> 5, lane = tid & 31;
    const int g = lane >> 2, tq = lane & 3;
    const int lrow = lane & 15, lcs = lane >> 4;
    const float SCALE = 0.125f;

    const float* base = qkv + (size_t)b * TLEN * (3 * DMODEL) + h * HDIM;

    for (int i = tid; i < 256 * 16; i += 256) {
        const int t = i >> 4, c = i & 15;
        float4 v = *(const float4*)(base + (size_t)t * (3 * DMODEL) + 2 * DMODEL + c * 4);
        *(float4*)(smem + AT_VSTAGE + t * 272 + c * 16) = v;
    }
    __syncthreads();

    {
        const int d = tid & 63;
        const int jb = (tid >> 6) * 64;
#pragma unroll 4
        for (int jp = 0; jp < 32; jp++) {
            const int j = jb + 2 * jp;
            float v0 = *(const float*)(smem + AT_VSTAGE + j * 272 + d * 4);
            float v1 = *(const float*)(smem + AT_VSTAGE + (j + 1) * 272 + d * 4);
            __half h0 = __float2half_rn(v0);
            __half h1 = __float2half_rn(v1);
            __half l0 = __float2half_rn(v0 - __half2float(h0));
            __half l1 = __float2half_rn(v1 - __half2float(h1));
            *(__half2*)(smem + AT_VTH + d * 528 + j * 2) = __halves2half2(h0, h1);
            *(__half2*)(smem + AT_VTL + d * 528 + j * 2) = __halves2half2(l0, l1);
        }
    }
    __syncthreads();

    for (int i = tid; i < 256 * 16; i += 256) {
        const int t = i >> 4, c = i & 15;
        const size_t roff = (size_t)t * (3 * DMODEL);
        float4 q = *(const float4*)(base + roff + c * 4);
        float4 k = *(const float4*)(base + roff + DMODEL + c * 4);
        float qv[4] = {q.x, q.y, q.z, q.w};
        float kv[4] = {k.x, k.y, k.z, k.w};
        __half qh[4], ql[4], kh[4], kl[4];
#pragma unroll
        for (int j = 0; j < 4; j++) {
            qh[j] = __float2half_rn(qv[j]);
            ql[j] = __float2half_rn(qv[j] - __half2float(qh[j]));
            kh[j] = __float2half_rn(kv[j]);
            kl[j] = __float2half_rn(kv[j] - __half2float(kh[j]));
        }
        const int so = t * 144 + c * 8;
        *(__half2*)(smem + AT_QH + so)     = __halves2half2(qh[0], qh[1]);
        *(__half2*)(smem + AT_QH + so + 4) = __halves2half2(qh[2], qh[3]);
        *(__half2*)(smem + AT_QL + so)     = __halves2half2(ql[0], ql[1]);
        *(__half2*)(smem + AT_QL + so + 4) = __halves2half2(ql[2], ql[3]);
        *(__half2*)(smem + AT_KH + so)     = __halves2half2(kh[0], kh[1]);
        *(__half2*)(smem + AT_KH + so + 4) = __halves2half2(kh[2], kh[3]);
        *(__half2*)(smem + AT_KL + so)     = __halves2half2(kl[0], kl[1]);
        *(__half2*)(smem + AT_KL + so + 4) = __halves2half2(kl[2], kl[3]);
    }
    __syncthreads();

#pragma unroll
    for (int half = 0; half < 2; half++) {
        const int tile = (half == 0) ? wid : 15 - wid;
        const int nch = tile / 4 + 1;

        float o[8][4];
#pragma unroll
        for (int nt = 0; nt < 8; nt++)
#pragma unroll
            for (int r = 0; r < 4; r++) o[nt][r] = 0.0f;
        float m0 = -1e30f, m1 = -1e30f, l0 = 0.0f, l1 = 0.0f;

        for (int c = 0; c < nch; c++) {
            float S[8][4];
#pragma unroll
            for (int nt = 0; nt < 8; nt++)
#pragma unroll
                for (int r = 0; r < 4; r++) S[nt][r] = 0.0f;

#pragma unroll
            for (int kt = 0; kt < 4; kt++) {
                uint32_t aH[4], aL[4];
                const uint32_t qro = (uint32_t)(tile * 16 + lrow) * 144 + kt * 32 + lcs * 16;
                ldsm_x4(aH, sbase + AT_QH + qro);
                ldsm_x4(aL, sbase + AT_QL + qro);
#pragma unroll
                for (int q = 0; q < 4; q++) {
                    const uint32_t kro =
                        (uint32_t)(c * 64 + q * 16 + lrow) * 144 + kt * 32 + lcs * 16;
                    uint32_t tH[4], tL[4];
                    ldsm_x4(tH, sbase + AT_KH + kro);
                    ldsm_x4(tL, sbase + AT_KL + kro);
                    uint32_t b0H[2] = {tH[0], tH[2]}, b1H[2] = {tH[1], tH[3]};
                    uint32_t b0L[2] = {tL[0], tL[2]}, b1L[2] = {tL[1], tL[3]};
                    mma16816(S[2 * q],     aH, b0H);
                    mma16816(S[2 * q + 1], aH, b1H);
                    uint32_t c0 = 0, c1 = 0;
                    mma16816h(c0, c1, aH, b0L);
                    mma16816h(c0, c1, aL, b0H);
                    flush_corr(S[2 * q], c0, c1);
                    c0 = 0; c1 = 0;
                    mma16816h(c0, c1, aH, b1L);
                    mma16816h(c0, c1, aL, b1H);
                    flush_corr(S[2 * q + 1], c0, c1);
                }
            }

            const int r0 = tile * 16 + g, r1 = r0 + 8;
            if (c == nch - 1) {
#pragma unroll
                for (int nt = 0; nt < 8; nt++) {
                    const int col = c * 64 + nt * 8 + 2 * tq;
                    S[nt][0] = (col     <= r0) ? S[nt][0] * SCALE : -1e30f;
                    S[nt][1] = (col + 1 <= r0) ? S[nt][1] * SCALE : -1e30f;
                    S[nt][2] = (col     <= r1) ? S[nt][2] * SCALE : -1e30f;
                    S[nt][3] = (col + 1 <= r1) ? S[nt][3] * SCALE : -1e30f;
                }
            } else {
#pragma unroll
                for (int nt = 0; nt < 8; nt++)
#pragma unroll
                    for (int r = 0; r < 4; r++) S[nt][r] *= SCALE;
            }

            float cm0 = -1e30f, cm1 = -1e30f;
#pragma unroll
            for (int nt = 0; nt < 8; nt++) {
                cm0 = fmaxf(cm0, fmaxf(S[nt][0], S[nt][1]));
                cm1 = fmaxf(cm1, fmaxf(S[nt][2], S[nt][3]));
            }
            cm0 = fmaxf(cm0, __shfl_xor_sync(0xffffffffu, cm0, 1));
            cm0 = fmaxf(cm0, __shfl_xor_sync(0xffffffffu, cm0, 2));
            cm1 = fmaxf(cm1, __shfl_xor_sync(0xffffffffu, cm1, 1));
            cm1 = fmaxf(cm1, __shfl_xor_sync(0xffffffffu, cm1, 2));
            const float mn0 = fmaxf(m0, cm0), mn1 = fmaxf(m1, cm1);
            const float a0 = __expf(m0 - mn0), a1 = __expf(m1 - mn1);
            m0 = mn0; m1 = mn1;

            float rs0 = 0.0f, rs1 = 0.0f;
#pragma unroll
            for (int nt = 0; nt < 8; nt++) {
                S[nt][0] = __expf(S[nt][0] - mn0);
                S[nt][1] = __expf(S[nt][1] - mn0);
                S[nt][2] = __expf(S[nt][2] - mn1);
                S[nt][3] = __expf(S[nt][3] - mn1);
                rs0 += S[nt][0] + S[nt][1];
                rs1 += S[nt][2] + S[nt][3];
            }
            rs0 += __shfl_xor_sync(0xffffffffu, rs0, 1);
            rs0 += __shfl_xor_sync(0xffffffffu, rs0, 2);
            rs1 += __shfl_xor_sync(0xffffffffu, rs1, 1);
            rs1 += __shfl_xor_sync(0xffffffffu, rs1, 2);
            l0 = l0 * a0 + rs0;
            l1 = l1 * a1 + rs1;

#pragma unroll
            for (int nt = 0; nt < 8; nt++) {
                o[nt][0] *= a0; o[nt][1] *= a0;
                o[nt][2] *= a1; o[nt][3] *= a1;
            }

            uint32_t pH[4][4], pL[4][4];
#pragma unroll
            for (int kt = 0; kt < 4; kt++) {
#pragma unroll
                for (int part = 0; part < 4; part++) {
                    const int nt = 2 * kt + (part >> 1);
                    const int rb = (part & 1) * 2;
                    const float p0 = S[nt][rb], p1 = S[nt][rb + 1];
                    __half h0 = __float2half_rn(p0);
                    __half h1 = __float2half_rn(p1);
                    float q0 = p0 - __half2float(h0);
                    float q1 = p1 - __half2float(h1);
                    __half2 hh = __halves2half2(h0, h1);
                    pH[kt][part] = *(uint32_t*)&hh;
                    pL[kt][part] = pack_h2(q0, q1);
                }
            }

#pragma unroll
            for (int kt = 0; kt < 4; kt++) {
#pragma unroll
                for (int q = 0; q < 4; q++) {
                    const uint32_t vro =
                        (uint32_t)(q * 16 + lrow) * 528 + c * 128 + kt * 32 + lcs * 16;
                    uint32_t tH[4], tL[4];
                    ldsm_x4(tH, sbase + AT_VTH + vro);
                    ldsm_x4(tL, sbase + AT_VTL + vro);
                    uint32_t b0H[2] = {tH[0], tH[2]}, b1H[2] = {tH[1], tH[3]};
                    uint32_t b0L[2] = {tL[0], tL[2]}, b1L[2] = {tL[1], tL[3]};
                    mma16816(o[2 * q],     pH[kt], b0H);
                    mma16816(o[2 * q + 1], pH[kt], b1H);
                    uint32_t c0 = 0, c1 = 0;
                    mma16816h(c0, c1, pH[kt], b0L);
                    mma16816h(c0, c1, pL[kt], b0H);
                    flush_corr(o[2 * q], c0, c1);
                    c0 = 0; c1 = 0;
                    mma16816h(c0, c1, pH[kt], b1L);
                    mma16816h(c0, c1, pL[kt], b1H);
                    flush_corr(o[2 * q + 1], c0, c1);
                }
            }
        }

        const float inv0 = 1.0f / l0, inv1 = 1.0f / l1;
        const int row0 = b * TLEN + tile * 16 + g;
#pragma unroll
        for (int nt = 0; nt < 8; nt++) {
            const int col = h * HDIM + nt * 8 + 2 * tq;
            const size_t i0 = (size_t)row0 * DMODEL + col;
            const size_t i1 = i0 + (size_t)8 * DMODEL;
            float v0 = o[nt][0] * inv0, v1 = o[nt][1] * inv0;
            float v2 = o[nt][2] * inv1, v3 = o[nt][3] * inv1;
            __half h0 = __float2half_rn(v0), h1 = __float2half_rn(v1);
            __half h2 = __float2half_rn(v2), h3 = __float2half_rn(v3);
            *(__half2*)(yh + i0) = __halves2half2(h0, h1);
            *(__half2*)(yh + i1) = __halves2half2(h2, h3);
            *(__half2*)(yl + i0) = __halves2half2(
                __float2half_rn(v0 - __half2float(h0)),
                __float2half_rn(v1 - __half2float(h1)));
            *(__half2*)(yl + i1) = __halves2half2(
                __float2half_rn(v2 - __half2float(h2)),
                __float2half_rn(v3 - __half2float(h3)));
        }
    }
}

// ---------------------------------------------------------------------------
extern "C" void kernel_launch(void* const* d_in, const int* in_sizes, int n_in,
                              void* d_out, int out_size) {
    const float* x     = (const float*)d_in[0];
    const float* W_qkv = (const float*)d_in[1];
    const float* b_qkv = (const float*)d_in[2];
    const float* W_out = (const float*)d_in[3];
    const float* b_out = (const float*)d_in[4];
    float* out = (float*)d_out;

    float* qkv;
    __half *ah, *al, *bh, *bl, *b2h, *b2l;
    cudaGetSymbolAddress((void**)&qkv, g_qkv);
    cudaGetSymbolAddress((void**)&ah, g_ah);
    cudaGetSymbolAddress((void**)&al, g_al);
    cudaGetSymbolAddress((void**)&bh, g_bh);
    cudaGetSymbolAddress((void**)&bl, g_bl);
    cudaGetSymbolAddress((void**)&b2h, g_b2h);
    cudaGetSymbolAddress((void**)&b2l, g_b2l);

    cudaFuncSetAttribute(gemm_mma_kernel,
                         cudaFuncAttributeMaxDynamicSharedMemorySize, GEMM_SMEM);
    cudaFuncSetAttribute(attn_mma_kernel,
                         cudaFuncAttributeMaxDynamicSharedMemorySize, ATTN_SMEM);

    // 1) split x -> fp16 hi/lo
    {
        const int n4 = MROWS * GK / 4;
        split_f16_kernel<<<(n4 + 255) / 256, 256>>>(x, ah, al, n4);
    }
    // 2) split+transpose weights
    splitT_f16_kernel<<<(GK * 3 * DMODEL + 255) / 256, 256>>>(W_qkv, bh, bl,
                                                              GK, 3 * DMODEL);
    splitT_f16_kernel<<<(GK * DMODEL + 255) / 256, 256>>>(W_out, b2h, b2l,
                                                          GK, DMODEL);

    // 3) QKV projection (tensor cores)
    {
        dim3 g(3 * DMODEL / 128, MROWS / 128);
        gemm_mma_kernel<<<g, 256, GEMM_SMEM>>>(ah, al, bh, bl, b_qkv, qkv,
                                               3 * DMODEL);
    }

    // 4) flash attention (tensor cores), writes fp16 hi/lo into ah/al
    attn_mma_kernel<<<BSZ * NHEADS, 256, ATTN_SMEM>>>(qkv, ah, al);

    // 5) output projection (tensor cores)
    {
        dim3 g(DMODEL / 128, MROWS / 128);
        gemm_mma_kernel<<<g, 256, GEMM_SMEM>>>(ah, al, b2h, b2l, b_out, out,
                                               DMODEL);
    }
}

// round 9
// speedup vs baseline: 1.1059x; 1.1059x over previous
#include <cuda_runtime.h>
#include <cuda_bf16.h>
#include <math.h>
#include <cstdint>

#define BSZ 128
#define TLEN 256
#define DMODEL 512
#define NHEADS 8
#define HDIM 64
#define MROWS (BSZ * TLEN)          // 32768
#define GK 512                       // K dim of both GEMMs

// ---------------------------------------------------------------------------
// Scratch: __device__ globals (allocation-free rule).
// ---------------------------------------------------------------------------
__device__ float g_qkv[(size_t)MROWS * 3 * DMODEL];   // [32768,1536]
__device__ __nv_bfloat16 g_ah[(size_t)MROWS * GK];    // A hi (x, then attn out)
__device__ __nv_bfloat16 g_al[(size_t)MROWS * GK];    // A lo
__device__ __nv_bfloat16 g_bh[(size_t)(3 * DMODEL) * GK];  // W_qkv^T hi
__device__ __nv_bfloat16 g_bl[(size_t)(3 * DMODEL) * GK];
__device__ __nv_bfloat16 g_b2h[(size_t)DMODEL * GK];       // W_out^T hi
__device__ __nv_bfloat16 g_b2l[(size_t)DMODEL * GK];

// ---------------------------------------------------------------------------
// PTX helpers — plain-sm_103-legal only (mma.sync / ldmatrix / cp.async).
// ---------------------------------------------------------------------------
__device__ __forceinline__ uint32_t smem_to_u32(const void* smem_ptr) {
    uint32_t addr;
    asm("{ .reg .u64 tmp; cvta.to.shared.u64 tmp, %1; cvt.u32.u64 %0, tmp; }"
        : "=r"(addr) : "l"(smem_ptr));
    return addr;
}

__device__ __forceinline__ void ldsm_x4(uint32_t* r, uint32_t addr) {
    asm volatile("ldmatrix.sync.aligned.m8n8.x4.shared.b16 {%0,%1,%2,%3}, [%4];"
                 : "=r"(r[0]), "=r"(r[1]), "=r"(r[2]), "=r"(r[3]) : "r"(addr));
}

__device__ __forceinline__ void mma16816(float* c, const uint32_t* a,
                                         const uint32_t* b) {
    asm volatile(
        "mma.sync.aligned.m16n8k16.row.col.f32.bf16.bf16.f32 "
        "{%0,%1,%2,%3}, {%4,%5,%6,%7}, {%8,%9}, {%0,%1,%2,%3};"
        : "+f"(c[0]), "+f"(c[1]), "+f"(c[2]), "+f"(c[3])
        : "r"(a[0]), "r"(a[1]), "r"(a[2]), "r"(a[3]), "r"(b[0]), "r"(b[1]));
}

__device__ __forceinline__ void cp_async16(uint32_t saddr, const void* gaddr) {
    asm volatile("cp.async.cg.shared.global [%0], [%1], 16;"
                 :: "r"(saddr), "l"(gaddr));
}
#define CP_COMMIT() asm volatile("cp.async.commit_group;" ::: "memory")
#define CP_WAIT(n)  asm volatile("cp.async.wait_group %0;" :: "n"(n) : "memory")

__device__ __forceinline__ uint32_t pack_bf16(float a, float b) {
    __nv_bfloat162 t = __floats2bfloat162_rn(a, b);
    return *(uint32_t*)&t;
}

// ---------------------------------------------------------------------------
// Precision-split conversion kernels
// ---------------------------------------------------------------------------
__global__ void split_bf16_kernel(const float* __restrict__ in,
                                  __nv_bfloat16* __restrict__ hi,
                                  __nv_bfloat16* __restrict__ lo, int n4) {
    int i = blockIdx.x * blockDim.x + threadIdx.x;
    if (i >= n4) return;
    float4 v = ((const float4*)in)[i];
    float vv[4] = {v.x, v.y, v.z, v.w};
    __nv_bfloat16 hb[4], lb[4];
#pragma unroll
    for (int j = 0; j < 4; j++) {
        hb[j] = __float2bfloat16(vv[j]);
        lb[j] = __float2bfloat16(vv[j] - __bfloat162float(hb[j]));
    }
    __nv_bfloat162* h2 = (__nv_bfloat162*)(hi + (size_t)i * 4);
    __nv_bfloat162* l2 = (__nv_bfloat162*)(lo + (size_t)i * 4);
    h2[0] = __halves2bfloat162(hb[0], hb[1]);
    h2[1] = __halves2bfloat162(hb[2], hb[3]);
    l2[0] = __halves2bfloat162(lb[0], lb[1]);
    l2[1] = __halves2bfloat162(lb[2], lb[3]);
}

__global__ void splitT_bf16_kernel(const float* __restrict__ W,
                                   __nv_bfloat16* __restrict__ th,
                                   __nv_bfloat16* __restrict__ tl,
                                   int K, int N) {
    int idx = blockIdx.x * blockDim.x + threadIdx.x;
    if (idx >= K * N) return;
    int k = idx / N, n = idx % N;
    float v = W[idx];
    __nv_bfloat16 h = __float2bfloat16(v);
    th[(size_t)n * K + k] = h;
    tl[(size_t)n * K + k] = __float2bfloat16(v - __bfloat162float(h));
}

// ---------------------------------------------------------------------------
// bf16x3 mma.sync GEMM. 128x128 tile, 8 warps (32x64 warp tile), BK=32, dbuf.
// R9: LDSM/MMA interleaved at per-q granularity — each B-fragment load pair
// hides under the previous q's 12 MMAs, removing the per-kk LDSM-burst bubble
// (was: 12 LDSM burst then 48 MMA burst, lockstep across warps -> 48% idle).
// ---------------------------------------------------------------------------
#define ROWB 80
#define SM_TILE (128 * ROWB)
#define SM_T_AH 0
#define SM_T_AL (SM_TILE)
#define SM_T_BH (2 * SM_TILE)
#define SM_T_BL (3 * SM_TILE)
#define SM_STAGE (4 * SM_TILE)
#define GEMM_SMEM (2 * SM_STAGE)

__global__ __launch_bounds__(256, 2)
void gemm_mma_kernel(const __nv_bfloat16* __restrict__ Ah,
                     const __nv_bfloat16* __restrict__ Al,
                     const __nv_bfloat16* __restrict__ Bh,
                     const __nv_bfloat16* __restrict__ Bl,
                     const float* __restrict__ bias,
                     float* __restrict__ C, int N) {
    extern __shared__ char smem[];
    const uint32_t sbase = smem_to_u32(smem);
    const int tid = threadIdx.x;
    const int wid = tid >> 5, lane = tid & 31;
    const int warpM = wid & 3, warpN = wid >> 2;
    const int m0 = blockIdx.y * 128, n0 = blockIdx.x * 128;

    const char* gAh = (const char*)(Ah + (size_t)m0 * GK);
    const char* gAl = (const char*)(Al + (size_t)m0 * GK);
    const char* gBh = (const char*)(Bh + (size_t)n0 * GK);
    const char* gBl = (const char*)(Bl + (size_t)n0 * GK);

    float acc[2][8][4];
#pragma unroll
    for (int mt = 0; mt < 2; mt++)
#pragma unroll
        for (int nt = 0; nt < 8; nt++)
#pragma unroll
            for (int r = 0; r < 4; r++) acc[mt][nt][r] = 0.0f;

    const int lr2 = (tid >> 2);
    const int lc2 = (tid & 3);

    {
        uint32_t sb = sbase;
#pragma unroll
        for (int p = 0; p < 2; p++) {
            int r = lr2 + p * 64;
            uint32_t so = r * ROWB + lc2 * 16;
            size_t go = (size_t)r * (GK * 2) + lc2 * 16;
            cp_async16(sb + SM_T_AH + so, gAh + go);
            cp_async16(sb + SM_T_AL + so, gAl + go);
            cp_async16(sb + SM_T_BH + so, gBh + go);
            cp_async16(sb + SM_T_BL + so, gBl + go);
        }
        CP_COMMIT();
    }

    const int lrow = lane & 15;
    const int lcs = lane >> 4;

    constexpr int NSTAGES = GK / 32;
    for (int s = 0; s < NSTAGES; s++) {
        if (s + 1 < NSTAGES) {
            uint32_t sb = sbase + ((s + 1) & 1) * SM_STAGE;
            const int kbyte = (s + 1) * 64;
#pragma unroll
            for (int p = 0; p < 2; p++) {
                int r = lr2 + p * 64;
                uint32_t so = r * ROWB + lc2 * 16;
                size_t go = (size_t)r * (GK * 2) + kbyte + lc2 * 16;
                cp_async16(sb + SM_T_AH + so, gAh + go);
                cp_async16(sb + SM_T_AL + so, gAl + go);
                cp_async16(sb + SM_T_BH + so, gBh + go);
                cp_async16(sb + SM_T_BL + so, gBl + go);
            }
            CP_COMMIT();
            CP_WAIT(1);
        } else {
            CP_WAIT(0);
        }
        __syncthreads();

        const uint32_t sb = sbase + (s & 1) * SM_STAGE;
#pragma unroll
        for (int kk = 0; kk < 2; kk++) {
            const uint32_t coff = (kk * 2 + lcs) * 16;
            uint32_t aH[2][4], aL[2][4];
#pragma unroll
            for (int mt = 0; mt < 2; mt++) {
                uint32_t ro = (uint32_t)(warpM * 32 + mt * 16 + lrow) * ROWB + coff;
                ldsm_x4(aH[mt], sb + SM_T_AH + ro);
                ldsm_x4(aL[mt], sb + SM_T_AL + ro);
            }
            // interleaved: per q, load B frags then immediately MMA —
            // LDSM for q hides under MMAs of q-1 (no SM-wide LDSM burst).
#pragma unroll
            for (int q = 0; q < 4; q++) {
                uint32_t ro = (uint32_t)(warpN * 64 + q * 16 + lrow) * ROWB + coff;
                uint32_t tH[4], tL[4];
                ldsm_x4(tH, sb + SM_T_BH + ro);
                ldsm_x4(tL, sb + SM_T_BL + ro);
                uint32_t b0H[2] = {tH[0], tH[2]}, b1H[2] = {tH[1], tH[3]};
                uint32_t b0L[2] = {tL[0], tL[2]}, b1L[2] = {tL[1], tL[3]};
#pragma unroll
                for (int mt = 0; mt < 2; mt++) {
                    mma16816(acc[mt][2 * q],     aH[mt], b0H);
                    mma16816(acc[mt][2 * q + 1], aH[mt], b1H);
                    mma16816(acc[mt][2 * q],     aH[mt], b0L);
                    mma16816(acc[mt][2 * q + 1], aH[mt], b1L);
                    mma16816(acc[mt][2 * q],     aL[mt], b0H);
                    mma16816(acc[mt][2 * q + 1], aL[mt], b1H);
                }
            }
        }
        __syncthreads();
    }

    const int g = lane >> 2, tc4 = lane & 3;
#pragma unroll
    for (int mt = 0; mt < 2; mt++) {
        const int row = m0 + warpM * 32 + mt * 16 + g;
#pragma unroll
        for (int nt = 0; nt < 8; nt++) {
            const int col = n0 + warpN * 64 + nt * 8 + tc4 * 2;
            const float bv0 = bias[col], bv1 = bias[col + 1];
            float2 v0, v1;
            v0.x = acc[mt][nt][0] + bv0; v0.y = acc[mt][nt][1] + bv1;
            v1.x = acc[mt][nt][2] + bv0; v1.y = acc[mt][nt][3] + bv1;
            *(float2*)(C + (size_t)row * N + col) = v0;
            *(float2*)(C + (size_t)(row + 8) * N + col) = v1;
        }
    }
}

// ---------------------------------------------------------------------------
// Flash attention with mma.sync bf16x3 (R5 version, already per-q interleaved).
// ---------------------------------------------------------------------------
#define AT_QH 0
#define AT_QL 36864
#define AT_KH 73728
#define AT_KL 110592
#define AT_VTH 147456
#define AT_VTL 181248
#define ATTN_SMEM 215040
#define AT_VSTAGE 0          // fp32 V staging [256][272B], overlaps Q region

__global__ __launch_bounds__(256, 1)
void attn_mma_kernel(const float* __restrict__ qkv,
                     __nv_bfloat16* __restrict__ yh,
                     __nv_bfloat16* __restrict__ yl) {
    extern __shared__ char smem[];
    const uint32_t sbase = smem_to_u32(smem);
    const int b = blockIdx.x >> 3;
    const int h = blockIdx.x & 7;
    const int tid = threadIdx.x;
    const int wid = tid >> 5, lane = tid & 31;
    const int g = lane >> 2, tq = lane & 3;
    const int lrow = lane & 15, lcs = lane >> 4;
    const float SCALE = 0.125f;

    const float* base = qkv + (size_t)b * TLEN * (3 * DMODEL) + h * HDIM;

    for (int i = tid; i < 256 * 16; i += 256) {
        const int t = i >> 4, c = i & 15;
        float4 v = *(const float4*)(base + (size_t)t * (3 * DMODEL) + 2 * DMODEL + c * 4);
        *(float4*)(smem + AT_VSTAGE + t * 272 + c * 16) = v;
    }
    __syncthreads();

    {
        const int d = tid & 63;
        const int jb = (tid >> 6) * 64;
#pragma unroll 4
        for (int jp = 0; jp < 32; jp++) {
            const int j = jb + 2 * jp;
            float v0 = *(const float*)(smem + AT_VSTAGE + j * 272 + d * 4);
            float v1 = *(const float*)(smem + AT_VSTAGE + (j + 1) * 272 + d * 4);
            __nv_bfloat16 h0 = __float2bfloat16(v0);
            __nv_bfloat16 h1 = __float2bfloat16(v1);
            __nv_bfloat16 l0 = __float2bfloat16(v0 - __bfloat162float(h0));
            __nv_bfloat16 l1 = __float2bfloat16(v1 - __bfloat162float(h1));
            *(__nv_bfloat162*)(smem + AT_VTH + d * 528 + j * 2) = __halves2bfloat162(h0, h1);
            *(__nv_bfloat162*)(smem + AT_VTL + d * 528 + j * 2) = __halves2bfloat162(l0, l1);
        }
    }
    __syncthreads();

    for (int i = tid; i < 256 * 16; i += 256) {
        const int t = i >> 4, c = i & 15;
        const size_t roff = (size_t)t * (3 * DMODEL);
        float4 q = *(const float4*)(base + roff + c * 4);
        float4 k = *(const float4*)(base + roff + DMODEL + c * 4);
        float qv[4] = {q.x, q.y, q.z, q.w};
        float kv[4] = {k.x, k.y, k.z, k.w};
        __nv_bfloat16 qh[4], ql[4], kh[4], kl[4];
#pragma unroll
        for (int j = 0; j < 4; j++) {
            qh[j] = __float2bfloat16(qv[j]);
            ql[j] = __float2bfloat16(qv[j] - __bfloat162float(qh[j]));
            kh[j] = __float2bfloat16(kv[j]);
            kl[j] = __float2bfloat16(kv[j] - __bfloat162float(kh[j]));
        }
        const int so = t * 144 + c * 8;
        *(__nv_bfloat162*)(smem + AT_QH + so)     = __halves2bfloat162(qh[0], qh[1]);
        *(__nv_bfloat162*)(smem + AT_QH + so + 4) = __halves2bfloat162(qh[2], qh[3]);
        *(__nv_bfloat162*)(smem + AT_QL + so)     = __halves2bfloat162(ql[0], ql[1]);
        *(__nv_bfloat162*)(smem + AT_QL + so + 4) = __halves2bfloat162(ql[2], ql[3]);
        *(__nv_bfloat162*)(smem + AT_KH + so)     = __halves2bfloat162(kh[0], kh[1]);
        *(__nv_bfloat162*)(smem + AT_KH + so + 4) = __halves2bfloat162(kh[2], kh[3]);
        *(__nv_bfloat162*)(smem + AT_KL + so)     = __halves2bfloat162(kl[0], kl[1]);
        *(__nv_bfloat162*)(smem + AT_KL + so + 4) = __halves2bfloat162(kl[2], kl[3]);
    }
    __syncthreads();

#pragma unroll
    for (int half = 0; half < 2; half++) {
        const int tile = (half == 0) ? wid : 15 - wid;
        const int nch = tile / 4 + 1;

        float o[8][4];
#pragma unroll
        for (int nt = 0; nt < 8; nt++)
#pragma unroll
            for (int r = 0; r < 4; r++) o[nt][r] = 0.0f;
        float m0 = -1e30f, m1 = -1e30f, l0 = 0.0f, l1 = 0.0f;

        for (int c = 0; c < nch; c++) {
            float S[8][4];
#pragma unroll
            for (int nt = 0; nt < 8; nt++)
#pragma unroll
                for (int r = 0; r < 4; r++) S[nt][r] = 0.0f;

#pragma unroll
            for (int kt = 0; kt < 4; kt++) {
                uint32_t aH[4], aL[4];
                const uint32_t qro = (uint32_t)(tile * 16 + lrow) * 144 + kt * 32 + lcs * 16;
                ldsm_x4(aH, sbase + AT_QH + qro);
                ldsm_x4(aL, sbase + AT_QL + qro);
#pragma unroll
                for (int q = 0; q < 4; q++) {
                    const uint32_t kro =
                        (uint32_t)(c * 64 + q * 16 + lrow) * 144 + kt * 32 + lcs * 16;
                    uint32_t tH[4], tL[4];
                    ldsm_x4(tH, sbase + AT_KH + kro);
                    ldsm_x4(tL, sbase + AT_KL + kro);
                    uint32_t b0H[2] = {tH[0], tH[2]}, b1H[2] = {tH[1], tH[3]};
                    uint32_t b0L[2] = {tL[0], tL[2]}, b1L[2] = {tL[1], tL[3]};
                    mma16816(S[2 * q],     aH, b0H);
                    mma16816(S[2 * q + 1], aH, b1H);
                    mma16816(S[2 * q],     aH, b0L);
                    mma16816(S[2 * q + 1], aH, b1L);
                    mma16816(S[2 * q],     aL, b0H);
                    mma16816(S[2 * q + 1], aL, b1H);
                }
            }

            const int r0 = tile * 16 + g, r1 = r0 + 8;
            if (c == nch - 1) {
#pragma unroll
                for (int nt = 0; nt < 8; nt++) {
                    const int col = c * 64 + nt * 8 + 2 * tq;
                    S[nt][0] = (col     <= r0) ? S[nt][0] * SCALE : -1e30f;
                    S[nt][1] = (col + 1 <= r0) ? S[nt][1] * SCALE : -1e30f;
                    S[nt][2] = (col     <= r1) ? S[nt][2] * SCALE : -1e30f;
                    S[nt][3] = (col + 1 <= r1) ? S[nt][3] * SCALE : -1e30f;
                }
            } else {
#pragma unroll
                for (int nt = 0; nt < 8; nt++)
#pragma unroll
                    for (int r = 0; r < 4; r++) S[nt][r] *= SCALE;
            }

            float cm0 = -1e30f, cm1 = -1e30f;
#pragma unroll
            for (int nt = 0; nt < 8; nt++) {
                cm0 = fmaxf(cm0, fmaxf(S[nt][0], S[nt][1]));
                cm1 = fmaxf(cm1, fmaxf(S[nt][2], S[nt][3]));
            }
            cm0 = fmaxf(cm0, __shfl_xor_sync(0xffffffffu, cm0, 1));
            cm0 = fmaxf(cm0, __shfl_xor_sync(0xffffffffu, cm0, 2));
            cm1 = fmaxf(cm1, __shfl_xor_sync(0xffffffffu, cm1, 1));
            cm1 = fmaxf(cm1, __shfl_xor_sync(0xffffffffu, cm1, 2));
            const float mn0 = fmaxf(m0, cm0), mn1 = fmaxf(m1, cm1);
            const float a0 = __expf(m0 - mn0), a1 = __expf(m1 - mn1);
            m0 = mn0; m1 = mn1;

            float rs0 = 0.0f, rs1 = 0.0f;
#pragma unroll
            for (int nt = 0; nt < 8; nt++) {
                S[nt][0] = __expf(S[nt][0] - mn0);
                S[nt][1] = __expf(S[nt][1] - mn0);
                S[nt][2] = __expf(S[nt][2] - mn1);
                S[nt][3] = __expf(S[nt][3] - mn1);
                rs0 += S[nt][0] + S[nt][1];
                rs1 += S[nt][2] + S[nt][3];
            }
            rs0 += __shfl_xor_sync(0xffffffffu, rs0, 1);
            rs0 += __shfl_xor_sync(0xffffffffu, rs0, 2);
            rs1 += __shfl_xor_sync(0xffffffffu, rs1, 1);
            rs1 += __shfl_xor_sync(0xffffffffu, rs1, 2);
            l0 = l0 * a0 + rs0;
            l1 = l1 * a1 + rs1;

#pragma unroll
            for (int nt = 0; nt < 8; nt++) {
                o[nt][0] *= a0; o[nt][1] *= a0;
                o[nt][2] *= a1; o[nt][3] *= a1;
            }

            uint32_t pH[4][4], pL[4][4];
#pragma unroll
            for (int kt = 0; kt < 4; kt++) {
#pragma unroll
                for (int part = 0; part < 4; part++) {
                    const int nt = 2 * kt + (part >> 1);
                    const int rb = (part & 1) * 2;
                    const float p0 = S[nt][rb], p1 = S[nt][rb + 1];
                    __nv_bfloat16 h0 = __float2bfloat16(p0);
                    __nv_bfloat16 h1 = __float2bfloat16(p1);
                    float q0 = p0 - __bfloat162float(h0);
                    float q1 = p1 - __bfloat162float(h1);
                    __nv_bfloat162 hh = __halves2bfloat162(h0, h1);
                    pH[kt][part] = *(uint32_t*)&hh;
                    pL[kt][part] = pack_bf16(q0, q1);
                }
            }

#pragma unroll
            for (int kt = 0; kt < 4; kt++) {
#pragma unroll
                for (int q = 0; q < 4; q++) {
                    const uint32_t vro =
                        (uint32_t)(q * 16 + lrow) * 528 + c * 128 + kt * 32 + lcs * 16;
                    uint32_t tH[4], tL[4];
                    ldsm_x4(tH, sbase + AT_VTH + vro);
                    ldsm_x4(tL, sbase + AT_VTL + vro);
                    uint32_t b0H[2] = {tH[0], tH[2]}, b1H[2] = {tH[1], tH[3]};
                    uint32_t b0L[2] = {tL[0], tL[2]}, b1L[2] = {tL[1], tL[3]};
                    mma16816(o[2 * q],     pH[kt], b0H);
                    mma16816(o[2 * q + 1], pH[kt], b1H);
                    mma16816(o[2 * q],     pH[kt], b0L);
                    mma16816(o[2 * q + 1], pH[kt], b1L);
                    mma16816(o[2 * q],     pL[kt], b0H);
                    mma16816(o[2 * q + 1], pL[kt], b1H);
                }
            }
        }

        const float inv0 = 1.0f / l0, inv1 = 1.0f / l1;
        const int row0 = b * TLEN + tile * 16 + g;
#pragma unroll
        for (int nt = 0; nt < 8; nt++) {
            const int col = h * HDIM + nt * 8 + 2 * tq;
            const size_t i0 = (size_t)row0 * DMODEL + col;
            const size_t i1 = i0 + (size_t)8 * DMODEL;
            float v0 = o[nt][0] * inv0, v1 = o[nt][1] * inv0;
            float v2 = o[nt][2] * inv1, v3 = o[nt][3] * inv1;
            __nv_bfloat16 h0 = __float2bfloat16(v0), h1 = __float2bfloat16(v1);
            __nv_bfloat16 h2 = __float2bfloat16(v2), h3 = __float2bfloat16(v3);
            *(__nv_bfloat162*)(yh + i0) = __halves2bfloat162(h0, h1);
            *(__nv_bfloat162*)(yh + i1) = __halves2bfloat162(h2, h3);
            *(__nv_bfloat162*)(yl + i0) = __halves2bfloat162(
                __float2bfloat16(v0 - __bfloat162float(h0)),
                __float2bfloat16(v1 - __bfloat162float(h1)));
            *(__nv_bfloat162*)(yl + i1) = __halves2bfloat162(
                __float2bfloat16(v2 - __bfloat162float(h2)),
                __float2bfloat16(v3 - __bfloat162float(h3)));
        }
    }
}

// ---------------------------------------------------------------------------
extern "C" void kernel_launch(void* const* d_in, const int* in_sizes, int n_in,
                              void* d_out, int out_size) {
    const float* x     = (const float*)d_in[0];
    const float* W_qkv = (const float*)d_in[1];
    const float* b_qkv = (const float*)d_in[2];
    const float* W_out = (const float*)d_in[3];
    const float* b_out = (const float*)d_in[4];
    float* out = (float*)d_out;

    float* qkv;
    __nv_bfloat16 *ah, *al, *bh, *bl, *b2h, *b2l;
    cudaGetSymbolAddress((void**)&qkv, g_qkv);
    cudaGetSymbolAddress((void**)&ah, g_ah);
    cudaGetSymbolAddress((void**)&al, g_al);
    cudaGetSymbolAddress((void**)&bh, g_bh);
    cudaGetSymbolAddress((void**)&bl, g_bl);
    cudaGetSymbolAddress((void**)&b2h, g_b2h);
    cudaGetSymbolAddress((void**)&b2l, g_b2l);

    cudaFuncSetAttribute(gemm_mma_kernel,
                         cudaFuncAttributeMaxDynamicSharedMemorySize, GEMM_SMEM);
    cudaFuncSetAttribute(attn_mma_kernel,
                         cudaFuncAttributeMaxDynamicSharedMemorySize, ATTN_SMEM);

    // 1) split x -> bf16 hi/lo
    {
        const int n4 = MROWS * GK / 4;
        split_bf16_kernel<<<(n4 + 255) / 256, 256>>>(x, ah, al, n4);
    }
    // 2) split+transpose weights
    splitT_bf16_kernel<<<(GK * 3 * DMODEL + 255) / 256, 256>>>(W_qkv, bh, bl,
                                                               GK, 3 * DMODEL);
    splitT_bf16_kernel<<<(GK * DMODEL + 255) / 256, 256>>>(W_out, b2h, b2l,
                                                           GK, DMODEL);

    // 3) QKV projection (tensor cores)
    {
        dim3 g(3 * DMODEL / 128, MROWS / 128);
        gemm_mma_kernel<<<g, 256, GEMM_SMEM>>>(ah, al, bh, bl, b_qkv, qkv,
                                               3 * DMODEL);
    }

    // 4) flash attention (tensor cores), writes bf16 hi/lo into ah/al
    attn_mma_kernel<<<BSZ * NHEADS, 256, ATTN_SMEM>>>(qkv, ah, al);

    // 5) output projection (tensor cores)
    {
        dim3 g(DMODEL / 128, MROWS / 128);
        gemm_mma_kernel<<<g, 256, GEMM_SMEM>>>(ah, al, b2h, b2l, b_out, out,
                                               DMODEL);
    }
}

// round 10
// speedup vs baseline: 1.4761x; 1.3347x over previous
#include <cuda_runtime.h>
#include <cuda_fp16.h>
#include <math.h>
#include <cstdint>

#define BSZ 128
#define TLEN 256
#define DMODEL 512
#define NHEADS 8
#define HDIM 64
#define MROWS (BSZ * TLEN)          // 32768
#define GK 512                       // K dim of both GEMMs

// ---------------------------------------------------------------------------
// Scratch: __device__ globals (allocation-free rule).
// ---------------------------------------------------------------------------
__device__ float g_qkv[(size_t)MROWS * 3 * DMODEL];   // [32768,1536]
__device__ __half g_ah[(size_t)MROWS * GK];           // A (x rounded, then attn out)
__device__ __half g_bh[(size_t)(3 * DMODEL) * GK];    // W_qkv^T hi
__device__ __half g_bl[(size_t)(3 * DMODEL) * GK];    // W_qkv^T lo
__device__ __half g_b2h[(size_t)DMODEL * GK];         // W_out^T hi
__device__ __half g_b2l[(size_t)DMODEL * GK];         // W_out^T lo

// ---------------------------------------------------------------------------
// PTX helpers — plain-sm_103-legal only (mma.sync / ldmatrix / cp.async).
// ---------------------------------------------------------------------------
__device__ __forceinline__ uint32_t smem_to_u32(const void* smem_ptr) {
    uint32_t addr;
    asm("{ .reg .u64 tmp; cvta.to.shared.u64 tmp, %1; cvt.u32.u64 %0, tmp; }"
        : "=r"(addr) : "l"(smem_ptr));
    return addr;
}

__device__ __forceinline__ void ldsm_x4(uint32_t* r, uint32_t addr) {
    asm volatile("ldmatrix.sync.aligned.m8n8.x4.shared.b16 {%0,%1,%2,%3}, [%4];"
                 : "=r"(r[0]), "=r"(r[1]), "=r"(r[2]), "=r"(r[3]) : "r"(addr));
}

__device__ __forceinline__ void mma16816(float* c, const uint32_t* a,
                                         const uint32_t* b) {
    asm volatile(
        "mma.sync.aligned.m16n8k16.row.col.f32.f16.f16.f32 "
        "{%0,%1,%2,%3}, {%4,%5,%6,%7}, {%8,%9}, {%0,%1,%2,%3};"
        : "+f"(c[0]), "+f"(c[1]), "+f"(c[2]), "+f"(c[3])
        : "r"(a[0]), "r"(a[1]), "r"(a[2]), "r"(a[3]), "r"(b[0]), "r"(b[1]));
}

__device__ __forceinline__ void cp_async16(uint32_t saddr, const void* gaddr) {
    asm volatile("cp.async.cg.shared.global [%0], [%1], 16;"
                 :: "r"(saddr), "l"(gaddr));
}
#define CP_COMMIT() asm volatile("cp.async.commit_group;" ::: "memory")
#define CP_WAIT(n)  asm volatile("cp.async.wait_group %0;" :: "n"(n) : "memory")

// ---------------------------------------------------------------------------
// Conversion kernels
// ---------------------------------------------------------------------------
__global__ void round_f16_kernel(const float* __restrict__ in,
                                 __half* __restrict__ hi, int n4) {
    int i = blockIdx.x * blockDim.x + threadIdx.x;
    if (i >= n4) return;
    float4 v = ((const float4*)in)[i];
    __half2* h2 = (__half2*)(hi + (size_t)i * 4);
    h2[0] = __floats2half2_rn(v.x, v.y);
    h2[1] = __floats2half2_rn(v.z, v.w);
}

// W[K,N] fp32 -> Wt hi/lo [N,K] fp16 (transpose + 22-bit split)
__global__ void splitT_f16_kernel(const float* __restrict__ W,
                                  __half* __restrict__ th,
                                  __half* __restrict__ tl,
                                  int K, int N) {
    int idx = blockIdx.x * blockDim.x + threadIdx.x;
    if (idx >= K * N) return;
    int k = idx / N, n = idx % N;
    float v = W[idx];
    __half h = __float2half_rn(v);
    th[(size_t)n * K + k] = h;
    tl[(size_t)n * K + k] = __float2half_rn(v - __half2float(h));
}

// ---------------------------------------------------------------------------
// fp16 2-term mma.sync GEMM: C = Ah @ (Bh + Bl)^T + bias.
// A rounded once to fp16 (err 2^-11); B split to 22 bits. 2 MMAs per tile
// (was 3) — MMA-issue-bound kernel, so expect ~2/3 the time.
// 128x128 tile, 8 warps (32x64), BK=32, double buffered.
// ---------------------------------------------------------------------------
#define ROWB 80
#define SM_TILE (128 * ROWB)           // 10240
#define SM_T_AH 0
#define SM_T_BH (SM_TILE)
#define SM_T_BL (2 * SM_TILE)
#define SM_STAGE (3 * SM_TILE)         // 30720
#define GEMM_SMEM (2 * SM_STAGE)       // 61440

__global__ __launch_bounds__(256, 2)
void gemm_mma_kernel(const __half* __restrict__ Ah,
                     const __half* __restrict__ Bh,
                     const __half* __restrict__ Bl,
                     const float* __restrict__ bias,
                     float* __restrict__ C, int N) {
    extern __shared__ char smem[];
    const uint32_t sbase = smem_to_u32(smem);
    const int tid = threadIdx.x;
    const int wid = tid >> 5, lane = tid & 31;
    const int warpM = wid & 3, warpN = wid >> 2;
    const int m0 = blockIdx.y * 128, n0 = blockIdx.x * 128;

    const char* gAh = (const char*)(Ah + (size_t)m0 * GK);
    const char* gBh = (const char*)(Bh + (size_t)n0 * GK);
    const char* gBl = (const char*)(Bl + (size_t)n0 * GK);

    float acc[2][8][4];
#pragma unroll
    for (int mt = 0; mt < 2; mt++)
#pragma unroll
        for (int nt = 0; nt < 8; nt++)
#pragma unroll
            for (int r = 0; r < 4; r++) acc[mt][nt][r] = 0.0f;

    const int lr2 = (tid >> 2);
    const int lc2 = (tid & 3);

    {
        uint32_t sb = sbase;
#pragma unroll
        for (int p = 0; p < 2; p++) {
            int r = lr2 + p * 64;
            uint32_t so = r * ROWB + lc2 * 16;
            size_t go = (size_t)r * (GK * 2) + lc2 * 16;
            cp_async16(sb + SM_T_AH + so, gAh + go);
            cp_async16(sb + SM_T_BH + so, gBh + go);
            cp_async16(sb + SM_T_BL + so, gBl + go);
        }
        CP_COMMIT();
    }

    const int lrow = lane & 15;
    const int lcs = lane >> 4;

    constexpr int NSTAGES = GK / 32;
    for (int s = 0; s < NSTAGES; s++) {
        if (s + 1 < NSTAGES) {
            uint32_t sb = sbase + ((s + 1) & 1) * SM_STAGE;
            const int kbyte = (s + 1) * 64;
#pragma unroll
            for (int p = 0; p < 2; p++) {
                int r = lr2 + p * 64;
                uint32_t so = r * ROWB + lc2 * 16;
                size_t go = (size_t)r * (GK * 2) + kbyte + lc2 * 16;
                cp_async16(sb + SM_T_AH + so, gAh + go);
                cp_async16(sb + SM_T_BH + so, gBh + go);
                cp_async16(sb + SM_T_BL + so, gBl + go);
            }
            CP_COMMIT();
            CP_WAIT(1);
        } else {
            CP_WAIT(0);
        }
        __syncthreads();

        const uint32_t sb = sbase + (s & 1) * SM_STAGE;
#pragma unroll
        for (int kk = 0; kk < 2; kk++) {
            const uint32_t coff = (kk * 2 + lcs) * 16;
            uint32_t aH[2][4];
#pragma unroll
            for (int mt = 0; mt < 2; mt++) {
                uint32_t ro = (uint32_t)(warpM * 32 + mt * 16 + lrow) * ROWB + coff;
                ldsm_x4(aH[mt], sb + SM_T_AH + ro);
            }
#pragma unroll
            for (int q = 0; q < 4; q++) {
                uint32_t ro = (uint32_t)(warpN * 64 + q * 16 + lrow) * ROWB + coff;
                uint32_t tH[4], tL[4];
                ldsm_x4(tH, sb + SM_T_BH + ro);
                ldsm_x4(tL, sb + SM_T_BL + ro);
                uint32_t b0H[2] = {tH[0], tH[2]}, b1H[2] = {tH[1], tH[3]};
                uint32_t b0L[2] = {tL[0], tL[2]}, b1L[2] = {tL[1], tL[3]};
#pragma unroll
                for (int mt = 0; mt < 2; mt++) {
                    mma16816(acc[mt][2 * q],     aH[mt], b0H);
                    mma16816(acc[mt][2 * q + 1], aH[mt], b1H);
                    mma16816(acc[mt][2 * q],     aH[mt], b0L);
                    mma16816(acc[mt][2 * q + 1], aH[mt], b1L);
                }
            }
        }
        __syncthreads();
    }

    const int g = lane >> 2, tc4 = lane & 3;
#pragma unroll
    for (int mt = 0; mt < 2; mt++) {
        const int row = m0 + warpM * 32 + mt * 16 + g;
#pragma unroll
        for (int nt = 0; nt < 8; nt++) {
            const int col = n0 + warpN * 64 + nt * 8 + tc4 * 2;
            const float bv0 = bias[col], bv1 = bias[col + 1];
            float2 v0, v1;
            v0.x = acc[mt][nt][0] + bv0; v0.y = acc[mt][nt][1] + bv1;
            v1.x = acc[mt][nt][2] + bv0; v1.y = acc[mt][nt][3] + bv1;
            *(float2*)(C + (size_t)row * N + col) = v0;
            *(float2*)(C + (size_t)(row + 8) * N + col) = v1;
        }
    }
}

// ---------------------------------------------------------------------------
// Flash attention, fp16 2-term: Q and P single fp16; K and V split hi/lo.
// One block per (b,h), 8 warps; warp handles m16 tiles {w, 15-w}.
// Output written once as rounded fp16 into the out-GEMM A buffer.
// ---------------------------------------------------------------------------
#define AT_QH 0
#define AT_KH 36864
#define AT_KL 73728
#define AT_VTH 110592
#define AT_VTL 144384
#define ATTN_SMEM 178176
#define AT_VSTAGE 0          // fp32 V staging [256][272B] = 69632B, < AT_KH+... safe (overlaps AT_QH only)

__global__ __launch_bounds__(256, 1)
void attn_mma_kernel(const float* __restrict__ qkv,
                     __half* __restrict__ yh) {
    extern __shared__ char smem[];
    const uint32_t sbase = smem_to_u32(smem);
    const int b = blockIdx.x >> 3;
    const int h = blockIdx.x & 7;
    const int tid = threadIdx.x;
    const int wid = tid >> 5, lane = tid & 31;
    const int g = lane >> 2, tq = lane & 3;
    const int lrow = lane & 15, lcs = lane >> 4;
    const float SCALE = 0.125f;

    const float* base = qkv + (size_t)b * TLEN * (3 * DMODEL) + h * HDIM;

    // 1) stage V fp32 coalesced into [256][272B] (overlaps Q region)
    for (int i = tid; i < 256 * 16; i += 256) {
        const int t = i >> 4, c = i & 15;
        float4 v = *(const float4*)(base + (size_t)t * (3 * DMODEL) + 2 * DMODEL + c * 4);
        *(float4*)(smem + AT_VSTAGE + t * 272 + c * 16) = v;
    }
    __syncthreads();

    // 2) transpose + split into Vth/Vtl [64][528B]
    {
        const int d = tid & 63;
        const int jb = (tid >> 6) * 64;
#pragma unroll 4
        for (int jp = 0; jp < 32; jp++) {
            const int j = jb + 2 * jp;
            float v0 = *(const float*)(smem + AT_VSTAGE + j * 272 + d * 4);
            float v1 = *(const float*)(smem + AT_VSTAGE + (j + 1) * 272 + d * 4);
            __half h0 = __float2half_rn(v0);
            __half h1 = __float2half_rn(v1);
            __half l0 = __float2half_rn(v0 - __half2float(h0));
            __half l1 = __float2half_rn(v1 - __half2float(h1));
            *(__half2*)(smem + AT_VTH + d * 528 + j * 2) = __halves2half2(h0, h1);
            *(__half2*)(smem + AT_VTL + d * 528 + j * 2) = __halves2half2(l0, l1);
        }
    }
    __syncthreads();

    // 3) load Q (rounded) and K (split) into [256][144B]
    for (int i = tid; i < 256 * 16; i += 256) {
        const int t = i >> 4, c = i & 15;
        const size_t roff = (size_t)t * (3 * DMODEL);
        float4 q = *(const float4*)(base + roff + c * 4);
        float4 k = *(const float4*)(base + roff + DMODEL + c * 4);
        float kv[4] = {k.x, k.y, k.z, k.w};
        __half kh[4], kl[4];
#pragma unroll
        for (int j = 0; j < 4; j++) {
            kh[j] = __float2half_rn(kv[j]);
            kl[j] = __float2half_rn(kv[j] - __half2float(kh[j]));
        }
        const int so = t * 144 + c * 8;
        *(__half2*)(smem + AT_QH + so)     = __floats2half2_rn(q.x, q.y);
        *(__half2*)(smem + AT_QH + so + 4) = __floats2half2_rn(q.z, q.w);
        *(__half2*)(smem + AT_KH + so)     = __halves2half2(kh[0], kh[1]);
        *(__half2*)(smem + AT_KH + so + 4) = __halves2half2(kh[2], kh[3]);
        *(__half2*)(smem + AT_KL + so)     = __halves2half2(kl[0], kl[1]);
        *(__half2*)(smem + AT_KL + so + 4) = __halves2half2(kl[2], kl[3]);
    }
    __syncthreads();

    // 4) compute: two m16 tiles per warp
#pragma unroll
    for (int half = 0; half < 2; half++) {
        const int tile = (half == 0) ? wid : 15 - wid;
        const int nch = tile / 4 + 1;

        float o[8][4];
#pragma unroll
        for (int nt = 0; nt < 8; nt++)
#pragma unroll
            for (int r = 0; r < 4; r++) o[nt][r] = 0.0f;
        float m0 = -1e30f, m1 = -1e30f, l0 = 0.0f, l1 = 0.0f;

        for (int c = 0; c < nch; c++) {
            float S[8][4];
#pragma unroll
            for (int nt = 0; nt < 8; nt++)
#pragma unroll
                for (int r = 0; r < 4; r++) S[nt][r] = 0.0f;

            // ---- S = Q @ K^T (2-term) ----
#pragma unroll
            for (int kt = 0; kt < 4; kt++) {
                uint32_t aH[4];
                const uint32_t qro = (uint32_t)(tile * 16 + lrow) * 144 + kt * 32 + lcs * 16;
                ldsm_x4(aH, sbase + AT_QH + qro);
#pragma unroll
                for (int q = 0; q < 4; q++) {
                    const uint32_t kro =
                        (uint32_t)(c * 64 + q * 16 + lrow) * 144 + kt * 32 + lcs * 16;
                    uint32_t tH[4], tL[4];
                    ldsm_x4(tH, sbase + AT_KH + kro);
                    ldsm_x4(tL, sbase + AT_KL + kro);
                    uint32_t b0H[2] = {tH[0], tH[2]}, b1H[2] = {tH[1], tH[3]};
                    uint32_t b0L[2] = {tL[0], tL[2]}, b1L[2] = {tL[1], tL[3]};
                    mma16816(S[2 * q],     aH, b0H);
                    mma16816(S[2 * q + 1], aH, b1H);
                    mma16816(S[2 * q],     aH, b0L);
                    mma16816(S[2 * q + 1], aH, b1L);
                }
            }

            // ---- scale + causal mask ----
            const int r0 = tile * 16 + g, r1 = r0 + 8;
            if (c == nch - 1) {
#pragma unroll
                for (int nt = 0; nt < 8; nt++) {
                    const int col = c * 64 + nt * 8 + 2 * tq;
                    S[nt][0] = (col     <= r0) ? S[nt][0] * SCALE : -1e30f;
                    S[nt][1] = (col + 1 <= r0) ? S[nt][1] * SCALE : -1e30f;
                    S[nt][2] = (col     <= r1) ? S[nt][2] * SCALE : -1e30f;
                    S[nt][3] = (col + 1 <= r1) ? S[nt][3] * SCALE : -1e30f;
                }
            } else {
#pragma unroll
                for (int nt = 0; nt < 8; nt++)
#pragma unroll
                    for (int r = 0; r < 4; r++) S[nt][r] *= SCALE;
            }

            // ---- online softmax ----
            float cm0 = -1e30f, cm1 = -1e30f;
#pragma unroll
            for (int nt = 0; nt < 8; nt++) {
                cm0 = fmaxf(cm0, fmaxf(S[nt][0], S[nt][1]));
                cm1 = fmaxf(cm1, fmaxf(S[nt][2], S[nt][3]));
            }
            cm0 = fmaxf(cm0, __shfl_xor_sync(0xffffffffu, cm0, 1));
            cm0 = fmaxf(cm0, __shfl_xor_sync(0xffffffffu, cm0, 2));
            cm1 = fmaxf(cm1, __shfl_xor_sync(0xffffffffu, cm1, 1));
            cm1 = fmaxf(cm1, __shfl_xor_sync(0xffffffffu, cm1, 2));
            const float mn0 = fmaxf(m0, cm0), mn1 = fmaxf(m1, cm1);
            const float a0 = __expf(m0 - mn0), a1 = __expf(m1 - mn1);
            m0 = mn0; m1 = mn1;

            float rs0 = 0.0f, rs1 = 0.0f;
#pragma unroll
            for (int nt = 0; nt < 8; nt++) {
                S[nt][0] = __expf(S[nt][0] - mn0);
                S[nt][1] = __expf(S[nt][1] - mn0);
                S[nt][2] = __expf(S[nt][2] - mn1);
                S[nt][3] = __expf(S[nt][3] - mn1);
                rs0 += S[nt][0] + S[nt][1];
                rs1 += S[nt][2] + S[nt][3];
            }
            rs0 += __shfl_xor_sync(0xffffffffu, rs0, 1);
            rs0 += __shfl_xor_sync(0xffffffffu, rs0, 2);
            rs1 += __shfl_xor_sync(0xffffffffu, rs1, 1);
            rs1 += __shfl_xor_sync(0xffffffffu, rs1, 2);
            l0 = l0 * a0 + rs0;
            l1 = l1 * a1 + rs1;

#pragma unroll
            for (int nt = 0; nt < 8; nt++) {
                o[nt][0] *= a0; o[nt][1] *= a0;
                o[nt][2] *= a1; o[nt][3] *= a1;
            }

            // ---- P frags (single fp16) ----
            uint32_t pH[4][4];
#pragma unroll
            for (int kt = 0; kt < 4; kt++) {
#pragma unroll
                for (int part = 0; part < 4; part++) {
                    const int nt = 2 * kt + (part >> 1);
                    const int rb = (part & 1) * 2;
                    __half2 hh = __floats2half2_rn(S[nt][rb], S[nt][rb + 1]);
                    pH[kt][part] = *(uint32_t*)&hh;
                }
            }

            // ---- O += P @ V (2-term on V) ----
#pragma unroll
            for (int kt = 0; kt < 4; kt++) {
#pragma unroll
                for (int q = 0; q < 4; q++) {
                    const uint32_t vro =
                        (uint32_t)(q * 16 + lrow) * 528 + c * 128 + kt * 32 + lcs * 16;
                    uint32_t tH[4], tL[4];
                    ldsm_x4(tH, sbase + AT_VTH + vro);
                    ldsm_x4(tL, sbase + AT_VTL + vro);
                    uint32_t b0H[2] = {tH[0], tH[2]}, b1H[2] = {tH[1], tH[3]};
                    uint32_t b0L[2] = {tL[0], tL[2]}, b1L[2] = {tL[1], tL[3]};
                    mma16816(o[2 * q],     pH[kt], b0H);
                    mma16816(o[2 * q + 1], pH[kt], b1H);
                    mma16816(o[2 * q],     pH[kt], b0L);
                    mma16816(o[2 * q + 1], pH[kt], b1L);
                }
            }
        }

        // ---- normalize + write rounded fp16 ----
        const float inv0 = 1.0f / l0, inv1 = 1.0f / l1;
        const int row0 = b * TLEN + tile * 16 + g;
#pragma unroll
        for (int nt = 0; nt < 8; nt++) {
            const int col = h * HDIM + nt * 8 + 2 * tq;
            const size_t i0 = (size_t)row0 * DMODEL + col;
            const size_t i1 = i0 + (size_t)8 * DMODEL;
            *(__half2*)(yh + i0) = __floats2half2_rn(o[nt][0] * inv0, o[nt][1] * inv0);
            *(__half2*)(yh + i1) = __floats2half2_rn(o[nt][2] * inv1, o[nt][3] * inv1);
        }
    }
}

// ---------------------------------------------------------------------------
extern "C" void kernel_launch(void* const* d_in, const int* in_sizes, int n_in,
                              void* d_out, int out_size) {
    const float* x     = (const float*)d_in[0];
    const float* W_qkv = (const float*)d_in[1];
    const float* b_qkv = (const float*)d_in[2];
    const float* W_out = (const float*)d_in[3];
    const float* b_out = (const float*)d_in[4];
    float* out = (float*)d_out;

    float* qkv;
    __half *ah, *bh, *bl, *b2h, *b2l;
    cudaGetSymbolAddress((void**)&qkv, g_qkv);
    cudaGetSymbolAddress((void**)&ah, g_ah);
    cudaGetSymbolAddress((void**)&bh, g_bh);
    cudaGetSymbolAddress((void**)&bl, g_bl);
    cudaGetSymbolAddress((void**)&b2h, g_b2h);
    cudaGetSymbolAddress((void**)&b2l, g_b2l);

    cudaFuncSetAttribute(gemm_mma_kernel,
                         cudaFuncAttributeMaxDynamicSharedMemorySize, GEMM_SMEM);
    cudaFuncSetAttribute(attn_mma_kernel,
                         cudaFuncAttributeMaxDynamicSharedMemorySize, ATTN_SMEM);

    // 1) round x -> fp16
    {
        const int n4 = MROWS * GK / 4;
        round_f16_kernel<<<(n4 + 255) / 256, 256>>>(x, ah, n4);
    }
    // 2) split+transpose weights (22-bit fp16 hi/lo)
    splitT_f16_kernel<<<(GK * 3 * DMODEL + 255) / 256, 256>>>(W_qkv, bh, bl,
                                                              GK, 3 * DMODEL);
    splitT_f16_kernel<<<(GK * DMODEL + 255) / 256, 256>>>(W_out, b2h, b2l,
                                                          GK, DMODEL);

    // 3) QKV projection (2-term fp16 tensor cores)
    {
        dim3 g(3 * DMODEL / 128, MROWS / 128);
        gemm_mma_kernel<<<g, 256, GEMM_SMEM>>>(ah, bh, bl, b_qkv, qkv,
                                               3 * DMODEL);
    }

    // 4) flash attention, writes rounded fp16 y into ah
    attn_mma_kernel<<<BSZ * NHEADS, 256, ATTN_SMEM>>>(qkv, ah);

    // 5) output projection (2-term fp16 tensor cores)
    {
        dim3 g(DMODEL / 128, MROWS / 128);
        gemm_mma_kernel<<<g, 256, GEMM_SMEM>>>(ah, b2h, b2l, b_out, out,
                                               DMODEL);
    }
}

// round 11
// speedup vs baseline: 2.4009x; 1.6265x over previous
#include <cuda_runtime.h>
#include <cuda_fp16.h>
#include <math.h>
#include <cstdint>

#define BSZ 128
#define TLEN 256
#define DMODEL 512
#define NHEADS 8
#define HDIM 64
#define MROWS (BSZ * TLEN)          // 32768
#define GK 512                       // K dim of both GEMMs

// ---------------------------------------------------------------------------
// Scratch: __device__ globals (allocation-free rule).
// ---------------------------------------------------------------------------
__device__ float g_qkv[(size_t)MROWS * 3 * DMODEL];   // [32768,1536]
__device__ __half g_ah[(size_t)MROWS * GK];           // A (x rounded, then attn out)
__device__ __half g_bh[(size_t)(3 * DMODEL) * GK];    // W_qkv^T fp16
__device__ __half g_b2h[(size_t)DMODEL * GK];         // W_out^T fp16

// ---------------------------------------------------------------------------
// PTX helpers — plain-sm_103-legal only (mma.sync / ldmatrix / cp.async).
// ---------------------------------------------------------------------------
__device__ __forceinline__ uint32_t smem_to_u32(const void* smem_ptr) {
    uint32_t addr;
    asm("{ .reg .u64 tmp; cvta.to.shared.u64 tmp, %1; cvt.u32.u64 %0, tmp; }"
        : "=r"(addr) : "l"(smem_ptr));
    return addr;
}

__device__ __forceinline__ void ldsm_x4(uint32_t* r, uint32_t addr) {
    asm volatile("ldmatrix.sync.aligned.m8n8.x4.shared.b16 {%0,%1,%2,%3}, [%4];"
                 : "=r"(r[0]), "=r"(r[1]), "=r"(r[2]), "=r"(r[3]) : "r"(addr));
}

__device__ __forceinline__ void mma16816(float* c, const uint32_t* a,
                                         const uint32_t* b) {
    asm volatile(
        "mma.sync.aligned.m16n8k16.row.col.f32.f16.f16.f32 "
        "{%0,%1,%2,%3}, {%4,%5,%6,%7}, {%8,%9}, {%0,%1,%2,%3};"
        : "+f"(c[0]), "+f"(c[1]), "+f"(c[2]), "+f"(c[3])
        : "r"(a[0]), "r"(a[1]), "r"(a[2]), "r"(a[3]), "r"(b[0]), "r"(b[1]));
}

__device__ __forceinline__ void cp_async16(uint32_t saddr, const void* gaddr) {
    asm volatile("cp.async.cg.shared.global [%0], [%1], 16;"
                 :: "r"(saddr), "l"(gaddr));
}
#define CP_COMMIT() asm volatile("cp.async.commit_group;" ::: "memory")
#define CP_WAIT(n)  asm volatile("cp.async.wait_group %0;" :: "n"(n) : "memory")

// ---------------------------------------------------------------------------
// Conversion kernels
// ---------------------------------------------------------------------------
__global__ void round_f16_kernel(const float* __restrict__ in,
                                 __half* __restrict__ hi, int n4) {
    int i = blockIdx.x * blockDim.x + threadIdx.x;
    if (i >= n4) return;
    float4 v = ((const float4*)in)[i];
    __half2* h2 = (__half2*)(hi + (size_t)i * 4);
    h2[0] = __floats2half2_rn(v.x, v.y);
    h2[1] = __floats2half2_rn(v.z, v.w);
}

// W[K,N] fp32 -> Wt[N,K] fp16 (transpose + round)
__global__ void roundT_f16_kernel(const float* __restrict__ W,
                                  __half* __restrict__ th, int K, int N) {
    int idx = blockIdx.x * blockDim.x + threadIdx.x;
    if (idx >= K * N) return;
    int k = idx / N, n = idx % N;
    th[(size_t)n * K + k] = __float2half_rn(W[idx]);
}

// ---------------------------------------------------------------------------
// fp16 single-term mma.sync GEMM: C = Ah @ Bh^T + bias (1 MMA per tile —
// MMA-issue bound at rt~16 cyc/HMMA-f32acc, so time ~ MMA count).
// 128x128 tile, 8 warps (32x64), BK=32, double buffered, 20KB/stage.
// ---------------------------------------------------------------------------
#define ROWB 80
#define SM_TILE (128 * ROWB)           // 10240
#define SM_T_A 0
#define SM_T_B (SM_TILE)
#define SM_STAGE (2 * SM_TILE)         // 20480
#define GEMM_SMEM (2 * SM_STAGE)       // 40960

__global__ __launch_bounds__(256, 2)
void gemm_mma_kernel(const __half* __restrict__ Ah,
                     const __half* __restrict__ Bh,
                     const float* __restrict__ bias,
                     float* __restrict__ C, int N) {
    extern __shared__ char smem[];
    const uint32_t sbase = smem_to_u32(smem);
    const int tid = threadIdx.x;
    const int wid = tid >> 5, lane = tid & 31;
    const int warpM = wid & 3, warpN = wid >> 2;
    const int m0 = blockIdx.y * 128, n0 = blockIdx.x * 128;

    const char* gA = (const char*)(Ah + (size_t)m0 * GK);
    const char* gB = (const char*)(Bh + (size_t)n0 * GK);

    float acc[2][8][4];
#pragma unroll
    for (int mt = 0; mt < 2; mt++)
#pragma unroll
        for (int nt = 0; nt < 8; nt++)
#pragma unroll
            for (int r = 0; r < 4; r++) acc[mt][nt][r] = 0.0f;

    const int lr2 = (tid >> 2);          // 0..63
    const int lc2 = (tid & 3);           // 0..3

    {
        uint32_t sb = sbase;
#pragma unroll
        for (int p = 0; p < 2; p++) {
            int r = lr2 + p * 64;
            uint32_t so = r * ROWB + lc2 * 16;
            size_t go = (size_t)r * (GK * 2) + lc2 * 16;
            cp_async16(sb + SM_T_A + so, gA + go);
            cp_async16(sb + SM_T_B + so, gB + go);
        }
        CP_COMMIT();
    }

    const int lrow = lane & 15;
    const int lcs = lane >> 4;

    constexpr int NSTAGES = GK / 32;     // 16
    for (int s = 0; s < NSTAGES; s++) {
        if (s + 1 < NSTAGES) {
            uint32_t sb = sbase + ((s + 1) & 1) * SM_STAGE;
            const int kbyte = (s + 1) * 64;
#pragma unroll
            for (int p = 0; p < 2; p++) {
                int r = lr2 + p * 64;
                uint32_t so = r * ROWB + lc2 * 16;
                size_t go = (size_t)r * (GK * 2) + kbyte + lc2 * 16;
                cp_async16(sb + SM_T_A + so, gA + go);
                cp_async16(sb + SM_T_B + so, gB + go);
            }
            CP_COMMIT();
            CP_WAIT(1);
        } else {
            CP_WAIT(0);
        }
        __syncthreads();

        const uint32_t sb = sbase + (s & 1) * SM_STAGE;
#pragma unroll
        for (int kk = 0; kk < 2; kk++) {
            const uint32_t coff = (kk * 2 + lcs) * 16;
            uint32_t aH[2][4];
#pragma unroll
            for (int mt = 0; mt < 2; mt++) {
                uint32_t ro = (uint32_t)(warpM * 32 + mt * 16 + lrow) * ROWB + coff;
                ldsm_x4(aH[mt], sb + SM_T_A + ro);
            }
#pragma unroll
            for (int q = 0; q < 4; q++) {
                uint32_t ro = (uint32_t)(warpN * 64 + q * 16 + lrow) * ROWB + coff;
                uint32_t tB[4];
                ldsm_x4(tB, sb + SM_T_B + ro);
                uint32_t b0[2] = {tB[0], tB[2]}, b1[2] = {tB[1], tB[3]};
#pragma unroll
                for (int mt = 0; mt < 2; mt++) {
                    mma16816(acc[mt][2 * q],     aH[mt], b0);
                    mma16816(acc[mt][2 * q + 1], aH[mt], b1);
                }
            }
        }
        __syncthreads();
    }

    const int g = lane >> 2, tc4 = lane & 3;
#pragma unroll
    for (int mt = 0; mt < 2; mt++) {
        const int row = m0 + warpM * 32 + mt * 16 + g;
#pragma unroll
        for (int nt = 0; nt < 8; nt++) {
            const int col = n0 + warpN * 64 + nt * 8 + tc4 * 2;
            const float bv0 = bias[col], bv1 = bias[col + 1];
            float2 v0, v1;
            v0.x = acc[mt][nt][0] + bv0; v0.y = acc[mt][nt][1] + bv1;
            v1.x = acc[mt][nt][2] + bv0; v1.y = acc[mt][nt][3] + bv1;
            *(float2*)(C + (size_t)row * N + col) = v0;
            *(float2*)(C + (size_t)(row + 8) * N + col) = v1;
        }
    }
}

// ---------------------------------------------------------------------------
// Flash attention, single-term fp16 (Q, K, P, V all rounded fp16).
// One block per (b,h), 8 warps; warp handles m16 tiles {w, 15-w}.
// smem 105KB -> 2 CTAs/SM. Output written rounded fp16 into out-GEMM A.
// ---------------------------------------------------------------------------
#define AT_QH 0
#define AT_KH 36864
#define AT_VTH 73728
#define ATTN_SMEM 107520
#define AT_VSTAGE 0          // fp32 V staging [256][272B]=69632B, inside Q+K region

__global__ __launch_bounds__(256, 2)
void attn_mma_kernel(const float* __restrict__ qkv,
                     __half* __restrict__ yh) {
    extern __shared__ char smem[];
    const uint32_t sbase = smem_to_u32(smem);
    const int b = blockIdx.x >> 3;
    const int h = blockIdx.x & 7;
    const int tid = threadIdx.x;
    const int wid = tid >> 5, lane = tid & 31;
    const int g = lane >> 2, tq = lane & 3;
    const int lrow = lane & 15, lcs = lane >> 4;
    const float SCALE = 0.125f;

    const float* base = qkv + (size_t)b * TLEN * (3 * DMODEL) + h * HDIM;

    // 1) stage V fp32 coalesced into [256][272B] (overlaps Q+K region)
    for (int i = tid; i < 256 * 16; i += 256) {
        const int t = i >> 4, c = i & 15;
        float4 v = *(const float4*)(base + (size_t)t * (3 * DMODEL) + 2 * DMODEL + c * 4);
        *(float4*)(smem + AT_VSTAGE + t * 272 + c * 16) = v;
    }
    __syncthreads();

    // 2) transpose + round into Vt [64][528B]
    {
        const int d = tid & 63;
        const int jb = (tid >> 6) * 64;
#pragma unroll 4
        for (int jp = 0; jp < 32; jp++) {
            const int j = jb + 2 * jp;
            float v0 = *(const float*)(smem + AT_VSTAGE + j * 272 + d * 4);
            float v1 = *(const float*)(smem + AT_VSTAGE + (j + 1) * 272 + d * 4);
            *(__half2*)(smem + AT_VTH + d * 528 + j * 2) = __floats2half2_rn(v0, v1);
        }
    }
    __syncthreads();

    // 3) load Q, K rounded fp16 into [256][144B] each
    for (int i = tid; i < 256 * 16; i += 256) {
        const int t = i >> 4, c = i & 15;
        const size_t roff = (size_t)t * (3 * DMODEL);
        float4 q = *(const float4*)(base + roff + c * 4);
        float4 k = *(const float4*)(base + roff + DMODEL + c * 4);
        const int so = t * 144 + c * 8;
        *(__half2*)(smem + AT_QH + so)     = __floats2half2_rn(q.x, q.y);
        *(__half2*)(smem + AT_QH + so + 4) = __floats2half2_rn(q.z, q.w);
        *(__half2*)(smem + AT_KH + so)     = __floats2half2_rn(k.x, k.y);
        *(__half2*)(smem + AT_KH + so + 4) = __floats2half2_rn(k.z, k.w);
    }
    __syncthreads();

    // 4) compute: two m16 tiles per warp
#pragma unroll
    for (int half = 0; half < 2; half++) {
        const int tile = (half == 0) ? wid : 15 - wid;
        const int nch = tile / 4 + 1;

        float o[8][4];
#pragma unroll
        for (int nt = 0; nt < 8; nt++)
#pragma unroll
            for (int r = 0; r < 4; r++) o[nt][r] = 0.0f;
        float m0 = -1e30f, m1 = -1e30f, l0 = 0.0f, l1 = 0.0f;

        for (int c = 0; c < nch; c++) {
            float S[8][4];
#pragma unroll
            for (int nt = 0; nt < 8; nt++)
#pragma unroll
                for (int r = 0; r < 4; r++) S[nt][r] = 0.0f;

            // ---- S = Q @ K^T ----
#pragma unroll
            for (int kt = 0; kt < 4; kt++) {
                uint32_t aH[4];
                const uint32_t qro = (uint32_t)(tile * 16 + lrow) * 144 + kt * 32 + lcs * 16;
                ldsm_x4(aH, sbase + AT_QH + qro);
#pragma unroll
                for (int q = 0; q < 4; q++) {
                    const uint32_t kro =
                        (uint32_t)(c * 64 + q * 16 + lrow) * 144 + kt * 32 + lcs * 16;
                    uint32_t tK[4];
                    ldsm_x4(tK, sbase + AT_KH + kro);
                    uint32_t b0[2] = {tK[0], tK[2]}, b1[2] = {tK[1], tK[3]};
                    mma16816(S[2 * q],     aH, b0);
                    mma16816(S[2 * q + 1], aH, b1);
                }
            }

            // ---- scale + causal mask ----
            const int r0 = tile * 16 + g, r1 = r0 + 8;
            if (c == nch - 1) {
#pragma unroll
                for (int nt = 0; nt < 8; nt++) {
                    const int col = c * 64 + nt * 8 + 2 * tq;
                    S[nt][0] = (col     <= r0) ? S[nt][0] * SCALE : -1e30f;
                    S[nt][1] = (col + 1 <= r0) ? S[nt][1] * SCALE : -1e30f;
                    S[nt][2] = (col     <= r1) ? S[nt][2] * SCALE : -1e30f;
                    S[nt][3] = (col + 1 <= r1) ? S[nt][3] * SCALE : -1e30f;
                }
            } else {
#pragma unroll
                for (int nt = 0; nt < 8; nt++)
#pragma unroll
                    for (int r = 0; r < 4; r++) S[nt][r] *= SCALE;
            }

            // ---- online softmax ----
            float cm0 = -1e30f, cm1 = -1e30f;
#pragma unroll
            for (int nt = 0; nt < 8; nt++) {
                cm0 = fmaxf(cm0, fmaxf(S[nt][0], S[nt][1]));
                cm1 = fmaxf(cm1, fmaxf(S[nt][2], S[nt][3]));
            }
            cm0 = fmaxf(cm0, __shfl_xor_sync(0xffffffffu, cm0, 1));
            cm0 = fmaxf(cm0, __shfl_xor_sync(0xffffffffu, cm0, 2));
            cm1 = fmaxf(cm1, __shfl_xor_sync(0xffffffffu, cm1, 1));
            cm1 = fmaxf(cm1, __shfl_xor_sync(0xffffffffu, cm1, 2));
            const float mn0 = fmaxf(m0, cm0), mn1 = fmaxf(m1, cm1);
            const float a0 = __expf(m0 - mn0), a1 = __expf(m1 - mn1);
            m0 = mn0; m1 = mn1;

            float rs0 = 0.0f, rs1 = 0.0f;
#pragma unroll
            for (int nt = 0; nt < 8; nt++) {
                S[nt][0] = __expf(S[nt][0] - mn0);
                S[nt][1] = __expf(S[nt][1] - mn0);
                S[nt][2] = __expf(S[nt][2] - mn1);
                S[nt][3] = __expf(S[nt][3] - mn1);
                rs0 += S[nt][0] + S[nt][1];
                rs1 += S[nt][2] + S[nt][3];
            }
            rs0 += __shfl_xor_sync(0xffffffffu, rs0, 1);
            rs0 += __shfl_xor_sync(0xffffffffu, rs0, 2);
            rs1 += __shfl_xor_sync(0xffffffffu, rs1, 1);
            rs1 += __shfl_xor_sync(0xffffffffu, rs1, 2);
            l0 = l0 * a0 + rs0;
            l1 = l1 * a1 + rs1;

#pragma unroll
            for (int nt = 0; nt < 8; nt++) {
                o[nt][0] *= a0; o[nt][1] *= a0;
                o[nt][2] *= a1; o[nt][3] *= a1;
            }

            // ---- P frags (fp16) ----
            uint32_t pH[4][4];
#pragma unroll
            for (int kt = 0; kt < 4; kt++) {
#pragma unroll
                for (int part = 0; part < 4; part++) {
                    const int nt = 2 * kt + (part >> 1);
                    const int rb = (part & 1) * 2;
                    __half2 hh = __floats2half2_rn(S[nt][rb], S[nt][rb + 1]);
                    pH[kt][part] = *(uint32_t*)&hh;
                }
            }

            // ---- O += P @ V ----
#pragma unroll
            for (int kt = 0; kt < 4; kt++) {
#pragma unroll
                for (int q = 0; q < 4; q++) {
                    const uint32_t vro =
                        (uint32_t)(q * 16 + lrow) * 528 + c * 128 + kt * 32 + lcs * 16;
                    uint32_t tV[4];
                    ldsm_x4(tV, sbase + AT_VTH + vro);
                    uint32_t b0[2] = {tV[0], tV[2]}, b1[2] = {tV[1], tV[3]};
                    mma16816(o[2 * q],     pH[kt], b0);
                    mma16816(o[2 * q + 1], pH[kt], b1);
                }
            }
        }

        // ---- normalize + write rounded fp16 ----
        const float inv0 = 1.0f / l0, inv1 = 1.0f / l1;
        const int row0 = b * TLEN + tile * 16 + g;
#pragma unroll
        for (int nt = 0; nt < 8; nt++) {
            const int col = h * HDIM + nt * 8 + 2 * tq;
            const size_t i0 = (size_t)row0 * DMODEL + col;
            const size_t i1 = i0 + (size_t)8 * DMODEL;
            *(__half2*)(yh + i0) = __floats2half2_rn(o[nt][0] * inv0, o[nt][1] * inv0);
            *(__half2*)(yh + i1) = __floats2half2_rn(o[nt][2] * inv1, o[nt][3] * inv1);
        }
    }
}

// ---------------------------------------------------------------------------
extern "C" void kernel_launch(void* const* d_in, const int* in_sizes, int n_in,
                              void* d_out, int out_size) {
    const float* x     = (const float*)d_in[0];
    const float* W_qkv = (const float*)d_in[1];
    const float* b_qkv = (const float*)d_in[2];
    const float* W_out = (const float*)d_in[3];
    const float* b_out = (const float*)d_in[4];
    float* out = (float*)d_out;

    float* qkv;
    __half *ah, *bh, *b2h;
    cudaGetSymbolAddress((void**)&qkv, g_qkv);
    cudaGetSymbolAddress((void**)&ah, g_ah);
    cudaGetSymbolAddress((void**)&bh, g_bh);
    cudaGetSymbolAddress((void**)&b2h, g_b2h);

    cudaFuncSetAttribute(gemm_mma_kernel,
                         cudaFuncAttributeMaxDynamicSharedMemorySize, GEMM_SMEM);
    cudaFuncSetAttribute(attn_mma_kernel,
                         cudaFuncAttributeMaxDynamicSharedMemorySize, ATTN_SMEM);

    // 1) round x -> fp16
    {
        const int n4 = MROWS * GK / 4;
        round_f16_kernel<<<(n4 + 255) / 256, 256>>>(x, ah, n4);
    }
    // 2) round+transpose weights
    roundT_f16_kernel<<<(GK * 3 * DMODEL + 255) / 256, 256>>>(W_qkv, bh,
                                                              GK, 3 * DMODEL);
    roundT_f16_kernel<<<(GK * DMODEL + 255) / 256, 256>>>(W_out, b2h,
                                                          GK, DMODEL);

    // 3) QKV projection (single-term fp16 tensor cores)
    {
        dim3 g(3 * DMODEL / 128, MROWS / 128);
        gemm_mma_kernel<<<g, 256, GEMM_SMEM>>>(ah, bh, b_qkv, qkv, 3 * DMODEL);
    }

    // 4) flash attention, writes rounded fp16 y into ah
    attn_mma_kernel<<<BSZ * NHEADS, 256, ATTN_SMEM>>>(qkv, ah);

    // 5) output projection (single-term fp16 tensor cores)
    {
        dim3 g(DMODEL / 128, MROWS / 128);
        gemm_mma_kernel<<<g, 256, GEMM_SMEM>>>(ah, b2h, b_out, out, DMODEL);
    }
}

// round 12
// speedup vs baseline: 2.6463x; 1.1022x over previous
#include <cuda_runtime.h>
#include <cuda_fp16.h>
#include <math.h>
#include <cstdint>

#define BSZ 128
#define TLEN 256
#define DMODEL 512
#define NHEADS 8
#define HDIM 64
#define MROWS (BSZ * TLEN)          // 32768
#define GK 512                       // K dim of both GEMMs

// ---------------------------------------------------------------------------
// Scratch: __device__ globals (allocation-free rule).
// ---------------------------------------------------------------------------
__device__ __half g_qkv[(size_t)MROWS * 3 * DMODEL];  // fp16 qkv intermediate
__device__ __half g_ah[(size_t)MROWS * GK];           // A (x rounded, then attn out)
__device__ __half g_bh[(size_t)(3 * DMODEL) * GK];    // W_qkv^T fp16
__device__ __half g_b2h[(size_t)DMODEL * GK];         // W_out^T fp16

// ---------------------------------------------------------------------------
// PTX helpers — plain-sm_103-legal only (mma.sync / ldmatrix / cp.async).
// ---------------------------------------------------------------------------
__device__ __forceinline__ uint32_t smem_to_u32(const void* smem_ptr) {
    uint32_t addr;
    asm("{ .reg .u64 tmp; cvta.to.shared.u64 tmp, %1; cvt.u32.u64 %0, tmp; }"
        : "=r"(addr) : "l"(smem_ptr));
    return addr;
}

__device__ __forceinline__ void ldsm_x4(uint32_t* r, uint32_t addr) {
    asm volatile("ldmatrix.sync.aligned.m8n8.x4.shared.b16 {%0,%1,%2,%3}, [%4];"
                 : "=r"(r[0]), "=r"(r[1]), "=r"(r[2]), "=r"(r[3]) : "r"(addr));
}

__device__ __forceinline__ void mma16816(float* c, const uint32_t* a,
                                         const uint32_t* b) {
    asm volatile(
        "mma.sync.aligned.m16n8k16.row.col.f32.f16.f16.f32 "
        "{%0,%1,%2,%3}, {%4,%5,%6,%7}, {%8,%9}, {%0,%1,%2,%3};"
        : "+f"(c[0]), "+f"(c[1]), "+f"(c[2]), "+f"(c[3])
        : "r"(a[0]), "r"(a[1]), "r"(a[2]), "r"(a[3]), "r"(b[0]), "r"(b[1]));
}

__device__ __forceinline__ void cp_async16(uint32_t saddr, const void* gaddr) {
    asm volatile("cp.async.cg.shared.global [%0], [%1], 16;"
                 :: "r"(saddr), "l"(gaddr));
}
#define CP_COMMIT() asm volatile("cp.async.commit_group;" ::: "memory")
#define CP_WAIT(n)  asm volatile("cp.async.wait_group %0;" :: "n"(n) : "memory")

// ---------------------------------------------------------------------------
// Conversion kernels
// ---------------------------------------------------------------------------
__global__ void round_f16_kernel(const float* __restrict__ in,
                                 __half* __restrict__ hi, int n4) {
    int i = blockIdx.x * blockDim.x + threadIdx.x;
    if (i >= n4) return;
    float4 v = ((const float4*)in)[i];
    __half2* h2 = (__half2*)(hi + (size_t)i * 4);
    h2[0] = __floats2half2_rn(v.x, v.y);
    h2[1] = __floats2half2_rn(v.z, v.w);
}

// W[K,N] fp32 -> Wt[N,K] fp16 (transpose + round)
__global__ void roundT_f16_kernel(const float* __restrict__ W,
                                  __half* __restrict__ th, int K, int N) {
    int idx = blockIdx.x * blockDim.x + threadIdx.x;
    if (idx >= K * N) return;
    int k = idx / N, n = idx % N;
    th[(size_t)n * K + k] = __float2half_rn(W[idx]);
}

// ---------------------------------------------------------------------------
// fp16 single-term mma.sync GEMM: C = Ah @ Bh^T + bias.
// R12: 3-stage cp.async pipeline (loads get ~2 compute-stages of cover);
// templated epilogue (fp16 out for QKV proj, fp32 for final out).
// 128x128 tile, 8 warps (32x64), BK=32, 20KB/stage x3 = 60KB, 2 CTAs/SM.
// ---------------------------------------------------------------------------
#define ROWB 80
#define SM_TILE (128 * ROWB)           // 10240
#define SM_T_A 0
#define SM_T_B (SM_TILE)
#define SM_STAGE (2 * SM_TILE)         // 20480
#define GEMM_SMEM (3 * SM_STAGE)       // 61440

template <bool HALF_OUT>
__global__ __launch_bounds__(256, 2)
void gemm_mma_kernel(const __half* __restrict__ Ah,
                     const __half* __restrict__ Bh,
                     const float* __restrict__ bias,
                     void* __restrict__ Cv, int N) {
    extern __shared__ char smem[];
    const uint32_t sbase = smem_to_u32(smem);
    const int tid = threadIdx.x;
    const int wid = tid >> 5, lane = tid & 31;
    const int warpM = wid & 3, warpN = wid >> 2;
    const int m0 = blockIdx.y * 128, n0 = blockIdx.x * 128;

    const char* gA = (const char*)(Ah + (size_t)m0 * GK);
    const char* gB = (const char*)(Bh + (size_t)n0 * GK);

    float acc[2][8][4];
#pragma unroll
    for (int mt = 0; mt < 2; mt++)
#pragma unroll
        for (int nt = 0; nt < 8; nt++)
#pragma unroll
            for (int r = 0; r < 4; r++) acc[mt][nt][r] = 0.0f;

    const int lr2 = (tid >> 2);          // 0..63
    const int lc2 = (tid & 3);           // 0..3

    constexpr int NSTAGES = GK / 32;     // 16

    // prefetch stages 0, 1
#pragma unroll
    for (int ps = 0; ps < 2; ps++) {
        uint32_t sb = sbase + ps * SM_STAGE;
        const int kbyte = ps * 64;
#pragma unroll
        for (int p = 0; p < 2; p++) {
            int r = lr2 + p * 64;
            uint32_t so = r * ROWB + lc2 * 16;
            size_t go = (size_t)r * (GK * 2) + kbyte + lc2 * 16;
            cp_async16(sb + SM_T_A + so, gA + go);
            cp_async16(sb + SM_T_B + so, gB + go);
        }
        CP_COMMIT();
    }

    const int lrow = lane & 15;
    const int lcs = lane >> 4;

    int buf = 0;
    for (int s = 0; s < NSTAGES; s++) {
        if (s + 1 < NSTAGES) { CP_WAIT(1); } else { CP_WAIT(0); }
        __syncthreads();

        // issue stage s+2 into buffer (s+2)%3 (freed by the bottom sync of s-1)
        if (s + 2 < NSTAGES) {
            int nb = buf + 2; if (nb >= 3) nb -= 3;
            uint32_t sb = sbase + nb * SM_STAGE;
            const int kbyte = (s + 2) * 64;
#pragma unroll
            for (int p = 0; p < 2; p++) {
                int r = lr2 + p * 64;
                uint32_t so = r * ROWB + lc2 * 16;
                size_t go = (size_t)r * (GK * 2) + kbyte + lc2 * 16;
                cp_async16(sb + SM_T_A + so, gA + go);
                cp_async16(sb + SM_T_B + so, gB + go);
            }
            CP_COMMIT();
        }

        const uint32_t sb = sbase + buf * SM_STAGE;
#pragma unroll
        for (int kk = 0; kk < 2; kk++) {
            const uint32_t coff = (kk * 2 + lcs) * 16;
            uint32_t aH[2][4];
#pragma unroll
            for (int mt = 0; mt < 2; mt++) {
                uint32_t ro = (uint32_t)(warpM * 32 + mt * 16 + lrow) * ROWB + coff;
                ldsm_x4(aH[mt], sb + SM_T_A + ro);
            }
#pragma unroll
            for (int q = 0; q < 4; q++) {
                uint32_t ro = (uint32_t)(warpN * 64 + q * 16 + lrow) * ROWB + coff;
                uint32_t tB[4];
                ldsm_x4(tB, sb + SM_T_B + ro);
                uint32_t b0[2] = {tB[0], tB[2]}, b1[2] = {tB[1], tB[3]};
#pragma unroll
                for (int mt = 0; mt < 2; mt++) {
                    mma16816(acc[mt][2 * q],     aH[mt], b0);
                    mma16816(acc[mt][2 * q + 1], aH[mt], b1);
                }
            }
        }
        __syncthreads();
        buf++; if (buf == 3) buf = 0;
    }

    const int g = lane >> 2, tc4 = lane & 3;
#pragma unroll
    for (int mt = 0; mt < 2; mt++) {
        const int row = m0 + warpM * 32 + mt * 16 + g;
#pragma unroll
        for (int nt = 0; nt < 8; nt++) {
            const int col = n0 + warpN * 64 + nt * 8 + tc4 * 2;
            const float bv0 = bias[col], bv1 = bias[col + 1];
            if (HALF_OUT) {
                __half* C = (__half*)Cv;
                *(__half2*)(C + (size_t)row * N + col) =
                    __floats2half2_rn(acc[mt][nt][0] + bv0, acc[mt][nt][1] + bv1);
                *(__half2*)(C + (size_t)(row + 8) * N + col) =
                    __floats2half2_rn(acc[mt][nt][2] + bv0, acc[mt][nt][3] + bv1);
            } else {
                float* C = (float*)Cv;
                float2 v0, v1;
                v0.x = acc[mt][nt][0] + bv0; v0.y = acc[mt][nt][1] + bv1;
                v1.x = acc[mt][nt][2] + bv0; v1.y = acc[mt][nt][3] + bv1;
                *(float2*)(C + (size_t)row * N + col) = v0;
                *(float2*)(C + (size_t)(row + 8) * N + col) = v1;
            }
        }
    }
}

// ---------------------------------------------------------------------------
// Flash attention, single-term fp16, fp16 qkv input (pure byte-copy staging).
// One block per (b,h), 8 warps; warp handles m16 tiles {w, 15-w}. 2 CTAs/SM.
// ---------------------------------------------------------------------------
#define AT_QH 0
#define AT_KH 36864
#define AT_VTH 73728
#define ATTN_SMEM 107520
#define AT_VSTAGE 0          // fp16 V staging [256][272B]=69632B, inside Q+K region

__global__ __launch_bounds__(256, 2)
void attn_mma_kernel(const __half* __restrict__ qkv,
                     __half* __restrict__ yh) {
    extern __shared__ char smem[];
    const uint32_t sbase = smem_to_u32(smem);
    const int b = blockIdx.x >> 3;
    const int h = blockIdx.x & 7;
    const int tid = threadIdx.x;
    const int wid = tid >> 5, lane = tid & 31;
    const int g = lane >> 2, tq = lane & 3;
    const int lrow = lane & 15, lcs = lane >> 4;
    const float SCALE = 0.125f;

    const __half* base = qkv + (size_t)b * TLEN * (3 * DMODEL) + h * HDIM;

    // 1) stage V fp16 into [256][272B] (row = 64 halves = 8 x 16B chunks)
    for (int i = tid; i < 256 * 8; i += 256) {
        const int t = i >> 3, c = i & 7;
        uint4 v = *(const uint4*)(base + (size_t)t * (3 * DMODEL) + 2 * DMODEL + c * 8);
        *(uint4*)(smem + AT_VSTAGE + t * 272 + c * 16) = v;
    }
    __syncthreads();

    // 2) transpose into Vt [64][528B]
    {
        const int d = tid & 63;
        const int jb = (tid >> 6) * 64;
#pragma unroll 4
        for (int jp = 0; jp < 32; jp++) {
            const int j = jb + 2 * jp;
            __half h0 = *(const __half*)(smem + AT_VSTAGE + j * 272 + d * 2);
            __half h1 = *(const __half*)(smem + AT_VSTAGE + (j + 1) * 272 + d * 2);
            *(__half2*)(smem + AT_VTH + d * 528 + j * 2) = __halves2half2(h0, h1);
        }
    }
    __syncthreads();

    // 3) copy Q, K fp16 into [256][144B] each
    for (int i = tid; i < 256 * 8; i += 256) {
        const int t = i >> 3, c = i & 7;
        const size_t roff = (size_t)t * (3 * DMODEL);
        uint4 q = *(const uint4*)(base + roff + c * 8);
        uint4 k = *(const uint4*)(base + roff + DMODEL + c * 8);
        const int so = t * 144 + c * 16;
        *(uint4*)(smem + AT_QH + so) = q;
        *(uint4*)(smem + AT_KH + so) = k;
    }
    __syncthreads();

    // 4) compute: two m16 tiles per warp
#pragma unroll
    for (int half = 0; half < 2; half++) {
        const int tile = (half == 0) ? wid : 15 - wid;
        const int nch = tile / 4 + 1;

        float o[8][4];
#pragma unroll
        for (int nt = 0; nt < 8; nt++)
#pragma unroll
            for (int r = 0; r < 4; r++) o[nt][r] = 0.0f;
        float m0 = -1e30f, m1 = -1e30f, l0 = 0.0f, l1 = 0.0f;

        for (int c = 0; c < nch; c++) {
            float S[8][4];
#pragma unroll
            for (int nt = 0; nt < 8; nt++)
#pragma unroll
                for (int r = 0; r < 4; r++) S[nt][r] = 0.0f;

            // ---- S = Q @ K^T ----
#pragma unroll
            for (int kt = 0; kt < 4; kt++) {
                uint32_t aH[4];
                const uint32_t qro = (uint32_t)(tile * 16 + lrow) * 144 + kt * 32 + lcs * 16;
                ldsm_x4(aH, sbase + AT_QH + qro);
#pragma unroll
                for (int q = 0; q < 4; q++) {
                    const uint32_t kro =
                        (uint32_t)(c * 64 + q * 16 + lrow) * 144 + kt * 32 + lcs * 16;
                    uint32_t tK[4];
                    ldsm_x4(tK, sbase + AT_KH + kro);
                    uint32_t b0[2] = {tK[0], tK[2]}, b1[2] = {tK[1], tK[3]};
                    mma16816(S[2 * q],     aH, b0);
                    mma16816(S[2 * q + 1], aH, b1);
                }
            }

            // ---- scale + causal mask ----
            const int r0 = tile * 16 + g, r1 = r0 + 8;
            if (c == nch - 1) {
#pragma unroll
                for (int nt = 0; nt < 8; nt++) {
                    const int col = c * 64 + nt * 8 + 2 * tq;
                    S[nt][0] = (col     <= r0) ? S[nt][0] * SCALE : -1e30f;
                    S[nt][1] = (col + 1 <= r0) ? S[nt][1] * SCALE : -1e30f;
                    S[nt][2] = (col     <= r1) ? S[nt][2] * SCALE : -1e30f;
                    S[nt][3] = (col + 1 <= r1) ? S[nt][3] * SCALE : -1e30f;
                }
            } else {
#pragma unroll
                for (int nt = 0; nt < 8; nt++)
#pragma unroll
                    for (int r = 0; r < 4; r++) S[nt][r] *= SCALE;
            }

            // ---- online softmax ----
            float cm0 = -1e30f, cm1 = -1e30f;
#pragma unroll
            for (int nt = 0; nt < 8; nt++) {
                cm0 = fmaxf(cm0, fmaxf(S[nt][0], S[nt][1]));
                cm1 = fmaxf(cm1, fmaxf(S[nt][2], S[nt][3]));
            }
            cm0 = fmaxf(cm0, __shfl_xor_sync(0xffffffffu, cm0, 1));
            cm0 = fmaxf(cm0, __shfl_xor_sync(0xffffffffu, cm0, 2));
            cm1 = fmaxf(cm1, __shfl_xor_sync(0xffffffffu, cm1, 1));
            cm1 = fmaxf(cm1, __shfl_xor_sync(0xffffffffu, cm1, 2));
            const float mn0 = fmaxf(m0, cm0), mn1 = fmaxf(m1, cm1);
            const float a0 = __expf(m0 - mn0), a1 = __expf(m1 - mn1);
            m0 = mn0; m1 = mn1;

            float rs0 = 0.0f, rs1 = 0.0f;
#pragma unroll
            for (int nt = 0; nt < 8; nt++) {
                S[nt][0] = __expf(S[nt][0] - mn0);
                S[nt][1] = __expf(S[nt][1] - mn0);
                S[nt][2] = __expf(S[nt][2] - mn1);
                S[nt][3] = __expf(S[nt][3] - mn1);
                rs0 += S[nt][0] + S[nt][1];
                rs1 += S[nt][2] + S[nt][3];
            }
            rs0 += __shfl_xor_sync(0xffffffffu, rs0, 1);
            rs0 += __shfl_xor_sync(0xffffffffu, rs0, 2);
            rs1 += __shfl_xor_sync(0xffffffffu, rs1, 1);
            rs1 += __shfl_xor_sync(0xffffffffu, rs1, 2);
            l0 = l0 * a0 + rs0;
            l1 = l1 * a1 + rs1;

#pragma unroll
            for (int nt = 0; nt < 8; nt++) {
                o[nt][0] *= a0; o[nt][1] *= a0;
                o[nt][2] *= a1; o[nt][3] *= a1;
            }

            // ---- P frags (fp16) ----
            uint32_t pH[4][4];
#pragma unroll
            for (int kt = 0; kt < 4; kt++) {
#pragma unroll
                for (int part = 0; part < 4; part++) {
                    const int nt = 2 * kt + (part >> 1);
                    const int rb = (part & 1) * 2;
                    __half2 hh = __floats2half2_rn(S[nt][rb], S[nt][rb + 1]);
                    pH[kt][part] = *(uint32_t*)&hh;
                }
            }

            // ---- O += P @ V ----
#pragma unroll
            for (int kt = 0; kt < 4; kt++) {
#pragma unroll
                for (int q = 0; q < 4; q++) {
                    const uint32_t vro =
                        (uint32_t)(q * 16 + lrow) * 528 + c * 128 + kt * 32 + lcs * 16;
                    uint32_t tV[4];
                    ldsm_x4(tV, sbase + AT_VTH + vro);
                    uint32_t b0[2] = {tV[0], tV[2]}, b1[2] = {tV[1], tV[3]};
                    mma16816(o[2 * q],     pH[kt], b0);
                    mma16816(o[2 * q + 1], pH[kt], b1);
                }
            }
        }

        // ---- normalize + write rounded fp16 ----
        const float inv0 = 1.0f / l0, inv1 = 1.0f / l1;
        const int row0 = b * TLEN + tile * 16 + g;
#pragma unroll
        for (int nt = 0; nt < 8; nt++) {
            const int col = h * HDIM + nt * 8 + 2 * tq;
            const size_t i0 = (size_t)row0 * DMODEL + col;
            const size_t i1 = i0 + (size_t)8 * DMODEL;
            *(__half2*)(yh + i0) = __floats2half2_rn(o[nt][0] * inv0, o[nt][1] * inv0);
            *(__half2*)(yh + i1) = __floats2half2_rn(o[nt][2] * inv1, o[nt][3] * inv1);
        }
    }
}

// ---------------------------------------------------------------------------
extern "C" void kernel_launch(void* const* d_in, const int* in_sizes, int n_in,
                              void* d_out, int out_size) {
    const float* x     = (const float*)d_in[0];
    const float* W_qkv = (const float*)d_in[1];
    const float* b_qkv = (const float*)d_in[2];
    const float* W_out = (const float*)d_in[3];
    const float* b_out = (const float*)d_in[4];
    float* out = (float*)d_out;

    __half *qkv, *ah, *bh, *b2h;
    cudaGetSymbolAddress((void**)&qkv, g_qkv);
    cudaGetSymbolAddress((void**)&ah, g_ah);
    cudaGetSymbolAddress((void**)&bh, g_bh);
    cudaGetSymbolAddress((void**)&b2h, g_b2h);

    cudaFuncSetAttribute(gemm_mma_kernel<true>,
                         cudaFuncAttributeMaxDynamicSharedMemorySize, GEMM_SMEM);
    cudaFuncSetAttribute(gemm_mma_kernel<false>,
                         cudaFuncAttributeMaxDynamicSharedMemorySize, GEMM_SMEM);
    cudaFuncSetAttribute(attn_mma_kernel,
                         cudaFuncAttributeMaxDynamicSharedMemorySize, ATTN_SMEM);

    // 1) round x -> fp16
    {
        const int n4 = MROWS * GK / 4;
        round_f16_kernel<<<(n4 + 255) / 256, 256>>>(x, ah, n4);
    }
    // 2) round+transpose weights
    roundT_f16_kernel<<<(GK * 3 * DMODEL + 255) / 256, 256>>>(W_qkv, bh,
                                                              GK, 3 * DMODEL);
    roundT_f16_kernel<<<(GK * DMODEL + 255) / 256, 256>>>(W_out, b2h,
                                                          GK, DMODEL);

    // 3) QKV projection -> fp16 qkv
    {
        dim3 g(3 * DMODEL / 128, MROWS / 128);
        gemm_mma_kernel<true><<<g, 256, GEMM_SMEM>>>(ah, bh, b_qkv, qkv,
                                                     3 * DMODEL);
    }

    // 4) flash attention (fp16 in/out), writes y into ah
    attn_mma_kernel<<<BSZ * NHEADS, 256, ATTN_SMEM>>>(qkv, ah);

    // 5) output projection -> fp32 out
    {
        dim3 g(DMODEL / 128, MROWS / 128);
        gemm_mma_kernel<false><<<g, 256, GEMM_SMEM>>>(ah, b2h, b_out, out,
                                                      DMODEL);
    }
}

// round 14
// speedup vs baseline: 2.6541x; 1.0029x over previous
#include <cuda_runtime.h>
#include <cuda_fp16.h>
#include <math.h>
#include <cstdint>

#define BSZ 128
#define TLEN 256
#define DMODEL 512
#define NHEADS 8
#define HDIM 64
#define MROWS (BSZ * TLEN)          // 32768
#define GK 512                       // K dim of both GEMMs

// ---------------------------------------------------------------------------
// Scratch: __device__ globals (allocation-free rule).
// ---------------------------------------------------------------------------
__device__ __half g_qkv[(size_t)MROWS * 3 * DMODEL];  // fp16 qkv intermediate
__device__ __half g_ah[(size_t)MROWS * GK];           // A (x rounded, then attn out)
__device__ __half g_bh[(size_t)(3 * DMODEL) * GK];    // W_qkv^T fp16
__device__ __half g_b2h[(size_t)DMODEL * GK];         // W_out^T fp16

// ---------------------------------------------------------------------------
// PTX helpers — plain-sm_103-legal only (mma.sync / ldmatrix / cp.async).
// ---------------------------------------------------------------------------
__device__ __forceinline__ uint32_t smem_to_u32(const void* smem_ptr) {
    uint32_t addr;
    asm("{ .reg .u64 tmp; cvta.to.shared.u64 tmp, %1; cvt.u32.u64 %0, tmp; }"
        : "=r"(addr) : "l"(smem_ptr));
    return addr;
}

__device__ __forceinline__ void ldsm_x4(uint32_t* r, uint32_t addr) {
    asm volatile("ldmatrix.sync.aligned.m8n8.x4.shared.b16 {%0,%1,%2,%3}, [%4];"
                 : "=r"(r[0]), "=r"(r[1]), "=r"(r[2]), "=r"(r[3]) : "r"(addr));
}

__device__ __forceinline__ void mma16816(float* c, const uint32_t* a,
                                         const uint32_t* b) {
    asm volatile(
        "mma.sync.aligned.m16n8k16.row.col.f32.f16.f16.f32 "
        "{%0,%1,%2,%3}, {%4,%5,%6,%7}, {%8,%9}, {%0,%1,%2,%3};"
        : "+f"(c[0]), "+f"(c[1]), "+f"(c[2]), "+f"(c[3])
        : "r"(a[0]), "r"(a[1]), "r"(a[2]), "r"(a[3]), "r"(b[0]), "r"(b[1]));
}

__device__ __forceinline__ void cp_async16(uint32_t saddr, const void* gaddr) {
    asm volatile("cp.async.cg.shared.global [%0], [%1], 16;"
                 :: "r"(saddr), "l"(gaddr));
}
#define CP_COMMIT() asm volatile("cp.async.commit_group;" ::: "memory")
#define CP_WAIT(n)  asm volatile("cp.async.wait_group %0;" :: "n"(n) : "memory")

// ---------------------------------------------------------------------------
// Conversion kernels
// ---------------------------------------------------------------------------
__global__ void round_f16_kernel(const float* __restrict__ in,
                                 __half* __restrict__ hi, int n4) {
    int i = blockIdx.x * blockDim.x + threadIdx.x;
    if (i >= n4) return;
    float4 v = ((const float4*)in)[i];
    __half2* h2 = (__half2*)(hi + (size_t)i * 4);
    h2[0] = __floats2half2_rn(v.x, v.y);
    h2[1] = __floats2half2_rn(v.z, v.w);
}

// W[K,N] fp32 -> Wt[N,K] fp16 (transpose + round)
__global__ void roundT_f16_kernel(const float* __restrict__ W,
                                  __half* __restrict__ th, int K, int N) {
    int idx = blockIdx.x * blockDim.x + threadIdx.x;
    if (idx >= K * N) return;
    int k = idx / N, n = idx % N;
    th[(size_t)n * K + k] = __float2half_rn(W[idx]);
}

// ---------------------------------------------------------------------------
// fp16 single-term mma.sync GEMM: C = Ah @ Bh^T + bias.
// R14: single-barrier pipeline, CORRECT order: wait(1) -> sync -> issue s+2
// -> compute s. Wait-before-barrier makes everyone's stage-s copies visible;
// the barrier also proves all warps finished compute(s-1), making buffer
// (s-1)%3 safe to overwrite. (R13's sync->issue->wait raced: wait_group is
// per-thread, so peers' copies weren't guaranteed before ldmatrix.)
// ---------------------------------------------------------------------------
#define ROWB 80
#define SM_TILE (128 * ROWB)           // 10240
#define SM_T_A 0
#define SM_T_B (SM_TILE)
#define SM_STAGE (2 * SM_TILE)         // 20480
#define GEMM_SMEM (3 * SM_STAGE)       // 61440

template <bool HALF_OUT>
__global__ __launch_bounds__(256, 2)
void gemm_mma_kernel(const __half* __restrict__ Ah,
                     const __half* __restrict__ Bh,
                     const float* __restrict__ bias,
                     void* __restrict__ Cv, int N) {
    extern __shared__ char smem[];
    const uint32_t sbase = smem_to_u32(smem);
    const int tid = threadIdx.x;
    const int wid = tid >> 5, lane = tid & 31;
    const int warpM = wid & 3, warpN = wid >> 2;
    const int m0 = blockIdx.y * 128, n0 = blockIdx.x * 128;

    const char* gA = (const char*)(Ah + (size_t)m0 * GK);
    const char* gB = (const char*)(Bh + (size_t)n0 * GK);

    float acc[2][8][4];
#pragma unroll
    for (int mt = 0; mt < 2; mt++)
#pragma unroll
        for (int nt = 0; nt < 8; nt++)
#pragma unroll
            for (int r = 0; r < 4; r++) acc[mt][nt][r] = 0.0f;

    const int lr2 = (tid >> 2);          // 0..63
    const int lc2 = (tid & 3);           // 0..3

    constexpr int NSTAGES = GK / 32;     // 16

    // prefetch stages 0, 1
#pragma unroll
    for (int ps = 0; ps < 2; ps++) {
        uint32_t sb = sbase + ps * SM_STAGE;
        const int kbyte = ps * 64;
#pragma unroll
        for (int p = 0; p < 2; p++) {
            int r = lr2 + p * 64;
            uint32_t so = r * ROWB + lc2 * 16;
            size_t go = (size_t)r * (GK * 2) + kbyte + lc2 * 16;
            cp_async16(sb + SM_T_A + so, gA + go);
            cp_async16(sb + SM_T_B + so, gB + go);
        }
        CP_COMMIT();
    }

    const int lrow = lane & 15;
    const int lcs = lane >> 4;

    int buf = 0;
    for (int s = 0; s < NSTAGES; s++) {
        // 1) my copies of stage s complete
        if (s + 1 < NSTAGES) { CP_WAIT(1); } else { CP_WAIT(0); }
        // 2) everyone's copies of stage s complete; all warps past compute(s-1)
        __syncthreads();

        // 3) issue stage s+2 into buffer (s+2)%3 == (s-1)%3 (reads done)
        if (s + 2 < NSTAGES) {
            int nb = buf + 2; if (nb >= 3) nb -= 3;
            uint32_t sb = sbase + nb * SM_STAGE;
            const int kbyte = (s + 2) * 64;
#pragma unroll
            for (int p = 0; p < 2; p++) {
                int r = lr2 + p * 64;
                uint32_t so = r * ROWB + lc2 * 16;
                size_t go = (size_t)r * (GK * 2) + kbyte + lc2 * 16;
                cp_async16(sb + SM_T_A + so, gA + go);
                cp_async16(sb + SM_T_B + so, gB + go);
            }
            CP_COMMIT();
        }

        // 4) compute stage s
        const uint32_t sb = sbase + buf * SM_STAGE;
#pragma unroll
        for (int kk = 0; kk < 2; kk++) {
            const uint32_t coff = (kk * 2 + lcs) * 16;
            uint32_t aH[2][4];
#pragma unroll
            for (int mt = 0; mt < 2; mt++) {
                uint32_t ro = (uint32_t)(warpM * 32 + mt * 16 + lrow) * ROWB + coff;
                ldsm_x4(aH[mt], sb + SM_T_A + ro);
            }
#pragma unroll
            for (int q = 0; q < 4; q++) {
                uint32_t ro = (uint32_t)(warpN * 64 + q * 16 + lrow) * ROWB + coff;
                uint32_t tB[4];
                ldsm_x4(tB, sb + SM_T_B + ro);
                uint32_t b0[2] = {tB[0], tB[2]}, b1[2] = {tB[1], tB[3]};
#pragma unroll
                for (int mt = 0; mt < 2; mt++) {
                    mma16816(acc[mt][2 * q],     aH[mt], b0);
                    mma16816(acc[mt][2 * q + 1], aH[mt], b1);
                }
            }
        }
        buf++; if (buf == 3) buf = 0;
    }

    const int g = lane >> 2, tc4 = lane & 3;
#pragma unroll
    for (int mt = 0; mt < 2; mt++) {
        const int row = m0 + warpM * 32 + mt * 16 + g;
#pragma unroll
        for (int nt = 0; nt < 8; nt++) {
            const int col = n0 + warpN * 64 + nt * 8 + tc4 * 2;
            const float bv0 = bias[col], bv1 = bias[col + 1];
            if (HALF_OUT) {
                __half* C = (__half*)Cv;
                *(__half2*)(C + (size_t)row * N + col) =
                    __floats2half2_rn(acc[mt][nt][0] + bv0, acc[mt][nt][1] + bv1);
                *(__half2*)(C + (size_t)(row + 8) * N + col) =
                    __floats2half2_rn(acc[mt][nt][2] + bv0, acc[mt][nt][3] + bv1);
            } else {
                float* C = (float*)Cv;
                float2 v0, v1;
                v0.x = acc[mt][nt][0] + bv0; v0.y = acc[mt][nt][1] + bv1;
                v1.x = acc[mt][nt][2] + bv0; v1.y = acc[mt][nt][3] + bv1;
                *(float2*)(C + (size_t)row * N + col) = v0;
                *(float2*)(C + (size_t)(row + 8) * N + col) = v1;
            }
        }
    }
}

// ---------------------------------------------------------------------------
// Flash attention, single-term fp16, fp16 qkv input (unchanged from R12).
// ---------------------------------------------------------------------------
#define AT_QH 0
#define AT_KH 36864
#define AT_VTH 73728
#define ATTN_SMEM 107520
#define AT_VSTAGE 0          // fp16 V staging [256][272B], inside Q+K region

__global__ __launch_bounds__(256, 2)
void attn_mma_kernel(const __half* __restrict__ qkv,
                     __half* __restrict__ yh) {
    extern __shared__ char smem[];
    const uint32_t sbase = smem_to_u32(smem);
    const int b = blockIdx.x >> 3;
    const int h = blockIdx.x & 7;
    const int tid = threadIdx.x;
    const int wid = tid >> 5, lane = tid & 31;
    const int g = lane >> 2, tq = lane & 3;
    const int lrow = lane & 15, lcs = lane >> 4;
    const float SCALE = 0.125f;

    const __half* base = qkv + (size_t)b * TLEN * (3 * DMODEL) + h * HDIM;

    for (int i = tid; i < 256 * 8; i += 256) {
        const int t = i >> 3, c = i & 7;
        uint4 v = *(const uint4*)(base + (size_t)t * (3 * DMODEL) + 2 * DMODEL + c * 8);
        *(uint4*)(smem + AT_VSTAGE + t * 272 + c * 16) = v;
    }
    __syncthreads();

    {
        const int d = tid & 63;
        const int jb = (tid >> 6) * 64;
#pragma unroll 4
        for (int jp = 0; jp < 32; jp++) {
            const int j = jb + 2 * jp;
            __half h0 = *(const __half*)(smem + AT_VSTAGE + j * 272 + d * 2);
            __half h1 = *(const __half*)(smem + AT_VSTAGE + (j + 1) * 272 + d * 2);
            *(__half2*)(smem + AT_VTH + d * 528 + j * 2) = __halves2half2(h0, h1);
        }
    }
    __syncthreads();

    for (int i = tid; i < 256 * 8; i += 256) {
        const int t = i >> 3, c = i & 7;
        const size_t roff = (size_t)t * (3 * DMODEL);
        uint4 q = *(const uint4*)(base + roff + c * 8);
        uint4 k = *(const uint4*)(base + roff + DMODEL + c * 8);
        const int so = t * 144 + c * 16;
        *(uint4*)(smem + AT_QH + so) = q;
        *(uint4*)(smem + AT_KH + so) = k;
    }
    __syncthreads();

#pragma unroll
    for (int half = 0; half < 2; half++) {
        const int tile = (half == 0) ? wid : 15 - wid;
        const int nch = tile / 4 + 1;

        float o[8][4];
#pragma unroll
        for (int nt = 0; nt < 8; nt++)
#pragma unroll
            for (int r = 0; r < 4; r++) o[nt][r] = 0.0f;
        float m0 = -1e30f, m1 = -1e30f, l0 = 0.0f, l1 = 0.0f;

        for (int c = 0; c < nch; c++) {
            float S[8][4];
#pragma unroll
            for (int nt = 0; nt < 8; nt++)
#pragma unroll
                for (int r = 0; r < 4; r++) S[nt][r] = 0.0f;

#pragma unroll
            for (int kt = 0; kt < 4; kt++) {
                uint32_t aH[4];
                const uint32_t qro = (uint32_t)(tile * 16 + lrow) * 144 + kt * 32 + lcs * 16;
                ldsm_x4(aH, sbase + AT_QH + qro);
#pragma unroll
                for (int q = 0; q < 4; q++) {
                    const uint32_t kro =
                        (uint32_t)(c * 64 + q * 16 + lrow) * 144 + kt * 32 + lcs * 16;
                    uint32_t tK[4];
                    ldsm_x4(tK, sbase + AT_KH + kro);
                    uint32_t b0[2] = {tK[0], tK[2]}, b1[2] = {tK[1], tK[3]};
                    mma16816(S[2 * q],     aH, b0);
                    mma16816(S[2 * q + 1], aH, b1);
                }
            }

            const int r0 = tile * 16 + g, r1 = r0 + 8;
            if (c == nch - 1) {
#pragma unroll
                for (int nt = 0; nt < 8; nt++) {
                    const int col = c * 64 + nt * 8 + 2 * tq;
                    S[nt][0] = (col     <= r0) ? S[nt][0] * SCALE : -1e30f;
                    S[nt][1] = (col + 1 <= r0) ? S[nt][1] * SCALE : -1e30f;
                    S[nt][2] = (col     <= r1) ? S[nt][2] * SCALE : -1e30f;
                    S[nt][3] = (col + 1 <= r1) ? S[nt][3] * SCALE : -1e30f;
                }
            } else {
#pragma unroll
                for (int nt = 0; nt < 8; nt++)
#pragma unroll
                    for (int r = 0; r < 4; r++) S[nt][r] *= SCALE;
            }

            float cm0 = -1e30f, cm1 = -1e30f;
#pragma unroll
            for (int nt = 0; nt < 8; nt++) {
                cm0 = fmaxf(cm0, fmaxf(S[nt][0], S[nt][1]));
                cm1 = fmaxf(cm1, fmaxf(S[nt][2], S[nt][3]));
            }
            cm0 = fmaxf(cm0, __shfl_xor_sync(0xffffffffu, cm0, 1));
            cm0 = fmaxf(cm0, __shfl_xor_sync(0xffffffffu, cm0, 2));
            cm1 = fmaxf(cm1, __shfl_xor_sync(0xffffffffu, cm1, 1));
            cm1 = fmaxf(cm1, __shfl_xor_sync(0xffffffffu, cm1, 2));
            const float mn0 = fmaxf(m0, cm0), mn1 = fmaxf(m1, cm1);
            const float a0 = __expf(m0 - mn0), a1 = __expf(m1 - mn1);
            m0 = mn0; m1 = mn1;

            float rs0 = 0.0f, rs1 = 0.0f;
#pragma unroll
            for (int nt = 0; nt < 8; nt++) {
                S[nt][0] = __expf(S[nt][0] - mn0);
                S[nt][1] = __expf(S[nt][1] - mn0);
                S[nt][2] = __expf(S[nt][2] - mn1);
                S[nt][3] = __expf(S[nt][3] - mn1);
                rs0 += S[nt][0] + S[nt][1];
                rs1 += S[nt][2] + S[nt][3];
            }
            rs0 += __shfl_xor_sync(0xffffffffu, rs0, 1);
            rs0 += __shfl_xor_sync(0xffffffffu, rs0, 2);
            rs1 += __shfl_xor_sync(0xffffffffu, rs1, 1);
            rs1 += __shfl_xor_sync(0xffffffffu, rs1, 2);
            l0 = l0 * a0 + rs0;
            l1 = l1 * a1 + rs1;

#pragma unroll
            for (int nt = 0; nt < 8; nt++) {
                o[nt][0] *= a0; o[nt][1] *= a0;
                o[nt][2] *= a1; o[nt][3] *= a1;
            }

            uint32_t pH[4][4];
#pragma unroll
            for (int kt = 0; kt < 4; kt++) {
#pragma unroll
                for (int part = 0; part < 4; part++) {
                    const int nt = 2 * kt + (part >> 1);
                    const int rb = (part & 1) * 2;
                    __half2 hh = __floats2half2_rn(S[nt][rb], S[nt][rb + 1]);
                    pH[kt][part] = *(uint32_t*)&hh;
                }
            }

#pragma unroll
            for (int kt = 0; kt < 4; kt++) {
#pragma unroll
                for (int q = 0; q < 4; q++) {
                    const uint32_t vro =
                        (uint32_t)(q * 16 + lrow) * 528 + c * 128 + kt * 32 + lcs * 16;
                    uint32_t tV[4];
                    ldsm_x4(tV, sbase + AT_VTH + vro);
                    uint32_t b0[2] = {tV[0], tV[2]}, b1[2] = {tV[1], tV[3]};
                    mma16816(o[2 * q],     pH[kt], b0);
                    mma16816(o[2 * q + 1], pH[kt], b1);
                }
            }
        }

        const float inv0 = 1.0f / l0, inv1 = 1.0f / l1;
        const int row0 = b * TLEN + tile * 16 + g;
#pragma unroll
        for (int nt = 0; nt < 8; nt++) {
            const int col = h * HDIM + nt * 8 + 2 * tq;
            const size_t i0 = (size_t)row0 * DMODEL + col;
            const size_t i1 = i0 + (size_t)8 * DMODEL;
            *(__half2*)(yh + i0) = __floats2half2_rn(o[nt][0] * inv0, o[nt][1] * inv0);
            *(__half2*)(yh + i1) = __floats2half2_rn(o[nt][2] * inv1, o[nt][3] * inv1);
        }
    }
}

// ---------------------------------------------------------------------------
extern "C" void kernel_launch(void* const* d_in, const int* in_sizes, int n_in,
                              void* d_out, int out_size) {
    const float* x     = (const float*)d_in[0];
    const float* W_qkv = (const float*)d_in[1];
    const float* b_qkv = (const float*)d_in[2];
    const float* W_out = (const float*)d_in[3];
    const float* b_out = (const float*)d_in[4];
    float* out = (float*)d_out;

    __half *qkv, *ah, *bh, *b2h;
    cudaGetSymbolAddress((void**)&qkv, g_qkv);
    cudaGetSymbolAddress((void**)&ah, g_ah);
    cudaGetSymbolAddress((void**)&bh, g_bh);
    cudaGetSymbolAddress((void**)&b2h, g_b2h);

    cudaFuncSetAttribute(gemm_mma_kernel<true>,
                         cudaFuncAttributeMaxDynamicSharedMemorySize, GEMM_SMEM);
    cudaFuncSetAttribute(gemm_mma_kernel<false>,
                         cudaFuncAttributeMaxDynamicSharedMemorySize, GEMM_SMEM);
    cudaFuncSetAttribute(attn_mma_kernel,
                         cudaFuncAttributeMaxDynamicSharedMemorySize, ATTN_SMEM);

    // 1) round x -> fp16
    {
        const int n4 = MROWS * GK / 4;
        round_f16_kernel<<<(n4 + 255) / 256, 256>>>(x, ah, n4);
    }
    // 2) round+transpose weights
    roundT_f16_kernel<<<(GK * 3 * DMODEL + 255) / 256, 256>>>(W_qkv, bh,
                                                              GK, 3 * DMODEL);
    roundT_f16_kernel<<<(GK * DMODEL + 255) / 256, 256>>>(W_out, b2h,
                                                          GK, DMODEL);

    // 3) QKV projection -> fp16 qkv
    {
        dim3 g(3 * DMODEL / 128, MROWS / 128);
        gemm_mma_kernel<true><<<g, 256, GEMM_SMEM>>>(ah, bh, b_qkv, qkv,
                                                     3 * DMODEL);
    }

    // 4) flash attention (fp16 in/out), writes y into ah
    attn_mma_kernel<<<BSZ * NHEADS, 256, ATTN_SMEM>>>(qkv, ah);

    // 5) output projection -> fp32 out
    {
        dim3 g(DMODEL / 128, MROWS / 128);
        gemm_mma_kernel<false><<<g, 256, GEMM_SMEM>>>(ah, b2h, b_out, out,
                                                      DMODEL);
    }
}

// round 15
// speedup vs baseline: 2.8406x; 1.0703x over previous
#include <cuda_runtime.h>
#include <cuda_fp16.h>
#include <math.h>
#include <cstdint>

#define BSZ 128
#define TLEN 256
#define DMODEL 512
#define NHEADS 8
#define HDIM 64
#define MROWS (BSZ * TLEN)          // 32768
#define GK 512                       // K dim of both GEMMs

// ---------------------------------------------------------------------------
// Scratch: __device__ globals (allocation-free rule).
// ---------------------------------------------------------------------------
__device__ __half g_qkv[(size_t)MROWS * 3 * DMODEL];  // fp16 qkv intermediate
__device__ __half g_ah[(size_t)MROWS * GK];           // A (x rounded, then attn out)
__device__ __half g_bh[(size_t)(3 * DMODEL) * GK];    // W_qkv^T fp16
__device__ __half g_b2h[(size_t)DMODEL * GK];         // W_out^T fp16

// ---------------------------------------------------------------------------
// PTX helpers — plain-sm_103-legal only (mma.sync / ldmatrix / cp.async).
// ---------------------------------------------------------------------------
__device__ __forceinline__ uint32_t smem_to_u32(const void* smem_ptr) {
    uint32_t addr;
    asm("{ .reg .u64 tmp; cvta.to.shared.u64 tmp, %1; cvt.u32.u64 %0, tmp; }"
        : "=r"(addr) : "l"(smem_ptr));
    return addr;
}

__device__ __forceinline__ void ldsm_x4(uint32_t* r, uint32_t addr) {
    asm volatile("ldmatrix.sync.aligned.m8n8.x4.shared.b16 {%0,%1,%2,%3}, [%4];"
                 : "=r"(r[0]), "=r"(r[1]), "=r"(r[2]), "=r"(r[3]) : "r"(addr));
}

__device__ __forceinline__ void ldsm_x4_t(uint32_t* r, uint32_t addr) {
    asm volatile("ldmatrix.sync.aligned.m8n8.x4.trans.shared.b16 {%0,%1,%2,%3}, [%4];"
                 : "=r"(r[0]), "=r"(r[1]), "=r"(r[2]), "=r"(r[3]) : "r"(addr));
}

__device__ __forceinline__ void mma16816(float* c, const uint32_t* a,
                                         const uint32_t* b) {
    asm volatile(
        "mma.sync.aligned.m16n8k16.row.col.f32.f16.f16.f32 "
        "{%0,%1,%2,%3}, {%4,%5,%6,%7}, {%8,%9}, {%0,%1,%2,%3};"
        : "+f"(c[0]), "+f"(c[1]), "+f"(c[2]), "+f"(c[3])
        : "r"(a[0]), "r"(a[1]), "r"(a[2]), "r"(a[3]), "r"(b[0]), "r"(b[1]));
}

__device__ __forceinline__ void cp_async16(uint32_t saddr, const void* gaddr) {
    asm volatile("cp.async.cg.shared.global [%0], [%1], 16;"
                 :: "r"(saddr), "l"(gaddr));
}
#define CP_COMMIT() asm volatile("cp.async.commit_group;" ::: "memory")
#define CP_WAIT(n)  asm volatile("cp.async.wait_group %0;" :: "n"(n) : "memory")

// ---------------------------------------------------------------------------
// Fused conversion kernel: one launch for x-round + both weight transposes.
// ---------------------------------------------------------------------------
#define CONV_XB (MROWS * GK / 4 / 256)                 // 16384 blocks
#define CONV_WQ (GK * 3 * DMODEL / 256)                // 3072 blocks
#define CONV_WO (GK * DMODEL / 256)                    // 1024 blocks

__global__ void convert_all_kernel(const float* __restrict__ x,
                                   const float* __restrict__ Wq,
                                   const float* __restrict__ Wo,
                                   __half* __restrict__ ah,
                                   __half* __restrict__ bh,
                                   __half* __restrict__ b2h) {
    const int bid = blockIdx.x;
    if (bid < CONV_XB) {
        int i = bid * 256 + threadIdx.x;
        float4 v = ((const float4*)x)[i];
        __half2* h2 = (__half2*)(ah + (size_t)i * 4);
        h2[0] = __floats2half2_rn(v.x, v.y);
        h2[1] = __floats2half2_rn(v.z, v.w);
    } else if (bid < CONV_XB + CONV_WQ) {
        int idx = (bid - CONV_XB) * 256 + threadIdx.x;
        int k = idx / (3 * DMODEL), n = idx % (3 * DMODEL);
        bh[(size_t)n * GK + k] = __float2half_rn(Wq[idx]);
    } else {
        int idx = (bid - CONV_XB - CONV_WQ) * 256 + threadIdx.x;
        int k = idx / DMODEL, n = idx % DMODEL;
        b2h[(size_t)n * GK + k] = __float2half_rn(Wo[idx]);
    }
}

// ---------------------------------------------------------------------------
// fp16 single-term mma.sync GEMM (R14, unchanged — near the HMMA-f32acc
// issue floor). Single-barrier 3-stage pipeline: wait(1)->sync->issue->compute.
// ---------------------------------------------------------------------------
#define ROWB 80
#define SM_TILE (128 * ROWB)           // 10240
#define SM_T_A 0
#define SM_T_B (SM_TILE)
#define SM_STAGE (2 * SM_TILE)         // 20480
#define GEMM_SMEM (3 * SM_STAGE)       // 61440

template <bool HALF_OUT>
__global__ __launch_bounds__(256, 2)
void gemm_mma_kernel(const __half* __restrict__ Ah,
                     const __half* __restrict__ Bh,
                     const float* __restrict__ bias,
                     void* __restrict__ Cv, int N) {
    extern __shared__ char smem[];
    const uint32_t sbase = smem_to_u32(smem);
    const int tid = threadIdx.x;
    const int wid = tid >> 5, lane = tid & 31;
    const int warpM = wid & 3, warpN = wid >> 2;
    const int m0 = blockIdx.y * 128, n0 = blockIdx.x * 128;

    const char* gA = (const char*)(Ah + (size_t)m0 * GK);
    const char* gB = (const char*)(Bh + (size_t)n0 * GK);

    float acc[2][8][4];
#pragma unroll
    for (int mt = 0; mt < 2; mt++)
#pragma unroll
        for (int nt = 0; nt < 8; nt++)
#pragma unroll
            for (int r = 0; r < 4; r++) acc[mt][nt][r] = 0.0f;

    const int lr2 = (tid >> 2);
    const int lc2 = (tid & 3);

    constexpr int NSTAGES = GK / 32;     // 16

#pragma unroll
    for (int ps = 0; ps < 2; ps++) {
        uint32_t sb = sbase + ps * SM_STAGE;
        const int kbyte = ps * 64;
#pragma unroll
        for (int p = 0; p < 2; p++) {
            int r = lr2 + p * 64;
            uint32_t so = r * ROWB + lc2 * 16;
            size_t go = (size_t)r * (GK * 2) + kbyte + lc2 * 16;
            cp_async16(sb + SM_T_A + so, gA + go);
            cp_async16(sb + SM_T_B + so, gB + go);
        }
        CP_COMMIT();
    }

    const int lrow = lane & 15;
    const int lcs = lane >> 4;

    int buf = 0;
    for (int s = 0; s < NSTAGES; s++) {
        if (s + 1 < NSTAGES) { CP_WAIT(1); } else { CP_WAIT(0); }
        __syncthreads();

        if (s + 2 < NSTAGES) {
            int nb = buf + 2; if (nb >= 3) nb -= 3;
            uint32_t sb = sbase + nb * SM_STAGE;
            const int kbyte = (s + 2) * 64;
#pragma unroll
            for (int p = 0; p < 2; p++) {
                int r = lr2 + p * 64;
                uint32_t so = r * ROWB + lc2 * 16;
                size_t go = (size_t)r * (GK * 2) + kbyte + lc2 * 16;
                cp_async16(sb + SM_T_A + so, gA + go);
                cp_async16(sb + SM_T_B + so, gB + go);
            }
            CP_COMMIT();
        }

        const uint32_t sb = sbase + buf * SM_STAGE;
#pragma unroll
        for (int kk = 0; kk < 2; kk++) {
            const uint32_t coff = (kk * 2 + lcs) * 16;
            uint32_t aH[2][4];
#pragma unroll
            for (int mt = 0; mt < 2; mt++) {
                uint32_t ro = (uint32_t)(warpM * 32 + mt * 16 + lrow) * ROWB + coff;
                ldsm_x4(aH[mt], sb + SM_T_A + ro);
            }
#pragma unroll
            for (int q = 0; q < 4; q++) {
                uint32_t ro = (uint32_t)(warpN * 64 + q * 16 + lrow) * ROWB + coff;
                uint32_t tB[4];
                ldsm_x4(tB, sb + SM_T_B + ro);
                uint32_t b0[2] = {tB[0], tB[2]}, b1[2] = {tB[1], tB[3]};
#pragma unroll
                for (int mt = 0; mt < 2; mt++) {
                    mma16816(acc[mt][2 * q],     aH[mt], b0);
                    mma16816(acc[mt][2 * q + 1], aH[mt], b1);
                }
            }
        }
        buf++; if (buf == 3) buf = 0;
    }

    const int g = lane >> 2, tc4 = lane & 3;
#pragma unroll
    for (int mt = 0; mt < 2; mt++) {
        const int row = m0 + warpM * 32 + mt * 16 + g;
#pragma unroll
        for (int nt = 0; nt < 8; nt++) {
            const int col = n0 + warpN * 64 + nt * 8 + tc4 * 2;
            const float bv0 = bias[col], bv1 = bias[col + 1];
            if (HALF_OUT) {
                __half* C = (__half*)Cv;
                *(__half2*)(C + (size_t)row * N + col) =
                    __floats2half2_rn(acc[mt][nt][0] + bv0, acc[mt][nt][1] + bv1);
                *(__half2*)(C + (size_t)(row + 8) * N + col) =
                    __floats2half2_rn(acc[mt][nt][2] + bv0, acc[mt][nt][3] + bv1);
            } else {
                float* C = (float*)Cv;
                float2 v0, v1;
                v0.x = acc[mt][nt][0] + bv0; v0.y = acc[mt][nt][1] + bv1;
                v1.x = acc[mt][nt][2] + bv0; v1.y = acc[mt][nt][3] + bv1;
                *(float2*)(C + (size_t)row * N + col) = v0;
                *(float2*)(C + (size_t)(row + 8) * N + col) = v1;
            }
        }
    }
}

// ---------------------------------------------------------------------------
// Flash attention R15: V kept row-major, PV B-frags via ldmatrix.trans
// (no staging/transpose passes, single load barrier); fully-masked QK/PV
// sub-tiles on the diagonal chunk skipped (bit-identical: those S entries
// are set to -1e30 by the mask loop regardless, masked P == 0 exactly).
// ---------------------------------------------------------------------------
#define AT_QH 0
#define AT_KH 36864
#define AT_VH 73728
#define ATTN_SMEM 110592

__global__ __launch_bounds__(256, 2)
void attn_mma_kernel(const __half* __restrict__ qkv,
                     __half* __restrict__ yh) {
    extern __shared__ char smem[];
    const uint32_t sbase = smem_to_u32(smem);
    const int b = blockIdx.x >> 3;
    const int h = blockIdx.x & 7;
    const int tid = threadIdx.x;
    const int wid = tid >> 5, lane = tid & 31;
    const int g = lane >> 2, tq = lane & 3;
    const int lrow = lane & 15, lcs = lane >> 4;
    const float SCALE = 0.125f;

    const __half* base = qkv + (size_t)b * TLEN * (3 * DMODEL) + h * HDIM;

    // single coalesced load of Q, K, V into [256][144B] regions
    for (int i = tid; i < 256 * 8; i += 256) {
        const int t = i >> 3, c = i & 7;
        const size_t roff = (size_t)t * (3 * DMODEL);
        uint4 q = *(const uint4*)(base + roff + c * 8);
        uint4 k = *(const uint4*)(base + roff + DMODEL + c * 8);
        uint4 v = *(const uint4*)(base + roff + 2 * DMODEL + c * 8);
        const int so = t * 144 + c * 16;
        *(uint4*)(smem + AT_QH + so) = q;
        *(uint4*)(smem + AT_KH + so) = k;
        *(uint4*)(smem + AT_VH + so) = v;
    }
    __syncthreads();

#pragma unroll
    for (int half = 0; half < 2; half++) {
        const int tile = (half == 0) ? wid : 15 - wid;
        const int nch = tile / 4 + 1;
        const int tmod = tile & 3;

        float o[8][4];
#pragma unroll
        for (int nt = 0; nt < 8; nt++)
#pragma unroll
            for (int r = 0; r < 4; r++) o[nt][r] = 0.0f;
        float m0 = -1e30f, m1 = -1e30f, l0 = 0.0f, l1 = 0.0f;

        for (int c = 0; c < nch; c++) {
            const bool diag = (c == nch - 1);
            const int qmax = diag ? tmod : 3;

            float S[8][4];
#pragma unroll
            for (int nt = 0; nt < 8; nt++)
#pragma unroll
                for (int r = 0; r < 4; r++) S[nt][r] = 0.0f;

            // ---- S = Q @ K^T (skip fully-masked key groups) ----
#pragma unroll
            for (int kt = 0; kt < 4; kt++) {
                uint32_t aH[4];
                const uint32_t qro = (uint32_t)(tile * 16 + lrow) * 144 + kt * 32 + lcs * 16;
                ldsm_x4(aH, sbase + AT_QH + qro);
#pragma unroll
                for (int q = 0; q < 4; q++) {
                    if (q > qmax) break;
                    const uint32_t kro =
                        (uint32_t)(c * 64 + q * 16 + lrow) * 144 + kt * 32 + lcs * 16;
                    uint32_t tK[4];
                    ldsm_x4(tK, sbase + AT_KH + kro);
                    uint32_t b0[2] = {tK[0], tK[2]}, b1[2] = {tK[1], tK[3]};
                    mma16816(S[2 * q],     aH, b0);
                    mma16816(S[2 * q + 1], aH, b1);
                }
            }

            // ---- scale + causal mask (covers skipped sub-tiles too) ----
            const int r0 = tile * 16 + g, r1 = r0 + 8;
            if (diag) {
#pragma unroll
                for (int nt = 0; nt < 8; nt++) {
                    const int col = c * 64 + nt * 8 + 2 * tq;
                    S[nt][0] = (col     <= r0) ? S[nt][0] * SCALE : -1e30f;
                    S[nt][1] = (col + 1 <= r0) ? S[nt][1] * SCALE : -1e30f;
                    S[nt][2] = (col     <= r1) ? S[nt][2] * SCALE : -1e30f;
                    S[nt][3] = (col + 1 <= r1) ? S[nt][3] * SCALE : -1e30f;
                }
            } else {
#pragma unroll
                for (int nt = 0; nt < 8; nt++)
#pragma unroll
                    for (int r = 0; r < 4; r++) S[nt][r] *= SCALE;
            }

            // ---- online softmax ----
            float cm0 = -1e30f, cm1 = -1e30f;
#pragma unroll
            for (int nt = 0; nt < 8; nt++) {
                cm0 = fmaxf(cm0, fmaxf(S[nt][0], S[nt][1]));
                cm1 = fmaxf(cm1, fmaxf(S[nt][2], S[nt][3]));
            }
            cm0 = fmaxf(cm0, __shfl_xor_sync(0xffffffffu, cm0, 1));
            cm0 = fmaxf(cm0, __shfl_xor_sync(0xffffffffu, cm0, 2));
            cm1 = fmaxf(cm1, __shfl_xor_sync(0xffffffffu, cm1, 1));
            cm1 = fmaxf(cm1, __shfl_xor_sync(0xffffffffu, cm1, 2));
            const float mn0 = fmaxf(m0, cm0), mn1 = fmaxf(m1, cm1);
            const float a0 = __expf(m0 - mn0), a1 = __expf(m1 - mn1);
            m0 = mn0; m1 = mn1;

            float rs0 = 0.0f, rs1 = 0.0f;
#pragma unroll
            for (int nt = 0; nt < 8; nt++) {
                S[nt][0] = __expf(S[nt][0] - mn0);
                S[nt][1] = __expf(S[nt][1] - mn0);
                S[nt][2] = __expf(S[nt][2] - mn1);
                S[nt][3] = __expf(S[nt][3] - mn1);
                rs0 += S[nt][0] + S[nt][1];
                rs1 += S[nt][2] + S[nt][3];
            }
            rs0 += __shfl_xor_sync(0xffffffffu, rs0, 1);
            rs0 += __shfl_xor_sync(0xffffffffu, rs0, 2);
            rs1 += __shfl_xor_sync(0xffffffffu, rs1, 1);
            rs1 += __shfl_xor_sync(0xffffffffu, rs1, 2);
            l0 = l0 * a0 + rs0;
            l1 = l1 * a1 + rs1;

#pragma unroll
            for (int nt = 0; nt < 8; nt++) {
                o[nt][0] *= a0; o[nt][1] *= a0;
                o[nt][2] *= a1; o[nt][3] *= a1;
            }

            // ---- P frags (fp16), only live key groups ----
            uint32_t pH[4][4];
#pragma unroll
            for (int kt = 0; kt < 4; kt++) {
                if (kt > qmax) break;
#pragma unroll
                for (int part = 0; part < 4; part++) {
                    const int nt = 2 * kt + (part >> 1);
                    const int rb = (part & 1) * 2;
                    __half2 hh = __floats2half2_rn(S[nt][rb], S[nt][rb + 1]);
                    pH[kt][part] = *(uint32_t*)&hh;
                }
            }

            // ---- O += P @ V via ldmatrix.trans on row-major V ----
#pragma unroll
            for (int kt = 0; kt < 4; kt++) {
                if (kt > qmax) break;
#pragma unroll
                for (int dq = 0; dq < 4; dq++) {
                    const uint32_t vro =
                        (uint32_t)(c * 64 + kt * 16 + lrow) * 144 + dq * 32 + lcs * 16;
                    uint32_t tV[4];
                    ldsm_x4_t(tV, sbase + AT_VH + vro);
                    uint32_t b0[2] = {tV[0], tV[1]}, b1[2] = {tV[2], tV[3]};
                    mma16816(o[2 * dq],     pH[kt], b0);
                    mma16816(o[2 * dq + 1], pH[kt], b1);
                }
            }
        }

        // ---- normalize + write rounded fp16 ----
        const float inv0 = 1.0f / l0, inv1 = 1.0f / l1;
        const int row0 = b * TLEN + tile * 16 + g;
#pragma unroll
        for (int nt = 0; nt < 8; nt++) {
            const int col = h * HDIM + nt * 8 + 2 * tq;
            const size_t i0 = (size_t)row0 * DMODEL + col;
            const size_t i1 = i0 + (size_t)8 * DMODEL;
            *(__half2*)(yh + i0) = __floats2half2_rn(o[nt][0] * inv0, o[nt][1] * inv0);
            *(__half2*)(yh + i1) = __floats2half2_rn(o[nt][2] * inv1, o[nt][3] * inv1);
        }
    }
}

// ---------------------------------------------------------------------------
extern "C" void kernel_launch(void* const* d_in, const int* in_sizes, int n_in,
                              void* d_out, int out_size) {
    const float* x     = (const float*)d_in[0];
    const float* W_qkv = (const float*)d_in[1];
    const float* b_qkv = (const float*)d_in[2];
    const float* W_out = (const float*)d_in[3];
    const float* b_out = (const float*)d_in[4];
    float* out = (float*)d_out;

    __half *qkv, *ah, *bh, *b2h;
    cudaGetSymbolAddress((void**)&qkv, g_qkv);
    cudaGetSymbolAddress((void**)&ah, g_ah);
    cudaGetSymbolAddress((void**)&bh, g_bh);
    cudaGetSymbolAddress((void**)&b2h, g_b2h);

    cudaFuncSetAttribute(gemm_mma_kernel<true>,
                         cudaFuncAttributeMaxDynamicSharedMemorySize, GEMM_SMEM);
    cudaFuncSetAttribute(gemm_mma_kernel<false>,
                         cudaFuncAttributeMaxDynamicSharedMemorySize, GEMM_SMEM);
    cudaFuncSetAttribute(attn_mma_kernel,
                         cudaFuncAttributeMaxDynamicSharedMemorySize, ATTN_SMEM);

    // 1) fused conversions (x round + both weight transposes)
    convert_all_kernel<<<CONV_XB + CONV_WQ + CONV_WO, 256>>>(
        x, W_qkv, W_out, ah, bh, b2h);

    // 2) QKV projection -> fp16 qkv
    {
        dim3 g(3 * DMODEL / 128, MROWS / 128);
        gemm_mma_kernel<true><<<g, 256, GEMM_SMEM>>>(ah, bh, b_qkv, qkv,
                                                     3 * DMODEL);
    }

    // 3) flash attention (fp16 in/out), writes y into ah
    attn_mma_kernel<<<BSZ * NHEADS, 256, ATTN_SMEM>>>(qkv, ah);

    // 4) output projection -> fp32 out
    {
        dim3 g(DMODEL / 128, MROWS / 128);
        gemm_mma_kernel<false><<<g, 256, GEMM_SMEM>>>(ah, b2h, b_out, out,
                                                      DMODEL);
    }
}

// round 16
// speedup vs baseline: 2.8440x; 1.0012x over previous
#include <cuda_runtime.h>
#include <cuda_fp16.h>
#include <math.h>
#include <cstdint>

#define BSZ 128
#define TLEN 256
#define DMODEL 512
#define NHEADS 8
#define HDIM 64
#define MROWS (BSZ * TLEN)          // 32768
#define GK 512                       // K dim of both GEMMs

// ---------------------------------------------------------------------------
// Scratch: __device__ globals (allocation-free rule).
// ---------------------------------------------------------------------------
__device__ __half g_qkv[(size_t)MROWS * 3 * DMODEL];  // fp16 qkv intermediate
__device__ __half g_ah[(size_t)MROWS * GK];           // A (x rounded, then attn out)
__device__ __half g_bh[(size_t)(3 * DMODEL) * GK];    // W_qkv^T fp16
__device__ __half g_b2h[(size_t)DMODEL * GK];         // W_out^T fp16

// ---------------------------------------------------------------------------
// PTX helpers — plain-sm_103-legal only (mma.sync / ldmatrix / cp.async).
// ---------------------------------------------------------------------------
__device__ __forceinline__ uint32_t smem_to_u32(const void* smem_ptr) {
    uint32_t addr;
    asm("{ .reg .u64 tmp; cvta.to.shared.u64 tmp, %1; cvt.u32.u64 %0, tmp; }"
        : "=r"(addr) : "l"(smem_ptr));
    return addr;
}

__device__ __forceinline__ void ldsm_x4(uint32_t* r, uint32_t addr) {
    asm volatile("ldmatrix.sync.aligned.m8n8.x4.shared.b16 {%0,%1,%2,%3}, [%4];"
                 : "=r"(r[0]), "=r"(r[1]), "=r"(r[2]), "=r"(r[3]) : "r"(addr));
}

__device__ __forceinline__ void ldsm_x4_t(uint32_t* r, uint32_t addr) {
    asm volatile("ldmatrix.sync.aligned.m8n8.x4.trans.shared.b16 {%0,%1,%2,%3}, [%4];"
                 : "=r"(r[0]), "=r"(r[1]), "=r"(r[2]), "=r"(r[3]) : "r"(addr));
}

__device__ __forceinline__ void mma16816(float* c, const uint32_t* a,
                                         const uint32_t* b) {
    asm volatile(
        "mma.sync.aligned.m16n8k16.row.col.f32.f16.f16.f32 "
        "{%0,%1,%2,%3}, {%4,%5,%6,%7}, {%8,%9}, {%0,%1,%2,%3};"
        : "+f"(c[0]), "+f"(c[1]), "+f"(c[2]), "+f"(c[3])
        : "r"(a[0]), "r"(a[1]), "r"(a[2]), "r"(a[3]), "r"(b[0]), "r"(b[1]));
}

__device__ __forceinline__ void cp_async16(uint32_t saddr, const void* gaddr) {
    asm volatile("cp.async.cg.shared.global [%0], [%1], 16;"
                 :: "r"(saddr), "l"(gaddr));
}
#define CP_COMMIT() asm volatile("cp.async.commit_group;" ::: "memory")
#define CP_WAIT(n)  asm volatile("cp.async.wait_group %0;" :: "n"(n) : "memory")

// ---------------------------------------------------------------------------
// Fused conversion kernel. R16: weight transposes through 32x33 smem tiles
// (coalesced loads AND stores; previous version scattered 2B stores).
// ---------------------------------------------------------------------------
#define CONV_XB (MROWS * GK / 4 / 256)                 // 16384 blocks
#define CONV_TQ ((GK / 32) * (3 * DMODEL / 32))        // 16*48 = 768 tiles
#define CONV_TO ((GK / 32) * (DMODEL / 32))            // 16*16 = 256 tiles

__device__ __forceinline__ void transpose_tile_f16(const float* __restrict__ W,
                                                   __half* __restrict__ out,
                                                   int K, int N, int k0, int n0,
                                                   __half (*tile)[33]) {
    const int tx = threadIdx.x & 31, ty = threadIdx.x >> 5;   // 32 x 8
#pragma unroll
    for (int r = 0; r < 32; r += 8)
        tile[ty + r][tx] = __float2half_rn(W[(size_t)(k0 + ty + r) * N + n0 + tx]);
    __syncthreads();
#pragma unroll
    for (int r = 0; r < 32; r += 8)
        out[(size_t)(n0 + ty + r) * K + k0 + tx] = tile[tx][ty + r];
}

__global__ void convert_all_kernel(const float* __restrict__ x,
                                   const float* __restrict__ Wq,
                                   const float* __restrict__ Wo,
                                   __half* __restrict__ ah,
                                   __half* __restrict__ bh,
                                   __half* __restrict__ b2h) {
    __shared__ __half tile[32][33];
    const int bid = blockIdx.x;
    if (bid < CONV_XB) {
        int i = bid * 256 + threadIdx.x;
        float4 v = ((const float4*)x)[i];
        __half2* h2 = (__half2*)(ah + (size_t)i * 4);
        h2[0] = __floats2half2_rn(v.x, v.y);
        h2[1] = __floats2half2_rn(v.z, v.w);
    } else if (bid < CONV_XB + CONV_TQ) {
        int t = bid - CONV_XB;
        int kt = t / (3 * DMODEL / 32), nt = t % (3 * DMODEL / 32);
        transpose_tile_f16(Wq, bh, GK, 3 * DMODEL, kt * 32, nt * 32, tile);
    } else {
        int t = bid - CONV_XB - CONV_TQ;
        int kt = t / (DMODEL / 32), nt = t % (DMODEL / 32);
        transpose_tile_f16(Wo, b2h, GK, DMODEL, kt * 32, nt * 32, tile);
    }
}

// ---------------------------------------------------------------------------
// fp16 single-term mma.sync GEMM (frozen since R14 — near the HMMA issue
// floor). Single-barrier 3-stage pipeline: wait(1)->sync->issue->compute.
// ---------------------------------------------------------------------------
#define ROWB 80
#define SM_TILE (128 * ROWB)           // 10240
#define SM_T_A 0
#define SM_T_B (SM_TILE)
#define SM_STAGE (2 * SM_TILE)         // 20480
#define GEMM_SMEM (3 * SM_STAGE)       // 61440

template <bool HALF_OUT>
__global__ __launch_bounds__(256, 2)
void gemm_mma_kernel(const __half* __restrict__ Ah,
                     const __half* __restrict__ Bh,
                     const float* __restrict__ bias,
                     void* __restrict__ Cv, int N) {
    extern __shared__ char smem[];
    const uint32_t sbase = smem_to_u32(smem);
    const int tid = threadIdx.x;
    const int wid = tid >> 5, lane = tid & 31;
    const int warpM = wid & 3, warpN = wid >> 2;
    const int m0 = blockIdx.y * 128, n0 = blockIdx.x * 128;

    const char* gA = (const char*)(Ah + (size_t)m0 * GK);
    const char* gB = (const char*)(Bh + (size_t)n0 * GK);

    float acc[2][8][4];
#pragma unroll
    for (int mt = 0; mt < 2; mt++)
#pragma unroll
        for (int nt = 0; nt < 8; nt++)
#pragma unroll
            for (int r = 0; r < 4; r++) acc[mt][nt][r] = 0.0f;

    const int lr2 = (tid >> 2);
    const int lc2 = (tid & 3);

    constexpr int NSTAGES = GK / 32;     // 16

#pragma unroll
    for (int ps = 0; ps < 2; ps++) {
        uint32_t sb = sbase + ps * SM_STAGE;
        const int kbyte = ps * 64;
#pragma unroll
        for (int p = 0; p < 2; p++) {
            int r = lr2 + p * 64;
            uint32_t so = r * ROWB + lc2 * 16;
            size_t go = (size_t)r * (GK * 2) + kbyte + lc2 * 16;
            cp_async16(sb + SM_T_A + so, gA + go);
            cp_async16(sb + SM_T_B + so, gB + go);
        }
        CP_COMMIT();
    }

    const int lrow = lane & 15;
    const int lcs = lane >> 4;

    int buf = 0;
    for (int s = 0; s < NSTAGES; s++) {
        if (s + 1 < NSTAGES) { CP_WAIT(1); } else { CP_WAIT(0); }
        __syncthreads();

        if (s + 2 < NSTAGES) {
            int nb = buf + 2; if (nb >= 3) nb -= 3;
            uint32_t sb = sbase + nb * SM_STAGE;
            const int kbyte = (s + 2) * 64;
#pragma unroll
            for (int p = 0; p < 2; p++) {
                int r = lr2 + p * 64;
                uint32_t so = r * ROWB + lc2 * 16;
                size_t go = (size_t)r * (GK * 2) + kbyte + lc2 * 16;
                cp_async16(sb + SM_T_A + so, gA + go);
                cp_async16(sb + SM_T_B + so, gB + go);
            }
            CP_COMMIT();
        }

        const uint32_t sb = sbase + buf * SM_STAGE;
#pragma unroll
        for (int kk = 0; kk < 2; kk++) {
            const uint32_t coff = (kk * 2 + lcs) * 16;
            uint32_t aH[2][4];
#pragma unroll
            for (int mt = 0; mt < 2; mt++) {
                uint32_t ro = (uint32_t)(warpM * 32 + mt * 16 + lrow) * ROWB + coff;
                ldsm_x4(aH[mt], sb + SM_T_A + ro);
            }
#pragma unroll
            for (int q = 0; q < 4; q++) {
                uint32_t ro = (uint32_t)(warpN * 64 + q * 16 + lrow) * ROWB + coff;
                uint32_t tB[4];
                ldsm_x4(tB, sb + SM_T_B + ro);
                uint32_t b0[2] = {tB[0], tB[2]}, b1[2] = {tB[1], tB[3]};
#pragma unroll
                for (int mt = 0; mt < 2; mt++) {
                    mma16816(acc[mt][2 * q],     aH[mt], b0);
                    mma16816(acc[mt][2 * q + 1], aH[mt], b1);
                }
            }
        }
        buf++; if (buf == 3) buf = 0;
    }

    const int g = lane >> 2, tc4 = lane & 3;
#pragma unroll
    for (int mt = 0; mt < 2; mt++) {
        const int row = m0 + warpM * 32 + mt * 16 + g;
#pragma unroll
        for (int nt = 0; nt < 8; nt++) {
            const int col = n0 + warpN * 64 + nt * 8 + tc4 * 2;
            const float bv0 = bias[col], bv1 = bias[col + 1];
            if (HALF_OUT) {
                __half* C = (__half*)Cv;
                *(__half2*)(C + (size_t)row * N + col) =
                    __floats2half2_rn(acc[mt][nt][0] + bv0, acc[mt][nt][1] + bv1);
                *(__half2*)(C + (size_t)(row + 8) * N + col) =
                    __floats2half2_rn(acc[mt][nt][2] + bv0, acc[mt][nt][3] + bv1);
            } else {
                float* C = (float*)Cv;
                float2 v0, v1;
                v0.x = acc[mt][nt][0] + bv0; v0.y = acc[mt][nt][1] + bv1;
                v1.x = acc[mt][nt][2] + bv0; v1.y = acc[mt][nt][3] + bv1;
                *(float2*)(C + (size_t)row * N + col) = v0;
                *(float2*)(C + (size_t)(row + 8) * N + col) = v1;
            }
        }
    }
}

// ---------------------------------------------------------------------------
// Flash attention R16: 2 blocks per (b,h) — block half 0 owns query tiles
// 0-7 (loads K/V rows 0-127 only), half 1 owns tiles 8-15 (full K/V).
// One tile per warp. Math bit-identical to R15.
// ---------------------------------------------------------------------------
#define AT_Q 0                       // [128][144B] = 18432
#define AT_K 18432                   // [256][144B] = 36864
#define AT_V 55296                   // [256][144B] = 36864
#define ATTN_SMEM 92160

__global__ __launch_bounds__(256, 2)
void attn_mma_kernel(const __half* __restrict__ qkv,
                     __half* __restrict__ yh) {
    extern __shared__ char smem[];
    const uint32_t sbase = smem_to_u32(smem);
    const int bh = blockIdx.x >> 1;
    const int halfid = blockIdx.x & 1;
    const int b = bh >> 3;
    const int h = bh & 7;
    const int tid = threadIdx.x;
    const int wid = tid >> 5, lane = tid & 31;
    const int g = lane >> 2, tq = lane & 3;
    const int lrow = lane & 15, lcs = lane >> 4;
    const float SCALE = 0.125f;

    const __half* base = qkv + (size_t)b * TLEN * (3 * DMODEL) + h * HDIM;

    // load Q (own 128 rows) and K/V (rows 0..nkv-1)
    const int q0 = halfid * 128;
    for (int i = tid; i < 128 * 8; i += 256) {
        const int t = i >> 3, c = i & 7;
        uint4 q = *(const uint4*)(base + (size_t)(q0 + t) * (3 * DMODEL) + c * 8);
        *(uint4*)(smem + AT_Q + t * 144 + c * 16) = q;
    }
    const int nkv = (halfid + 1) * 128;
    for (int i = tid; i < nkv * 8; i += 256) {
        const int t = i >> 3, c = i & 7;
        const size_t roff = (size_t)t * (3 * DMODEL);
        uint4 k = *(const uint4*)(base + roff + DMODEL + c * 8);
        uint4 v = *(const uint4*)(base + roff + 2 * DMODEL + c * 8);
        const int so = t * 144 + c * 16;
        *(uint4*)(smem + AT_K + so) = k;
        *(uint4*)(smem + AT_V + so) = v;
    }
    __syncthreads();

    const int tile = halfid * 8 + wid;       // global tile 0..15
    const int nch = tile / 4 + 1;
    const int tmod = tile & 3;

    float o[8][4];
#pragma unroll
    for (int nt = 0; nt < 8; nt++)
#pragma unroll
        for (int r = 0; r < 4; r++) o[nt][r] = 0.0f;
    float m0 = -1e30f, m1 = -1e30f, l0 = 0.0f, l1 = 0.0f;

    for (int c = 0; c < nch; c++) {
        const bool diag = (c == nch - 1);
        const int qmax = diag ? tmod : 3;

        float S[8][4];
#pragma unroll
        for (int nt = 0; nt < 8; nt++)
#pragma unroll
            for (int r = 0; r < 4; r++) S[nt][r] = 0.0f;

        // ---- S = Q @ K^T (skip fully-masked key groups) ----
#pragma unroll
        for (int kt = 0; kt < 4; kt++) {
            uint32_t aH[4];
            const uint32_t qro = (uint32_t)(wid * 16 + lrow) * 144 + kt * 32 + lcs * 16;
            ldsm_x4(aH, sbase + AT_Q + qro);
#pragma unroll
            for (int q = 0; q < 4; q++) {
                if (q > qmax) break;
                const uint32_t kro =
                    (uint32_t)(c * 64 + q * 16 + lrow) * 144 + kt * 32 + lcs * 16;
                uint32_t tK[4];
                ldsm_x4(tK, sbase + AT_K + kro);
                uint32_t b0[2] = {tK[0], tK[2]}, b1[2] = {tK[1], tK[3]};
                mma16816(S[2 * q],     aH, b0);
                mma16816(S[2 * q + 1], aH, b1);
            }
        }

        // ---- scale + causal mask ----
        const int r0 = tile * 16 + g, r1 = r0 + 8;
        if (diag) {
#pragma unroll
            for (int nt = 0; nt < 8; nt++) {
                const int col = c * 64 + nt * 8 + 2 * tq;
                S[nt][0] = (col     <= r0) ? S[nt][0] * SCALE : -1e30f;
                S[nt][1] = (col + 1 <= r0) ? S[nt][1] * SCALE : -1e30f;
                S[nt][2] = (col     <= r1) ? S[nt][2] * SCALE : -1e30f;
                S[nt][3] = (col + 1 <= r1) ? S[nt][3] * SCALE : -1e30f;
            }
        } else {
#pragma unroll
            for (int nt = 0; nt < 8; nt++)
#pragma unroll
                for (int r = 0; r < 4; r++) S[nt][r] *= SCALE;
        }

        // ---- online softmax ----
        float cm0 = -1e30f, cm1 = -1e30f;
#pragma unroll
        for (int nt = 0; nt < 8; nt++) {
            cm0 = fmaxf(cm0, fmaxf(S[nt][0], S[nt][1]));
            cm1 = fmaxf(cm1, fmaxf(S[nt][2], S[nt][3]));
        }
        cm0 = fmaxf(cm0, __shfl_xor_sync(0xffffffffu, cm0, 1));
        cm0 = fmaxf(cm0, __shfl_xor_sync(0xffffffffu, cm0, 2));
        cm1 = fmaxf(cm1, __shfl_xor_sync(0xffffffffu, cm1, 1));
        cm1 = fmaxf(cm1, __shfl_xor_sync(0xffffffffu, cm1, 2));
        const float mn0 = fmaxf(m0, cm0), mn1 = fmaxf(m1, cm1);
        const float a0 = __expf(m0 - mn0), a1 = __expf(m1 - mn1);
        m0 = mn0; m1 = mn1;

        float rs0 = 0.0f, rs1 = 0.0f;
#pragma unroll
        for (int nt = 0; nt < 8; nt++) {
            S[nt][0] = __expf(S[nt][0] - mn0);
            S[nt][1] = __expf(S[nt][1] - mn0);
            S[nt][2] = __expf(S[nt][2] - mn1);
            S[nt][3] = __expf(S[nt][3] - mn1);
            rs0 += S[nt][0] + S[nt][1];
            rs1 += S[nt][2] + S[nt][3];
        }
        rs0 += __shfl_xor_sync(0xffffffffu, rs0, 1);
        rs0 += __shfl_xor_sync(0xffffffffu, rs0, 2);
        rs1 += __shfl_xor_sync(0xffffffffu, rs1, 1);
        rs1 += __shfl_xor_sync(0xffffffffu, rs1, 2);
        l0 = l0 * a0 + rs0;
        l1 = l1 * a1 + rs1;

#pragma unroll
        for (int nt = 0; nt < 8; nt++) {
            o[nt][0] *= a0; o[nt][1] *= a0;
            o[nt][2] *= a1; o[nt][3] *= a1;
        }

        // ---- P frags (fp16), only live key groups ----
        uint32_t pH[4][4];
#pragma unroll
        for (int kt = 0; kt < 4; kt++) {
            if (kt > qmax) break;
#pragma unroll
            for (int part = 0; part < 4; part++) {
                const int nt = 2 * kt + (part >> 1);
                const int rb = (part & 1) * 2;
                __half2 hh = __floats2half2_rn(S[nt][rb], S[nt][rb + 1]);
                pH[kt][part] = *(uint32_t*)&hh;
            }
        }

        // ---- O += P @ V via ldmatrix.trans on row-major V ----
#pragma unroll
        for (int kt = 0; kt < 4; kt++) {
            if (kt > qmax) break;
#pragma unroll
            for (int dq = 0; dq < 4; dq++) {
                const uint32_t vro =
                    (uint32_t)(c * 64 + kt * 16 + lrow) * 144 + dq * 32 + lcs * 16;
                uint32_t tV[4];
                ldsm_x4_t(tV, sbase + AT_V + vro);
                uint32_t b0[2] = {tV[0], tV[1]}, b1[2] = {tV[2], tV[3]};
                mma16816(o[2 * dq],     pH[kt], b0);
                mma16816(o[2 * dq + 1], pH[kt], b1);
            }
        }
    }

    // ---- normalize + write rounded fp16 ----
    const float inv0 = 1.0f / l0, inv1 = 1.0f / l1;
    const int row0 = b * TLEN + tile * 16 + g;
#pragma unroll
    for (int nt = 0; nt < 8; nt++) {
        const int col = h * HDIM + nt * 8 + 2 * tq;
        const size_t i0 = (size_t)row0 * DMODEL + col;
        const size_t i1 = i0 + (size_t)8 * DMODEL;
        *(__half2*)(yh + i0) = __floats2half2_rn(o[nt][0] * inv0, o[nt][1] * inv0);
        *(__half2*)(yh + i1) = __floats2half2_rn(o[nt][2] * inv1, o[nt][3] * inv1);
    }
}

// ---------------------------------------------------------------------------
extern "C" void kernel_launch(void* const* d_in, const int* in_sizes, int n_in,
                              void* d_out, int out_size) {
    const float* x     = (const float*)d_in[0];
    const float* W_qkv = (const float*)d_in[1];
    const float* b_qkv = (const float*)d_in[2];
    const float* W_out = (const float*)d_in[3];
    const float* b_out = (const float*)d_in[4];
    float* out = (float*)d_out;

    __half *qkv, *ah, *bh, *b2h;
    cudaGetSymbolAddress((void**)&qkv, g_qkv);
    cudaGetSymbolAddress((void**)&ah, g_ah);
    cudaGetSymbolAddress((void**)&bh, g_bh);
    cudaGetSymbolAddress((void**)&b2h, g_b2h);

    cudaFuncSetAttribute(gemm_mma_kernel<true>,
                         cudaFuncAttributeMaxDynamicSharedMemorySize, GEMM_SMEM);
    cudaFuncSetAttribute(gemm_mma_kernel<false>,
                         cudaFuncAttributeMaxDynamicSharedMemorySize, GEMM_SMEM);
    cudaFuncSetAttribute(attn_mma_kernel,
                         cudaFuncAttributeMaxDynamicSharedMemorySize, ATTN_SMEM);

    // 1) fused conversions (x round + tiled weight transposes)
    convert_all_kernel<<<CONV_XB + CONV_TQ + CONV_TO, 256>>>(
        x, W_qkv, W_out, ah, bh, b2h);

    // 2) QKV projection -> fp16 qkv
    {
        dim3 g(3 * DMODEL / 128, MROWS / 128);
        gemm_mma_kernel<true><<<g, 256, GEMM_SMEM>>>(ah, bh, b_qkv, qkv,
                                                     3 * DMODEL);
    }

    // 3) flash attention (2 blocks per (b,h)), writes y into ah
    attn_mma_kernel<<<BSZ * NHEADS * 2, 256, ATTN_SMEM>>>(qkv, ah);

    // 4) output projection -> fp32 out
    {
        dim3 g(DMODEL / 128, MROWS / 128);
        gemm_mma_kernel<false><<<g, 256, GEMM_SMEM>>>(ah, b2h, b_out, out,
                                                      DMODEL);
    }
}

// round 17
// speedup vs baseline: 3.0009x; 1.0552x over previous
#include <cuda_runtime.h>
#include <cuda_fp16.h>
#include <math.h>
#include <cstdint>

#define BSZ 128
#define TLEN 256
#define DMODEL 512
#define NHEADS 8
#define HDIM 64
#define MROWS (BSZ * TLEN)          // 32768
#define GK 512                       // K dim of both GEMMs

// ---------------------------------------------------------------------------
// Scratch: __device__ globals (allocation-free rule).
// ---------------------------------------------------------------------------
__device__ __half g_qkv[(size_t)MROWS * 3 * DMODEL];  // fp16 qkv (Q pre-scaled)
__device__ __half g_ah[(size_t)MROWS * GK];           // A (x rounded, then attn out)
__device__ __half g_bh[(size_t)(3 * DMODEL) * GK];    // W_qkv^T fp16
__device__ __half g_b2h[(size_t)DMODEL * GK];         // W_out^T fp16

// ---------------------------------------------------------------------------
// PTX helpers — plain-sm_103-legal only (mma.sync / ldmatrix / cp.async).
// ---------------------------------------------------------------------------
__device__ __forceinline__ uint32_t smem_to_u32(const void* smem_ptr) {
    uint32_t addr;
    asm("{ .reg .u64 tmp; cvta.to.shared.u64 tmp, %1; cvt.u32.u64 %0, tmp; }"
        : "=r"(addr) : "l"(smem_ptr));
    return addr;
}

__device__ __forceinline__ void ldsm_x4(uint32_t* r, uint32_t addr) {
    asm volatile("ldmatrix.sync.aligned.m8n8.x4.shared.b16 {%0,%1,%2,%3}, [%4];"
                 : "=r"(r[0]), "=r"(r[1]), "=r"(r[2]), "=r"(r[3]) : "r"(addr));
}

__device__ __forceinline__ void ldsm_x4_t(uint32_t* r, uint32_t addr) {
    asm volatile("ldmatrix.sync.aligned.m8n8.x4.trans.shared.b16 {%0,%1,%2,%3}, [%4];"
                 : "=r"(r[0]), "=r"(r[1]), "=r"(r[2]), "=r"(r[3]) : "r"(addr));
}

__device__ __forceinline__ void mma16816(float* c, const uint32_t* a,
                                         const uint32_t* b) {
    asm volatile(
        "mma.sync.aligned.m16n8k16.row.col.f32.f16.f16.f32 "
        "{%0,%1,%2,%3}, {%4,%5,%6,%7}, {%8,%9}, {%0,%1,%2,%3};"
        : "+f"(c[0]), "+f"(c[1]), "+f"(c[2]), "+f"(c[3])
        : "r"(a[0]), "r"(a[1]), "r"(a[2]), "r"(a[3]), "r"(b[0]), "r"(b[1]));
}

__device__ __forceinline__ void cp_async16(uint32_t saddr, const void* gaddr) {
    asm volatile("cp.async.cg.shared.global [%0], [%1], 16;"
                 :: "r"(saddr), "l"(gaddr));
}
#define CP_COMMIT() asm volatile("cp.async.commit_group;" ::: "memory")
#define CP_WAIT(n)  asm volatile("cp.async.wait_group %0;" :: "n"(n) : "memory")

// raw ex2.approx (same accuracy class as __expf's internal ex2)
__device__ __forceinline__ float ex2f(float x) {
    float y;
    asm("ex2.approx.f32 %0, %1;" : "=f"(y) : "f"(x));
    return y;
}

// ---------------------------------------------------------------------------
// Fused conversion kernel (R16 tiled transposes).
// ---------------------------------------------------------------------------
#define CONV_XB (MROWS * GK / 4 / 256)
#define CONV_TQ ((GK / 32) * (3 * DMODEL / 32))
#define CONV_TO ((GK / 32) * (DMODEL / 32))

__device__ __forceinline__ void transpose_tile_f16(const float* __restrict__ W,
                                                   __half* __restrict__ out,
                                                   int K, int N, int k0, int n0,
                                                   __half (*tile)[33]) {
    const int tx = threadIdx.x & 31, ty = threadIdx.x >> 5;
#pragma unroll
    for (int r = 0; r < 32; r += 8)
        tile[ty + r][tx] = __float2half_rn(W[(size_t)(k0 + ty + r) * N + n0 + tx]);
    __syncthreads();
#pragma unroll
    for (int r = 0; r < 32; r += 8)
        out[(size_t)(n0 + ty + r) * K + k0 + tx] = tile[tx][ty + r];
}

__global__ void convert_all_kernel(const float* __restrict__ x,
                                   const float* __restrict__ Wq,
                                   const float* __restrict__ Wo,
                                   __half* __restrict__ ah,
                                   __half* __restrict__ bh,
                                   __half* __restrict__ b2h) {
    __shared__ __half tile[32][33];
    const int bid = blockIdx.x;
    if (bid < CONV_XB) {
        int i = bid * 256 + threadIdx.x;
        float4 v = ((const float4*)x)[i];
        __half2* h2 = (__half2*)(ah + (size_t)i * 4);
        h2[0] = __floats2half2_rn(v.x, v.y);
        h2[1] = __floats2half2_rn(v.z, v.w);
    } else if (bid < CONV_XB + CONV_TQ) {
        int t = bid - CONV_XB;
        int kt = t / (3 * DMODEL / 32), nt = t % (3 * DMODEL / 32);
        transpose_tile_f16(Wq, bh, GK, 3 * DMODEL, kt * 32, nt * 32, tile);
    } else {
        int t = bid - CONV_XB - CONV_TQ;
        int kt = t / (DMODEL / 32), nt = t % (DMODEL / 32);
        transpose_tile_f16(Wo, b2h, GK, DMODEL, kt * 32, nt * 32, tile);
    }
}

// ---------------------------------------------------------------------------
// fp16 single-term mma.sync GEMM (mainloop frozen since R14).
// R17: HALF_OUT epilogue pre-scales Q columns (col < 512) by 0.125*log2(e)
// in fp32 before the single fp16 round — attention then runs in the log2
// domain with no scale pass and bare ex2.
// ---------------------------------------------------------------------------
#define ROWB 80
#define SM_TILE (128 * ROWB)
#define SM_T_A 0
#define SM_T_B (SM_TILE)
#define SM_STAGE (2 * SM_TILE)
#define GEMM_SMEM (3 * SM_STAGE)

#define QSCALE 0.1803368801111204f   // 0.125 * log2(e)

template <bool HALF_OUT>
__global__ __launch_bounds__(256, 2)
void gemm_mma_kernel(const __half* __restrict__ Ah,
                     const __half* __restrict__ Bh,
                     const float* __restrict__ bias,
                     void* __restrict__ Cv, int N) {
    extern __shared__ char smem[];
    const uint32_t sbase = smem_to_u32(smem);
    const int tid = threadIdx.x;
    const int wid = tid >> 5, lane = tid & 31;
    const int warpM = wid & 3, warpN = wid >> 2;
    const int m0 = blockIdx.y * 128, n0 = blockIdx.x * 128;

    const char* gA = (const char*)(Ah + (size_t)m0 * GK);
    const char* gB = (const char*)(Bh + (size_t)n0 * GK);

    float acc[2][8][4];
#pragma unroll
    for (int mt = 0; mt < 2; mt++)
#pragma unroll
        for (int nt = 0; nt < 8; nt++)
#pragma unroll
            for (int r = 0; r < 4; r++) acc[mt][nt][r] = 0.0f;

    const int lr2 = (tid >> 2);
    const int lc2 = (tid & 3);

    constexpr int NSTAGES = GK / 32;

#pragma unroll
    for (int ps = 0; ps < 2; ps++) {
        uint32_t sb = sbase + ps * SM_STAGE;
        const int kbyte = ps * 64;
#pragma unroll
        for (int p = 0; p < 2; p++) {
            int r = lr2 + p * 64;
            uint32_t so = r * ROWB + lc2 * 16;
            size_t go = (size_t)r * (GK * 2) + kbyte + lc2 * 16;
            cp_async16(sb + SM_T_A + so, gA + go);
            cp_async16(sb + SM_T_B + so, gB + go);
        }
        CP_COMMIT();
    }

    const int lrow = lane & 15;
    const int lcs = lane >> 4;

    int buf = 0;
    for (int s = 0; s < NSTAGES; s++) {
        if (s + 1 < NSTAGES) { CP_WAIT(1); } else { CP_WAIT(0); }
        __syncthreads();

        if (s + 2 < NSTAGES) {
            int nb = buf + 2; if (nb >= 3) nb -= 3;
            uint32_t sb = sbase + nb * SM_STAGE;
            const int kbyte = (s + 2) * 64;
#pragma unroll
            for (int p = 0; p < 2; p++) {
                int r = lr2 + p * 64;
                uint32_t so = r * ROWB + lc2 * 16;
                size_t go = (size_t)r * (GK * 2) + kbyte + lc2 * 16;
                cp_async16(sb + SM_T_A + so, gA + go);
                cp_async16(sb + SM_T_B + so, gB + go);
            }
            CP_COMMIT();
        }

        const uint32_t sb = sbase + buf * SM_STAGE;
#pragma unroll
        for (int kk = 0; kk < 2; kk++) {
            const uint32_t coff = (kk * 2 + lcs) * 16;
            uint32_t aH[2][4];
#pragma unroll
            for (int mt = 0; mt < 2; mt++) {
                uint32_t ro = (uint32_t)(warpM * 32 + mt * 16 + lrow) * ROWB + coff;
                ldsm_x4(aH[mt], sb + SM_T_A + ro);
            }
#pragma unroll
            for (int q = 0; q < 4; q++) {
                uint32_t ro = (uint32_t)(warpN * 64 + q * 16 + lrow) * ROWB + coff;
                uint32_t tB[4];
                ldsm_x4(tB, sb + SM_T_B + ro);
                uint32_t b0[2] = {tB[0], tB[2]}, b1[2] = {tB[1], tB[3]};
#pragma unroll
                for (int mt = 0; mt < 2; mt++) {
                    mma16816(acc[mt][2 * q],     aH[mt], b0);
                    mma16816(acc[mt][2 * q + 1], aH[mt], b1);
                }
            }
        }
        buf++; if (buf == 3) buf = 0;
    }

    const int g = lane >> 2, tc4 = lane & 3;
#pragma unroll
    for (int mt = 0; mt < 2; mt++) {
        const int row = m0 + warpM * 32 + mt * 16 + g;
#pragma unroll
        for (int nt = 0; nt < 8; nt++) {
            const int col = n0 + warpN * 64 + nt * 8 + tc4 * 2;
            const float bv0 = bias[col], bv1 = bias[col + 1];
            if (HALF_OUT) {
                // Q columns (col < DMODEL) pre-scaled by 0.125*log2e
                const float sc = (col < DMODEL) ? QSCALE : 1.0f;
                __half* C = (__half*)Cv;
                *(__half2*)(C + (size_t)row * N + col) =
                    __floats2half2_rn((acc[mt][nt][0] + bv0) * sc,
                                      (acc[mt][nt][1] + bv1) * sc);
                *(__half2*)(C + (size_t)(row + 8) * N + col) =
                    __floats2half2_rn((acc[mt][nt][2] + bv0) * sc,
                                      (acc[mt][nt][3] + bv1) * sc);
            } else {
                float* C = (float*)Cv;
                float2 v0, v1;
                v0.x = acc[mt][nt][0] + bv0; v0.y = acc[mt][nt][1] + bv1;
                v1.x = acc[mt][nt][2] + bv0; v1.y = acc[mt][nt][3] + bv1;
                *(float2*)(C + (size_t)row * N + col) = v0;
                *(float2*)(C + (size_t)(row + 8) * N + col) = v1;
            }
        }
    }
}

// ---------------------------------------------------------------------------
// Flash attention R17: log2-domain softmax (Q pre-scaled in GEMM1 epilogue):
// no scale pass, mask is pure select, exp is bare ex2.approx. Loads via
// cp.async. 2 blocks per (b,h); one m16 query tile per warp.
// ---------------------------------------------------------------------------
#define AT_Q 0                       // [128][144B] = 18432
#define AT_K 18432                   // [256][144B] = 36864
#define AT_V 55296                   // [256][144B] = 36864
#define ATTN_SMEM 92160

__global__ __launch_bounds__(256, 2)
void attn_mma_kernel(const __half* __restrict__ qkv,
                     __half* __restrict__ yh) {
    extern __shared__ char smem[];
    const uint32_t sbase = smem_to_u32(smem);
    const int bh = blockIdx.x >> 1;
    const int halfid = blockIdx.x & 1;
    const int b = bh >> 3;
    const int h = bh & 7;
    const int tid = threadIdx.x;
    const int wid = tid >> 5, lane = tid & 31;
    const int g = lane >> 2, tq = lane & 3;
    const int lrow = lane & 15, lcs = lane >> 4;

    const __half* base = qkv + (size_t)b * TLEN * (3 * DMODEL) + h * HDIM;

    // cp.async loads: Q (own 128 rows), K/V rows 0..nkv-1
    const int q0 = halfid * 128;
    for (int i = tid; i < 128 * 8; i += 256) {
        const int t = i >> 3, c = i & 7;
        cp_async16(sbase + AT_Q + t * 144 + c * 16,
                   base + (size_t)(q0 + t) * (3 * DMODEL) + c * 8);
    }
    const int nkv = (halfid + 1) * 128;
    for (int i = tid; i < nkv * 8; i += 256) {
        const int t = i >> 3, c = i & 7;
        const size_t roff = (size_t)t * (3 * DMODEL);
        const int so = t * 144 + c * 16;
        cp_async16(sbase + AT_K + so, base + roff + DMODEL + c * 8);
        cp_async16(sbase + AT_V + so, base + roff + 2 * DMODEL + c * 8);
    }
    CP_COMMIT();
    CP_WAIT(0);
    __syncthreads();

    const int tile = halfid * 8 + wid;       // global tile 0..15
    const int nch = tile / 4 + 1;
    const int tmod = tile & 3;

    float o[8][4];
#pragma unroll
    for (int nt = 0; nt < 8; nt++)
#pragma unroll
        for (int r = 0; r < 4; r++) o[nt][r] = 0.0f;
    float m0 = -1e30f, m1 = -1e30f, l0 = 0.0f, l1 = 0.0f;

    for (int c = 0; c < nch; c++) {
        const bool diag = (c == nch - 1);
        const int qmax = diag ? tmod : 3;

        float S[8][4];
#pragma unroll
        for (int nt = 0; nt < 8; nt++)
#pragma unroll
            for (int r = 0; r < 4; r++) S[nt][r] = 0.0f;

        // ---- S = Q' @ K^T (already log2-scaled; skip masked key groups) ----
#pragma unroll
        for (int kt = 0; kt < 4; kt++) {
            uint32_t aH[4];
            const uint32_t qro = (uint32_t)(wid * 16 + lrow) * 144 + kt * 32 + lcs * 16;
            ldsm_x4(aH, sbase + AT_Q + qro);
#pragma unroll
            for (int q = 0; q < 4; q++) {
                if (q > qmax) break;
                const uint32_t kro =
                    (uint32_t)(c * 64 + q * 16 + lrow) * 144 + kt * 32 + lcs * 16;
                uint32_t tK[4];
                ldsm_x4(tK, sbase + AT_K + kro);
                uint32_t b0[2] = {tK[0], tK[2]}, b1[2] = {tK[1], tK[3]};
                mma16816(S[2 * q],     aH, b0);
                mma16816(S[2 * q + 1], aH, b1);
            }
        }

        // ---- causal mask: pure select on the diagonal chunk only ----
        const int r0 = tile * 16 + g, r1 = r0 + 8;
        if (diag) {
#pragma unroll
            for (int nt = 0; nt < 8; nt++) {
                const int col = c * 64 + nt * 8 + 2 * tq;
                S[nt][0] = (col     <= r0) ? S[nt][0] : -1e30f;
                S[nt][1] = (col + 1 <= r0) ? S[nt][1] : -1e30f;
                S[nt][2] = (col     <= r1) ? S[nt][2] : -1e30f;
                S[nt][3] = (col + 1 <= r1) ? S[nt][3] : -1e30f;
            }
        }

        // ---- online softmax (log2 domain, bare ex2) ----
        float cm0 = -1e30f, cm1 = -1e30f;
#pragma unroll
        for (int nt = 0; nt < 8; nt++) {
            cm0 = fmaxf(cm0, fmaxf(S[nt][0], S[nt][1]));
            cm1 = fmaxf(cm1, fmaxf(S[nt][2], S[nt][3]));
        }
        cm0 = fmaxf(cm0, __shfl_xor_sync(0xffffffffu, cm0, 1));
        cm0 = fmaxf(cm0, __shfl_xor_sync(0xffffffffu, cm0, 2));
        cm1 = fmaxf(cm1, __shfl_xor_sync(0xffffffffu, cm1, 1));
        cm1 = fmaxf(cm1, __shfl_xor_sync(0xffffffffu, cm1, 2));
        const float mn0 = fmaxf(m0, cm0), mn1 = fmaxf(m1, cm1);
        const float a0 = ex2f(m0 - mn0), a1 = ex2f(m1 - mn1);
        m0 = mn0; m1 = mn1;

        float rs0 = 0.0f, rs1 = 0.0f;
#pragma unroll
        for (int nt = 0; nt < 8; nt++) {
            S[nt][0] = ex2f(S[nt][0] - mn0);
            S[nt][1] = ex2f(S[nt][1] - mn0);
            S[nt][2] = ex2f(S[nt][2] - mn1);
            S[nt][3] = ex2f(S[nt][3] - mn1);
            rs0 += S[nt][0] + S[nt][1];
            rs1 += S[nt][2] + S[nt][3];
        }
        rs0 += __shfl_xor_sync(0xffffffffu, rs0, 1);
        rs0 += __shfl_xor_sync(0xffffffffu, rs0, 2);
        rs1 += __shfl_xor_sync(0xffffffffu, rs1, 1);
        rs1 += __shfl_xor_sync(0xffffffffu, rs1, 2);
        l0 = l0 * a0 + rs0;
        l1 = l1 * a1 + rs1;

#pragma unroll
        for (int nt = 0; nt < 8; nt++) {
            o[nt][0] *= a0; o[nt][1] *= a0;
            o[nt][2] *= a1; o[nt][3] *= a1;
        }

        // ---- P frags (fp16), only live key groups ----
        uint32_t pH[4][4];
#pragma unroll
        for (int kt = 0; kt < 4; kt++) {
            if (kt > qmax) break;
#pragma unroll
            for (int part = 0; part < 4; part++) {
                const int nt = 2 * kt + (part >> 1);
                const int rb = (part & 1) * 2;
                __half2 hh = __floats2half2_rn(S[nt][rb], S[nt][rb + 1]);
                pH[kt][part] = *(uint32_t*)&hh;
            }
        }

        // ---- O += P @ V via ldmatrix.trans on row-major V ----
#pragma unroll
        for (int kt = 0; kt < 4; kt++) {
            if (kt > qmax) break;
#pragma unroll
            for (int dq = 0; dq < 4; dq++) {
                const uint32_t vro =
                    (uint32_t)(c * 64 + kt * 16 + lrow) * 144 + dq * 32 + lcs * 16;
                uint32_t tV[4];
                ldsm_x4_t(tV, sbase + AT_V + vro);
                uint32_t b0[2] = {tV[0], tV[1]}, b1[2] = {tV[2], tV[3]};
                mma16816(o[2 * dq],     pH[kt], b0);
                mma16816(o[2 * dq + 1], pH[kt], b1);
            }
        }
    }

    // ---- normalize + write rounded fp16 ----
    const float inv0 = 1.0f / l0, inv1 = 1.0f / l1;
    const int row0 = b * TLEN + tile * 16 + g;
#pragma unroll
    for (int nt = 0; nt < 8; nt++) {
        const int col = h * HDIM + nt * 8 + 2 * tq;
        const size_t i0 = (size_t)row0 * DMODEL + col;
        const size_t i1 = i0 + (size_t)8 * DMODEL;
        *(__half2*)(yh + i0) = __floats2half2_rn(o[nt][0] * inv0, o[nt][1] * inv0);
        *(__half2*)(yh + i1) = __floats2half2_rn(o[nt][2] * inv1, o[nt][3] * inv1);
    }
}

// ---------------------------------------------------------------------------
extern "C" void kernel_launch(void* const* d_in, const int* in_sizes, int n_in,
                              void* d_out, int out_size) {
    const float* x     = (const float*)d_in[0];
    const float* W_qkv = (const float*)d_in[1];
    const float* b_qkv = (const float*)d_in[2];
    const float* W_out = (const float*)d_in[3];
    const float* b_out = (const float*)d_in[4];
    float* out = (float*)d_out;

    __half *qkv, *ah, *bh, *b2h;
    cudaGetSymbolAddress((void**)&qkv, g_qkv);
    cudaGetSymbolAddress((void**)&ah, g_ah);
    cudaGetSymbolAddress((void**)&bh, g_bh);
    cudaGetSymbolAddress((void**)&b2h, g_b2h);

    cudaFuncSetAttribute(gemm_mma_kernel<true>,
                         cudaFuncAttributeMaxDynamicSharedMemorySize, GEMM_SMEM);
    cudaFuncSetAttribute(gemm_mma_kernel<false>,
                         cudaFuncAttributeMaxDynamicSharedMemorySize, GEMM_SMEM);
    cudaFuncSetAttribute(attn_mma_kernel,
                         cudaFuncAttributeMaxDynamicSharedMemorySize, ATTN_SMEM);

    // 1) fused conversions
    convert_all_kernel<<<CONV_XB + CONV_TQ + CONV_TO, 256>>>(
        x, W_qkv, W_out, ah, bh, b2h);

    // 2) QKV projection -> fp16 qkv (Q columns pre-scaled)
    {
        dim3 g(3 * DMODEL / 128, MROWS / 128);
        gemm_mma_kernel<true><<<g, 256, GEMM_SMEM>>>(ah, bh, b_qkv, qkv,
                                                     3 * DMODEL);
    }

    // 3) flash attention (log2-domain softmax), writes y into ah
    attn_mma_kernel<<<BSZ * NHEADS * 2, 256, ATTN_SMEM>>>(qkv, ah);

    // 4) output projection -> fp32 out
    {
        dim3 g(DMODEL / 128, MROWS / 128);
        gemm_mma_kernel<false><<<g, 256, GEMM_SMEM>>>(ah, b2h, b_out, out,
                                                      DMODEL);
    }
}